// round 5
// baseline (speedup 1.0000x reference)
#include <cuda_runtime.h>
#include <math.h>
#include <stdint.h>

// ============================================================================
// CosFormer attention (sm_103 base target; no tcgen05).
// GEMMs: int8 IMMA m16n8k32, 16-bit fixed-point emulation of fp32:
//   x ~= s_i*(qh*256+ql), w ~= t_j*(rh*256+rl)
//   x.w = s*t*(65536*hh + 256*(hl+lh) + [ql*rl dropped, ~2^-16 rel])
// 3 int8 passes @ 4096 MACs/instr = 2x the bf16 m16n8k16 path of round 4.
// Attention: chunked linear attention, fp32 (unchanged).
// ============================================================================

namespace cf {

constexpr int Bc = 2, Tc = 4096, Hc = 16, DHc = 64;
constexpr int DM = 1024, HD = 1024;
constexpr int Mrows = Bc * Tc;            // 8192
constexpr int CH = 128, NCH = Tc / CH;    // 128, 32
constexpr int BHc = Bc * Hc;              // 32
constexpr float ANGC = 3.14159265358979323846f / (2.0f * (float)Tc);

constexpr int KDIM = 1024;
constexpr int KT = 64;                    // K elems (bytes) per SMEM stage
constexpr int NKT = KDIM / KT;            // 16

// ---- fp32 scratch (attention path) ----
__device__ __align__(16) float g_Qc[(size_t)Mrows * HD];
__device__ __align__(16) float g_Qs[(size_t)Mrows * HD];
__device__ __align__(16) float g_Kc[(size_t)Mrows * HD];
__device__ __align__(16) float g_Ks[(size_t)Mrows * HD];
__device__ __align__(16) float g_V [(size_t)Mrows * HD];
__device__ __align__(16) float g_attn[(size_t)Mrows * HD];
__device__ __align__(16) float g_Scos[(size_t)BHc * NCH * DHc * DHc];
__device__ __align__(16) float g_Ssin[(size_t)BHc * NCH * DHc * DHc];
__device__ __align__(16) float g_zcos[(size_t)BHc * NCH * DHc];
__device__ __align__(16) float g_zsin[(size_t)BHc * NCH * DHc];

// ---- int8 split operands ----
__device__ __align__(16) int8_t g_x8h[(size_t)Mrows * DM];
__device__ __align__(16) int8_t g_x8l[(size_t)Mrows * DM];
__device__ __align__(16) int8_t g_a8h[(size_t)Mrows * HD];
__device__ __align__(16) int8_t g_a8l[(size_t)Mrows * HD];
__device__ __align__(16) int8_t g_W8h[4 * (size_t)HD * DM];
__device__ __align__(16) int8_t g_W8l[4 * (size_t)HD * DM];
__device__ float g_sx[Mrows];
__device__ float g_sa[Mrows];
__device__ float g_sWmax[4 * 1024];
__device__ float g_sW[4 * 1024];

// ============================================================================
// helpers
// ============================================================================
__device__ __forceinline__ uint32_t smem_u32(const void* p) {
  uint32_t a;
  asm("{ .reg .u64 t; cvta.to.shared.u64 t, %1; cvt.u32.u64 %0, t; }"
      : "=r"(a) : "l"(p));
  return a;
}
__device__ __forceinline__ void ldsm4(uint32_t* r, uint32_t addr) {
  asm volatile(
      "ldmatrix.sync.aligned.m8n8.x4.shared.b16 {%0,%1,%2,%3}, [%4];"
      : "=r"(r[0]), "=r"(r[1]), "=r"(r[2]), "=r"(r[3]) : "r"(addr));
}
__device__ __forceinline__ void mma_s8(int* d, const uint32_t* a,
                                       const uint32_t* b) {
  asm volatile(
      "mma.sync.aligned.m16n8k32.row.col.s32.s8.s8.s32 "
      "{%0,%1,%2,%3}, {%4,%5,%6,%7}, {%8,%9}, {%0,%1,%2,%3};"
      : "+r"(d[0]), "+r"(d[1]), "+r"(d[2]), "+r"(d[3])
      : "r"(a[0]), "r"(a[1]), "r"(a[2]), "r"(a[3]), "r"(b[0]), "r"(b[1]));
}
__device__ __forceinline__ void cpasync16(uint32_t dst, const void* src) {
  asm volatile("cp.async.cg.shared.global [%0], [%1], 16;"
               ::"r"(dst), "l"(src) : "memory");
}
__device__ __forceinline__ void cp_commit() {
  asm volatile("cp.async.commit_group;" ::: "memory");
}
template <int N>
__device__ __forceinline__ void cp_wait() {
  asm volatile("cp.async.wait_group %0;" ::"n"(N) : "memory");
}
__device__ __forceinline__ uint32_t swz64(uint32_t off) {
  return off ^ ((off >> 3) & 0x30);
}

// ============================================================================
// Row quantization: fp32 [rows x 1024] -> int8 hi/lo + per-row scale.
// SRC 0: x (param) -> g_x8*, g_sx.   SRC 1: g_attn -> g_a8*, g_sa.
// ============================================================================
template <int SRC>
__global__ __launch_bounds__(256) void quant_rows(const float* __restrict__ in) {
  const int w = threadIdx.x >> 5, lane = threadIdx.x & 31;
  const int row = blockIdx.x * 8 + w;
  const float* src = (SRC ? g_attn : in) + (size_t)row * 1024;
  float4 v[8];
  float mx = 0.f;
#pragma unroll
  for (int j = 0; j < 8; ++j) {
    v[j] = *(const float4*)(src + j * 128 + lane * 4);
    mx = fmaxf(mx, fmaxf(fmaxf(fabsf(v[j].x), fabsf(v[j].y)),
                         fmaxf(fabsf(v[j].z), fabsf(v[j].w))));
  }
#pragma unroll
  for (int d = 16; d; d >>= 1) mx = fmaxf(mx, __shfl_xor_sync(~0u, mx, d));
  mx = fmaxf(mx, 1e-20f);
  const float inv = 32512.f / mx;
  if (lane == 0) (SRC ? g_sa : g_sx)[row] = mx * (1.f / 32512.f);
  int8_t* qh = SRC ? g_a8h : g_x8h;
  int8_t* ql = SRC ? g_a8l : g_x8l;
#pragma unroll
  for (int j = 0; j < 8; ++j) {
    float f[4] = {v[j].x, v[j].y, v[j].z, v[j].w};
    char h4[4], l4[4];
#pragma unroll
    for (int e = 0; e < 4; ++e) {
      const int q = __float2int_rn(f[e] * inv);
      const int qlv = ((q + 128) & 255) - 128;
      h4[e] = (char)((q - qlv) >> 8);
      l4[e] = (char)qlv;
    }
    const size_t o = (size_t)row * 1024 + j * 128 + lane * 4;
    *(uint32_t*)(qh + o) = *(uint32_t*)h4;
    *(uint32_t*)(ql + o) = *(uint32_t*)l4;
  }
}

// ============================================================================
// Per-column absmax of W[1024x1024] (column = output feature).
// grid (32, 4), block (32, 8).
// ============================================================================
__global__ void colmax(const float* __restrict__ Wq,
                       const float* __restrict__ Wk,
                       const float* __restrict__ Wv,
                       const float* __restrict__ Wo) {
  const int w = blockIdx.y;
  const float* W = (w == 0) ? Wq : (w == 1) ? Wk : (w == 2) ? Wv : Wo;
  const int col = blockIdx.x * 32 + threadIdx.x;
  const int ty = threadIdx.y;
  float mx = 0.f;
  for (int r = ty; r < 1024; r += 8)
    mx = fmaxf(mx, fabsf(W[(size_t)r * 1024 + col]));
  __shared__ float sm[8][32];
  sm[ty][threadIdx.x] = mx;
  __syncthreads();
  if (ty == 0) {
#pragma unroll
    for (int i = 1; i < 8; ++i) mx = fmaxf(mx, sm[i][threadIdx.x]);
    g_sWmax[w * 1024 + col] = fmaxf(mx, 1e-20f);
  }
}

// ============================================================================
// Transpose + quantize W -> Wt[N][K] int8 hi/lo.  grid (32, 32, 4), blk (32,8)
// ============================================================================
__global__ __launch_bounds__(256) void quantW(const float* __restrict__ Wq,
                                              const float* __restrict__ Wk,
                                              const float* __restrict__ Wv,
                                              const float* __restrict__ Wo) {
  const int w = blockIdx.z;
  const float* W = (w == 0) ? Wq : (w == 1) ? Wk : (w == 2) ? Wv : Wo;
  int8_t* Th = g_W8h + (size_t)w * 1024 * 1024;
  int8_t* Tl = g_W8l + (size_t)w * 1024 * 1024;
  __shared__ float tile[32][33];
  const int bx = blockIdx.x * 32, by = blockIdx.y * 32;
  const int tx = threadIdx.x, ty = threadIdx.y;
#pragma unroll
  for (int j = 0; j < 4; ++j)
    tile[ty + j * 8][tx] = W[(size_t)(by + ty + j * 8) * 1024 + bx + tx];
  __syncthreads();
#pragma unroll
  for (int j = 0; j < 4; ++j) {
    const int orow = bx + ty + j * 8;  // output-feature index (Wt row)
    const float mx = g_sWmax[w * 1024 + orow];
    const float inv = 32512.f / mx;
    const float v = tile[tx][ty + j * 8];
    const int q = __float2int_rn(v * inv);
    const int qlv = ((q + 128) & 255) - 128;
    const size_t o = (size_t)orow * 1024 + by + tx;
    Th[o] = (int8_t)((q - qlv) >> 8);
    Tl[o] = (int8_t)qlv;
    if (by + tx == 0) g_sW[w * 1024 + orow] = mx * (1.f / 32512.f);
  }
}

// ============================================================================
// IMMA GEMM: C[8192,1024] = A @ Wt^T.  CTA 128x128, 8 warps of 64x32,
// K staged 64 bytes, cp.async double buffer, 64B-row swizzle + ldmatrix.
// FUSED=1: QKV (blockIdx.z selects weight set).  FUSED=0: output proj.
// ============================================================================
constexpr int PIECE8 = 128 * KT;            // 8192
constexpr int STAGE8 = 4 * PIECE8;          // 32768
constexpr int GEMM_SMEM8 = 2 * STAGE8;      // 65536

template <int FUSED>
__global__ __launch_bounds__(256, 1) void gemm_i8(
    const float* __restrict__ bias_q, const float* __restrict__ bias_k,
    const float* __restrict__ bias_v, float* __restrict__ outO) {
  extern __shared__ __align__(16) char smem[];
  const uint32_t sb = smem_u32(smem);
  const int tid = threadIdx.x, wid = tid >> 5, lane = tid & 31;
  const int wm = wid >> 2, wn = wid & 3;
  const int bm = blockIdx.y, bn = blockIdx.x;
  const int w = FUSED ? (int)blockIdx.z : 3;  // 0=Q 1=K 2=V 3=O

  const int8_t* Ah = FUSED ? g_x8h : g_a8h;
  const int8_t* Al = FUSED ? g_x8l : g_a8l;
  const int8_t* Bh = g_W8h + (size_t)w * 1024 * 1024;
  const int8_t* Bl = g_W8l + (size_t)w * 1024 * 1024;
  const float* bias = FUSED
                          ? ((w == 0) ? bias_q : (w == 1) ? bias_k : bias_v)
                          : bias_q;
  const float* sRow = FUSED ? g_sx : g_sa;
  const float* sCol = g_sW + w * 1024;

  // loader: piece p = tid>>6 (0:Ah 1:Al 2:Bh 3:Bl), q = tid&63
  const int p = tid >> 6, q = tid & 63;
  const int8_t* psrc;
  {
    const size_t arow = (size_t)bm * 128 * KDIM;
    const size_t brow = (size_t)bn * 128 * KDIM;
    psrc = (p == 0) ? Ah + arow : (p == 1) ? Al + arow
                                : (p == 2) ? Bh + brow : Bl + brow;
  }
  auto issue = [&](int kt) {
    const int buf = kt & 1;
    const uint32_t dstbase = sb + buf * STAGE8 + p * PIECE8;
#pragma unroll
    for (int j = 0; j < 8; ++j) {
      const int cid = q + j * 64;
      const int r = cid >> 2, cb = cid & 3;
      cpasync16(dstbase + swz64((uint32_t)(r * 64 + cb * 16)),
                psrc + (size_t)r * KDIM + kt * KT + cb * 16);
    }
    cp_commit();
  };

  int acc_hh[4][4][4], acc_cx[4][4][4];
#pragma unroll
  for (int i = 0; i < 4; ++i)
#pragma unroll
    for (int j = 0; j < 4; ++j)
#pragma unroll
      for (int k = 0; k < 4; ++k) {
        acc_hh[i][j][k] = 0;
        acc_cx[i][j][k] = 0;
      }

  issue(0);
#pragma unroll 1
  for (int kt = 0; kt < NKT; ++kt) {
    if (kt + 1 < NKT) {
      issue(kt + 1);
      cp_wait<1>();
    } else {
      cp_wait<0>();
    }
    __syncthreads();

    const uint32_t base = sb + (kt & 1) * STAGE8;
#pragma unroll
    for (int ks = 0; ks < 2; ++ks) {
      const int k0 = ks * 32;
      uint32_t ah[4][4], al[4][4], bh[2][4], bl[2][4];
#pragma unroll
      for (int mt = 0; mt < 4; ++mt) {
        const uint32_t row = wm * 64 + mt * 16 + (lane & 15);
        const uint32_t off = row * 64 + k0 + ((lane >> 4) << 4);
        ldsm4(ah[mt], base + swz64(off));
        ldsm4(al[mt], base + PIECE8 + swz64(off));
      }
#pragma unroll
      for (int nt2 = 0; nt2 < 2; ++nt2) {
        const uint32_t row =
            wn * 32 + nt2 * 16 + (lane & 7) + ((lane >> 4) << 3);
        const uint32_t off = row * 64 + k0 + (((lane >> 3) & 1) << 4);
        ldsm4(bh[nt2], base + 2 * PIECE8 + swz64(off));
        ldsm4(bl[nt2], base + 3 * PIECE8 + swz64(off));
      }
      // term pass 1: hh
#pragma unroll
      for (int mt = 0; mt < 4; ++mt)
#pragma unroll
        for (int nt = 0; nt < 4; ++nt)
          mma_s8(acc_hh[mt][nt], ah[mt], &bh[nt >> 1][(nt & 1) * 2]);
      // term pass 2: hl -> cross
#pragma unroll
      for (int mt = 0; mt < 4; ++mt)
#pragma unroll
        for (int nt = 0; nt < 4; ++nt)
          mma_s8(acc_cx[mt][nt], ah[mt], &bl[nt >> 1][(nt & 1) * 2]);
      // term pass 3: lh -> cross
#pragma unroll
      for (int mt = 0; mt < 4; ++mt)
#pragma unroll
        for (int nt = 0; nt < 4; ++nt)
          mma_s8(acc_cx[mt][nt], al[mt], &bh[nt >> 1][(nt & 1) * 2]);
    }
    __syncthreads();
  }

  // ---- epilogue ----
  const int g = lane >> 2, t2 = (lane & 3) * 2;
#pragma unroll
  for (int mt = 0; mt < 4; ++mt) {
    const int r0 = bm * 128 + wm * 64 + mt * 16 + g;
    const int r1 = r0 + 8;
    const float s0 = __ldg(&sRow[r0]), s1 = __ldg(&sRow[r1]);
    float sn0 = 0.f, cs0 = 0.f, sn1 = 0.f, cs1 = 0.f;
    if (FUSED && w <= 1) {
      sincosf(ANGC * (float)(r0 & (Tc - 1)), &sn0, &cs0);
      sincosf(ANGC * (float)(r1 & (Tc - 1)), &sn1, &cs1);
    }
#pragma unroll
    for (int nt = 0; nt < 4; ++nt) {
      const int col = bn * 128 + wn * 32 + nt * 8 + t2;
      const float ta = __ldg(&sCol[col]), tb = __ldg(&sCol[col + 1]);
      const float b0 = __ldg(&bias[col]), b1 = __ldg(&bias[col + 1]);
      const int* hh = acc_hh[mt][nt];
      const int* cx = acc_cx[mt][nt];
      const float v00 =
          (65536.f * (float)hh[0] + 256.f * (float)cx[0]) * (s0 * ta) + b0;
      const float v01 =
          (65536.f * (float)hh[1] + 256.f * (float)cx[1]) * (s0 * tb) + b1;
      const float v10 =
          (65536.f * (float)hh[2] + 256.f * (float)cx[2]) * (s1 * ta) + b0;
      const float v11 =
          (65536.f * (float)hh[3] + 256.f * (float)cx[3]) * (s1 * tb) + b1;
      if (!FUSED) {
        *(float2*)&outO[(size_t)r0 * DM + col] = make_float2(v00, v01);
        *(float2*)&outO[(size_t)r1 * DM + col] = make_float2(v10, v11);
      } else if (w == 2) {
        *(float2*)&g_V[(size_t)r0 * HD + col] = make_float2(v00, v01);
        *(float2*)&g_V[(size_t)r1 * HD + col] = make_float2(v10, v11);
      } else {
        const float a00 = fmaxf(v00, 0.f), a01 = fmaxf(v01, 0.f);
        const float a10 = fmaxf(v10, 0.f), a11 = fmaxf(v11, 0.f);
        float* dc = (w == 0) ? g_Qc : g_Kc;
        float* ds = (w == 0) ? g_Qs : g_Ks;
        *(float2*)&dc[(size_t)r0 * HD + col] =
            make_float2(a00 * cs0, a01 * cs0);
        *(float2*)&dc[(size_t)r1 * HD + col] =
            make_float2(a10 * cs1, a11 * cs1);
        *(float2*)&ds[(size_t)r0 * HD + col] =
            make_float2(a00 * sn0, a01 * sn0);
        *(float2*)&ds[(size_t)r1 * HD + col] =
            make_float2(a10 * sn1, a11 * sn1);
      }
    }
  }
}

// ============================================================================
// Pass A: per-chunk states S_c = Kc^T V, Ks^T V (64x64), z = col-sums of K.
// ============================================================================
__global__ __launch_bounds__(256) void chunk_stats() {
  const int blk = blockIdx.x;
  const int c = blk & (NCH - 1);
  const int bh = blk >> 5;
  const int b = bh >> 4, h = bh & 15;
  const int tid = threadIdx.x, tx = tid & 15, ty = tid >> 4;

  __shared__ __align__(16) float sKc[32][64];
  __shared__ __align__(16) float sKs[32][64];
  __shared__ __align__(16) float sV[32][64];

  float aC[4][4] = {}, aS[4][4] = {};
  float zc[4] = {}, zs[4] = {};
  const size_t rowbase = ((size_t)b * Tc + (size_t)c * CH) * HD + h * DHc;

  for (int t0 = 0; t0 < CH; t0 += 32) {
    __syncthreads();
    for (int l = tid; l < 32 * 16; l += 256) {
      const int r = l >> 4, cc = (l & 15) << 2;
      const size_t g = rowbase + (size_t)(t0 + r) * HD + cc;
      *(float4*)&sKc[r][cc] = *(const float4*)&g_Kc[g];
      *(float4*)&sKs[r][cc] = *(const float4*)&g_Ks[g];
      *(float4*)&sV[r][cc] = *(const float4*)&g_V[g];
    }
    __syncthreads();
#pragma unroll 4
    for (int t = 0; t < 32; ++t) {
      float kc[4], ks[4], v[4];
#pragma unroll
      for (int i = 0; i < 4; ++i) {
        kc[i] = sKc[t][ty * 4 + i];
        ks[i] = sKs[t][ty * 4 + i];
      }
#pragma unroll
      for (int j = 0; j < 4; ++j) v[j] = sV[t][tx * 4 + j];
#pragma unroll
      for (int i = 0; i < 4; ++i)
#pragma unroll
        for (int j = 0; j < 4; ++j) {
          aC[i][j] += kc[i] * v[j];
          aS[i][j] += ks[i] * v[j];
        }
      if (tx == 0) {
#pragma unroll
        for (int i = 0; i < 4; ++i) { zc[i] += kc[i]; zs[i] += ks[i]; }
      }
    }
  }

  const size_t sbse = ((size_t)bh * NCH + c) * (DHc * DHc);
#pragma unroll
  for (int i = 0; i < 4; ++i) {
    *(float4*)&g_Scos[sbse + (size_t)(ty * 4 + i) * 64 + tx * 4] =
        make_float4(aC[i][0], aC[i][1], aC[i][2], aC[i][3]);
    *(float4*)&g_Ssin[sbse + (size_t)(ty * 4 + i) * 64 + tx * 4] =
        make_float4(aS[i][0], aS[i][1], aS[i][2], aS[i][3]);
  }
  if (tx == 0) {
    const size_t zb = ((size_t)bh * NCH + c) * DHc;
#pragma unroll
    for (int i = 0; i < 4; ++i) {
      g_zcos[zb + ty * 4 + i] = zc[i];
      g_zsin[zb + ty * 4 + i] = zs[i];
    }
  }
}

// ============================================================================
// Pass B: exclusive prefix over chunks. grid (16, 32) x 256 threads.
// ============================================================================
__global__ __launch_bounds__(256) void chunk_scan2() {
  const int bh = blockIdx.y;
  const int e = blockIdx.x * 256 + threadIdx.x;
  {
    const size_t base = (size_t)bh * NCH * (DHc * DHc) + e;
    float ac = 0.f, as2 = 0.f;
#pragma unroll 1
    for (int c = 0; c < NCH; ++c) {
      const size_t idx = base + (size_t)c * (DHc * DHc);
      const float tc = g_Scos[idx], ts = g_Ssin[idx];
      g_Scos[idx] = ac;
      g_Ssin[idx] = as2;
      ac += tc;
      as2 += ts;
    }
  }
  if (blockIdx.x == 0 && threadIdx.x < DHc) {
    const size_t zb = (size_t)bh * NCH * DHc + threadIdx.x;
    float ac = 0.f, as2 = 0.f;
#pragma unroll 1
    for (int c = 0; c < NCH; ++c) {
      const size_t idx = zb + (size_t)c * DHc;
      const float tc = g_zcos[idx], ts = g_zsin[idx];
      g_zcos[idx] = ac;
      g_zsin[idx] = as2;
      ac += tc;
      as2 += ts;
    }
  }
}

// ============================================================================
// Pass C: per-chunk output (intra causal + inter state), fp32.
// ============================================================================
constexpr int SQ_LD = 65;
constexpr int SA_LD = 129;
constexpr int OFF_QC = 0;
constexpr int OFF_QS = CH * SQ_LD;
constexpr int OFF_KC = 2 * CH * SQ_LD;
constexpr int OFF_KS = 3 * CH * SQ_LD;
constexpr int OFF_A = 4 * CH * SQ_LD;
constexpr int OFF_DEN = OFF_A + CH * SA_LD;
constexpr int OFF_ZC = OFF_DEN + CH;
constexpr int OFF_ZS = OFF_ZC + DHc;
constexpr int SMEM_FLOATS = OFF_ZS + DHc;

__global__ __launch_bounds__(256, 1) void attn_out() {
  extern __shared__ __align__(16) float sm[];
  const int blk = blockIdx.x;
  const int c = blk & (NCH - 1);
  const int bh = blk >> 5;
  const int b = bh >> 4, h = bh & 15;
  const int tid = threadIdx.x, tx = tid & 15, ty = tid >> 4;

  float* sQc = sm + OFF_QC;
  float* sQs = sm + OFF_QS;
  float* sKc = sm + OFF_KC;
  float* sKs = sm + OFF_KS;
  float* sA = sm + OFF_A;
  float* sDen = sm + OFF_DEN;
  float* szc = sm + OFF_ZC;
  float* szs = sm + OFF_ZS;
  float* sV = sKc;
  float* sScos = sKs;
  float* sSsin = sKs + DHc * DHc;

  const size_t gbase = ((size_t)b * Tc + (size_t)c * CH) * HD + h * DHc;

  for (int l = tid; l < CH * 16; l += 256) {
    const int r = l >> 4, cc = (l & 15) << 2;
    const size_t g = gbase + (size_t)r * HD + cc;
    float4 vq = *(const float4*)&g_Qc[g];
    float4 vs = *(const float4*)&g_Qs[g];
    float4 vk = *(const float4*)&g_Kc[g];
    float4 vx = *(const float4*)&g_Ks[g];
    float* pp;
    pp = &sQc[r * SQ_LD + cc]; pp[0]=vq.x; pp[1]=vq.y; pp[2]=vq.z; pp[3]=vq.w;
    pp = &sQs[r * SQ_LD + cc]; pp[0]=vs.x; pp[1]=vs.y; pp[2]=vs.z; pp[3]=vs.w;
    pp = &sKc[r * SQ_LD + cc]; pp[0]=vk.x; pp[1]=vk.y; pp[2]=vk.z; pp[3]=vk.w;
    pp = &sKs[r * SQ_LD + cc]; pp[0]=vx.x; pp[1]=vx.y; pp[2]=vx.z; pp[3]=vx.w;
  }
  __syncthreads();

  const int t0 = ty * 8, s0 = tx * 8;
  float a[8][8] = {};
  if (tx <= ty) {
#pragma unroll 2
    for (int d = 0; d < DHc; ++d) {
      float qc[8], qs[8], kc[8], ks[8];
#pragma unroll
      for (int i = 0; i < 8; ++i) {
        qc[i] = sQc[(t0 + i) * SQ_LD + d];
        qs[i] = sQs[(t0 + i) * SQ_LD + d];
      }
#pragma unroll
      for (int j = 0; j < 8; ++j) {
        kc[j] = sKc[(s0 + j) * SQ_LD + d];
        ks[j] = sKs[(s0 + j) * SQ_LD + d];
      }
#pragma unroll
      for (int i = 0; i < 8; ++i)
#pragma unroll
        for (int j = 0; j < 8; ++j) {
          a[i][j] += qc[i] * kc[j];
          a[i][j] += qs[i] * ks[j];
        }
    }
  }
#pragma unroll
  for (int i = 0; i < 8; ++i) {
    const int t = t0 + i;
    float rs = 0.f;
#pragma unroll
    for (int j = 0; j < 8; ++j) {
      const float v = (s0 + j <= t) ? a[i][j] : 0.f;
      sA[t * SA_LD + s0 + j] = v;
      rs += v;
    }
    rs += __shfl_xor_sync(0xffffffffu, rs, 1);
    rs += __shfl_xor_sync(0xffffffffu, rs, 2);
    rs += __shfl_xor_sync(0xffffffffu, rs, 4);
    rs += __shfl_xor_sync(0xffffffffu, rs, 8);
    if (tx == 0) sDen[t] = rs;
  }
  __syncthreads();

  for (int l = tid; l < CH * 16; l += 256) {
    const int r = l >> 4, cc = (l & 15) << 2;
    *(float4*)&sV[r * 64 + cc] =
        *(const float4*)&g_V[gbase + (size_t)r * HD + cc];
  }
  const size_t sbse = ((size_t)bh * NCH + c) * (DHc * DHc);
  for (int l = tid; l < 64 * 16; l += 256) {
    const int r = l >> 4, cc = (l & 15) << 2;
    *(float4*)&sScos[r * 64 + cc] = *(const float4*)&g_Scos[sbse + r * 64 + cc];
    *(float4*)&sSsin[r * 64 + cc] = *(const float4*)&g_Ssin[sbse + r * 64 + cc];
  }
  if (tid < DHc) {
    const size_t zb = ((size_t)bh * NCH + c) * DHc;
    szc[tid] = g_zcos[zb + tid];
    szs[tid] = g_zsin[zb + tid];
  }
  __syncthreads();

  float o[8][4] = {};
  float dden[8] = {};
  const int n0 = tx * 4;
  const int smax = t0 + 8;
#pragma unroll 2
  for (int s = 0; s < smax; ++s) {
    const float4 v4 = *(const float4*)&sV[s * 64 + n0];
#pragma unroll
    for (int i = 0; i < 8; ++i) {
      const float av = sA[(t0 + i) * SA_LD + s];
      o[i][0] += av * v4.x;
      o[i][1] += av * v4.y;
      o[i][2] += av * v4.z;
      o[i][3] += av * v4.w;
    }
  }
#pragma unroll 2
  for (int d = 0; d < DHc; ++d) {
    const float4 sc = *(const float4*)&sScos[d * 64 + n0];
    const float4 ss = *(const float4*)&sSsin[d * 64 + n0];
    const float zc = szc[d], zs = szs[d];
#pragma unroll
    for (int i = 0; i < 8; ++i) {
      const float qc = sQc[(t0 + i) * SQ_LD + d];
      const float qs = sQs[(t0 + i) * SQ_LD + d];
      o[i][0] += qc * sc.x + qs * ss.x;
      o[i][1] += qc * sc.y + qs * ss.y;
      o[i][2] += qc * sc.z + qs * ss.z;
      o[i][3] += qc * sc.w + qs * ss.w;
      dden[i] += qc * zc + qs * zs;
    }
  }
#pragma unroll
  for (int i = 0; i < 8; ++i) {
    const int t = t0 + i;
    float den = fmaxf(sDen[t] + dden[i], 1e-6f);
    const float inv = 1.0f / den;
    *(float4*)&g_attn[gbase + (size_t)t * HD + n0] =
        make_float4(o[i][0] * inv, o[i][1] * inv, o[i][2] * inv, o[i][3] * inv);
  }
}

}  // namespace cf

extern "C" void kernel_launch(void* const* d_in, const int* in_sizes, int n_in,
                              void* d_out, int out_size) {
  using namespace cf;
  const float* x = (const float*)d_in[0];
  const float* Wq = (const float*)d_in[1];
  const float* bq = (const float*)d_in[2];
  const float* Wk = (const float*)d_in[3];
  const float* bk = (const float*)d_in[4];
  const float* Wv = (const float*)d_in[5];
  const float* bv = (const float*)d_in[6];
  const float* Wo = (const float*)d_in[7];
  const float* bo = (const float*)d_in[8];
  float* out = (float*)d_out;

  cudaFuncSetAttribute(gemm_i8<1>, cudaFuncAttributeMaxDynamicSharedMemorySize, GEMM_SMEM8);
  cudaFuncSetAttribute(gemm_i8<0>, cudaFuncAttributeMaxDynamicSharedMemorySize, GEMM_SMEM8);
  cudaFuncSetAttribute(attn_out, cudaFuncAttributeMaxDynamicSharedMemorySize,
                       (int)(SMEM_FLOATS * sizeof(float)));

  // 1) quantize inputs and weights
  quant_rows<0><<<Mrows / 8, 256>>>(x);
  colmax<<<dim3(32, 4), dim3(32, 8)>>>(Wq, Wk, Wv, Wo);
  quantW<<<dim3(32, 32, 4), dim3(32, 8)>>>(Wq, Wk, Wv, Wo);

  // 2) fused QKV projection GEMMs (int8 tensor cores)
  dim3 gq(HD / 128, Mrows / 128, 3);
  gemm_i8<1><<<gq, 256, GEMM_SMEM8>>>(bq, bk, bv, nullptr);

  // 3) attention
  chunk_stats<<<BHc * NCH, 256>>>();
  chunk_scan2<<<dim3(16, 32), 256>>>();
  attn_out<<<BHc * NCH, 256, SMEM_FLOATS * sizeof(float)>>>();

  // 4) output GEMM
  quant_rows<1><<<Mrows / 8, 256>>>(nullptr);
  dim3 go(HD / 128, Mrows / 128, 1);
  gemm_i8<0><<<go, 256, GEMM_SMEM8>>>(bo, nullptr, nullptr, out);
}

// round 6
// speedup vs baseline: 2.0248x; 2.0248x over previous
#include <cuda_runtime.h>
#include <cuda_bf16.h>
#include <math.h>
#include <stdint.h>

// ============================================================================
// CosFormer attention (sm_103 base target -> legacy HMMA bf16 mma.sync).
// GEMMs: bf16x3 fp32-emulation split (hh+hl+lh), term-pass reordering.
// Attention: chunked linear attention fp32, balanced triangle tiling,
// folded-row AV phase, fused rowsum, direct bf16-split epilogue.
// ============================================================================

namespace cf {

constexpr int Bc = 2, Tc = 4096, Hc = 16, DHc = 64;
constexpr int DM = 1024, HD = 1024;
constexpr int Mrows = Bc * Tc;            // 8192
constexpr int CH = 128, NCH = Tc / CH;    // 128, 32
constexpr int BHc = Bc * Hc;              // 32
constexpr float ANGC = 3.14159265358979323846f / (2.0f * (float)Tc);

constexpr int KDIM = 1024;
constexpr int KT = 64;
constexpr int NKT = KDIM / KT;            // 16

// ---- fp32 scratch ----
__device__ __align__(16) float g_Qc[(size_t)Mrows * HD];
__device__ __align__(16) float g_Qs[(size_t)Mrows * HD];
__device__ __align__(16) float g_Kc[(size_t)Mrows * HD];
__device__ __align__(16) float g_Ks[(size_t)Mrows * HD];
__device__ __align__(16) float g_V [(size_t)Mrows * HD];
__device__ __align__(16) float g_Scos[(size_t)BHc * NCH * DHc * DHc];
__device__ __align__(16) float g_Ssin[(size_t)BHc * NCH * DHc * DHc];
__device__ __align__(16) float g_zcos[(size_t)BHc * NCH * DHc];
__device__ __align__(16) float g_zsin[(size_t)BHc * NCH * DHc];

// ---- bf16 split operands ----
__device__ __align__(16) __nv_bfloat16 g_xh[(size_t)Mrows * DM];
__device__ __align__(16) __nv_bfloat16 g_xl[(size_t)Mrows * DM];
__device__ __align__(16) __nv_bfloat16 g_ah[(size_t)Mrows * HD];
__device__ __align__(16) __nv_bfloat16 g_al[(size_t)Mrows * HD];
__device__ __align__(16) __nv_bfloat16 g_Wqh[(size_t)HD * DM];
__device__ __align__(16) __nv_bfloat16 g_Wql[(size_t)HD * DM];
__device__ __align__(16) __nv_bfloat16 g_Wkh[(size_t)HD * DM];
__device__ __align__(16) __nv_bfloat16 g_Wkl[(size_t)HD * DM];
__device__ __align__(16) __nv_bfloat16 g_Wvh[(size_t)HD * DM];
__device__ __align__(16) __nv_bfloat16 g_Wvl[(size_t)HD * DM];
__device__ __align__(16) __nv_bfloat16 g_Woh[(size_t)DM * HD];
__device__ __align__(16) __nv_bfloat16 g_Wol[(size_t)DM * HD];

// ============================================================================
// helpers
// ============================================================================
__device__ __forceinline__ uint32_t smem_u32(const void* p) {
  uint32_t a;
  asm("{ .reg .u64 t; cvta.to.shared.u64 t, %1; cvt.u32.u64 %0, t; }"
      : "=r"(a) : "l"(p));
  return a;
}
__device__ __forceinline__ void ldsm4(uint32_t* r, uint32_t addr) {
  asm volatile(
      "ldmatrix.sync.aligned.m8n8.x4.shared.b16 {%0,%1,%2,%3}, [%4];"
      : "=r"(r[0]), "=r"(r[1]), "=r"(r[2]), "=r"(r[3]) : "r"(addr));
}
__device__ __forceinline__ void mma16816(float* d, const uint32_t* a,
                                         const uint32_t* b) {
  asm volatile(
      "mma.sync.aligned.m16n8k16.row.col.f32.bf16.bf16.f32 "
      "{%0,%1,%2,%3}, {%4,%5,%6,%7}, {%8,%9}, {%0,%1,%2,%3};"
      : "+f"(d[0]), "+f"(d[1]), "+f"(d[2]), "+f"(d[3])
      : "r"(a[0]), "r"(a[1]), "r"(a[2]), "r"(a[3]), "r"(b[0]), "r"(b[1]));
}
__device__ __forceinline__ void cpasync16(uint32_t dst, const void* src) {
  asm volatile("cp.async.cg.shared.global [%0], [%1], 16;"
               ::"r"(dst), "l"(src) : "memory");
}
__device__ __forceinline__ void cp_commit() {
  asm volatile("cp.async.commit_group;" ::: "memory");
}
template <int N>
__device__ __forceinline__ void cp_wait() {
  asm volatile("cp.async.wait_group %0;" ::"n"(N) : "memory");
}

// ============================================================================
// Splits: fp32 -> (bf16 hi, bf16 lo)
// ============================================================================
__global__ __launch_bounds__(256) void split_x(const float* __restrict__ in) {
  int i = blockIdx.x * 256 + threadIdx.x;
  float4 v = *(const float4*)(in + (size_t)i * 4);
  __nv_bfloat16 h[4], l[4];
  float f[4] = {v.x, v.y, v.z, v.w};
#pragma unroll
  for (int j = 0; j < 4; ++j) {
    h[j] = __float2bfloat16(f[j]);
    l[j] = __float2bfloat16(f[j] - __bfloat162float(h[j]));
  }
  *(uint2*)(g_xh + (size_t)i * 4) = *(uint2*)h;
  *(uint2*)(g_xl + (size_t)i * 4) = *(uint2*)l;
}

template <int WSEL>
__global__ __launch_bounds__(256) void tsplit(const float* __restrict__ W) {
  __nv_bfloat16* Th = (WSEL == 0) ? g_Wqh : (WSEL == 1) ? g_Wkh
                        : (WSEL == 2) ? g_Wvh : g_Woh;
  __nv_bfloat16* Tl = (WSEL == 0) ? g_Wql : (WSEL == 1) ? g_Wkl
                        : (WSEL == 2) ? g_Wvl : g_Wol;
  __shared__ float tile[32][33];
  const int bx = blockIdx.x * 32, by = blockIdx.y * 32;
  const int tx = threadIdx.x, ty = threadIdx.y;  // (32, 8)
#pragma unroll
  for (int j = 0; j < 4; ++j)
    tile[ty + j * 8][tx] = W[(size_t)(by + ty + j * 8) * 1024 + bx + tx];
  __syncthreads();
#pragma unroll
  for (int j = 0; j < 4; ++j) {
    float v = tile[tx][ty + j * 8];
    __nv_bfloat16 h = __float2bfloat16(v);
    __nv_bfloat16 l = __float2bfloat16(v - __bfloat162float(h));
    const size_t o = (size_t)(bx + ty + j * 8) * 1024 + by + tx;
    Th[o] = h;
    Tl[o] = l;
  }
}

// ============================================================================
// HMMA GEMM (round-4 proven): 128x128 CTA, 8 warps of 64x32, K staged 64,
// cp.async double buffer, SW128 swizzle + ldmatrix, 3 term passes.
// ============================================================================
constexpr int PIECE_BYTES = 128 * KT * 2;         // 16384
constexpr int STAGE_BYTES = 4 * PIECE_BYTES;      // 65536
constexpr int GEMM_SMEM = 2 * STAGE_BYTES;        // 131072

template <int FUSED>
__global__ __launch_bounds__(256, 1) void gemm_mma(
    const float* __restrict__ bias_q, const float* __restrict__ bias_k,
    const float* __restrict__ bias_v, float* __restrict__ outO) {
  extern __shared__ __align__(16) char smem[];
  const uint32_t sb = smem_u32(smem);
  const int tid = threadIdx.x, wid = tid >> 5, lane = tid & 31;
  const int wm = wid >> 2, wn = wid & 3;
  const int bm = blockIdx.y, bn = blockIdx.x;
  const int w = FUSED ? (int)blockIdx.z : 3;  // 0=Q 1=K 2=V 3=O

  const __nv_bfloat16* Ah = FUSED ? g_xh : g_ah;
  const __nv_bfloat16* Al = FUSED ? g_xl : g_al;
  const __nv_bfloat16* Bh = (w == 0) ? g_Wqh : (w == 1) ? g_Wkh
                              : (w == 2) ? g_Wvh : g_Woh;
  const __nv_bfloat16* Bl = (w == 0) ? g_Wql : (w == 1) ? g_Wkl
                              : (w == 2) ? g_Wvl : g_Wol;
  const float* bias = FUSED
                          ? ((w == 0) ? bias_q : (w == 1) ? bias_k : bias_v)
                          : bias_q;

  const int p = tid >> 6, q = tid & 63;
  const __nv_bfloat16* psrc;
  {
    const size_t arow = (size_t)bm * 128 * KDIM;
    const size_t brow = (size_t)bn * 128 * KDIM;
    psrc = (p == 0) ? Ah + arow : (p == 1) ? Al + arow
                                : (p == 2) ? Bh + brow : Bl + brow;
  }
  const __nv_bfloat16* gbase = psrc + (size_t)(q >> 3) * KDIM + (q & 7) * 8;
  const uint32_t loff0 = (uint32_t)((q >> 3) * 128 + (q & 7) * 16);

  auto issue = [&](int kt) {
    const int buf = kt & 1;
    const __nv_bfloat16* g = gbase + kt * KT;
    const uint32_t dstbase = sb + buf * STAGE_BYTES + p * PIECE_BYTES;
#pragma unroll
    for (int j = 0; j < 16; ++j) {
      const uint32_t off = loff0 + j * 1024;
      const uint32_t swz = off ^ ((off >> 3) & 0x70);
      cpasync16(dstbase + swz, g + (size_t)j * 8 * KDIM);
    }
    cp_commit();
  };

  float acc[4][4][4];
#pragma unroll
  for (int i = 0; i < 4; ++i)
#pragma unroll
    for (int j = 0; j < 4; ++j)
#pragma unroll
      for (int k = 0; k < 4; ++k) acc[i][j][k] = 0.f;

  issue(0);
#pragma unroll 1
  for (int kt = 0; kt < NKT; ++kt) {
    if (kt + 1 < NKT) {
      issue(kt + 1);
      cp_wait<1>();
    } else {
      cp_wait<0>();
    }
    __syncthreads();

    const uint32_t base = sb + (kt & 1) * STAGE_BYTES;
#pragma unroll
    for (int ks = 0; ks < 4; ++ks) {
      const int k0 = ks * 16;
      uint32_t ah[4][4], al[4][4], bh[2][4], bl[2][4];
#pragma unroll
      for (int mt = 0; mt < 4; ++mt) {
        const uint32_t row = wm * 64 + mt * 16 + (lane & 15);
        const uint32_t off = row * 128 + k0 * 2 + ((lane >> 4) << 4);
        const uint32_t swz = off ^ ((off >> 3) & 0x70);
        ldsm4(ah[mt], base + swz);
        ldsm4(al[mt], base + PIECE_BYTES + swz);
      }
#pragma unroll
      for (int nt2 = 0; nt2 < 2; ++nt2) {
        const uint32_t row =
            wn * 32 + nt2 * 16 + (lane & 7) + ((lane >> 4) << 3);
        const uint32_t off = row * 128 + k0 * 2 + (((lane >> 3) & 1) << 4);
        const uint32_t swz = off ^ ((off >> 3) & 0x70);
        ldsm4(bh[nt2], base + 2 * PIECE_BYTES + swz);
        ldsm4(bl[nt2], base + 3 * PIECE_BYTES + swz);
      }
#pragma unroll
      for (int mt = 0; mt < 4; ++mt)
#pragma unroll
        for (int nt = 0; nt < 4; ++nt)
          mma16816(acc[mt][nt], ah[mt], &bh[nt >> 1][(nt & 1) * 2]);
#pragma unroll
      for (int mt = 0; mt < 4; ++mt)
#pragma unroll
        for (int nt = 0; nt < 4; ++nt)
          mma16816(acc[mt][nt], ah[mt], &bl[nt >> 1][(nt & 1) * 2]);
#pragma unroll
      for (int mt = 0; mt < 4; ++mt)
#pragma unroll
        for (int nt = 0; nt < 4; ++nt)
          mma16816(acc[mt][nt], al[mt], &bh[nt >> 1][(nt & 1) * 2]);
    }
    __syncthreads();
  }

  const int g = lane >> 2, t2 = (lane & 3) * 2;
#pragma unroll
  for (int mt = 0; mt < 4; ++mt) {
    const int r0 = bm * 128 + wm * 64 + mt * 16 + g;
    const int r1 = r0 + 8;
    float sn0 = 0.f, cs0 = 0.f, sn1 = 0.f, cs1 = 0.f;
    if (FUSED && w <= 1) {
      sincosf(ANGC * (float)(r0 & (Tc - 1)), &sn0, &cs0);
      sincosf(ANGC * (float)(r1 & (Tc - 1)), &sn1, &cs1);
    }
#pragma unroll
    for (int nt = 0; nt < 4; ++nt) {
      const int col = bn * 128 + wn * 32 + nt * 8 + t2;
      const float b0 = __ldg(&bias[col]), b1 = __ldg(&bias[col + 1]);
      const float v00 = acc[mt][nt][0] + b0, v01 = acc[mt][nt][1] + b1;
      const float v10 = acc[mt][nt][2] + b0, v11 = acc[mt][nt][3] + b1;
      if (!FUSED) {
        *(float2*)&outO[(size_t)r0 * DM + col] = make_float2(v00, v01);
        *(float2*)&outO[(size_t)r1 * DM + col] = make_float2(v10, v11);
      } else if (w == 2) {
        *(float2*)&g_V[(size_t)r0 * HD + col] = make_float2(v00, v01);
        *(float2*)&g_V[(size_t)r1 * HD + col] = make_float2(v10, v11);
      } else {
        const float a00 = fmaxf(v00, 0.f), a01 = fmaxf(v01, 0.f);
        const float a10 = fmaxf(v10, 0.f), a11 = fmaxf(v11, 0.f);
        float* dc = (w == 0) ? g_Qc : g_Kc;
        float* ds = (w == 0) ? g_Qs : g_Ks;
        *(float2*)&dc[(size_t)r0 * HD + col] =
            make_float2(a00 * cs0, a01 * cs0);
        *(float2*)&dc[(size_t)r1 * HD + col] =
            make_float2(a10 * cs1, a11 * cs1);
        *(float2*)&ds[(size_t)r0 * HD + col] =
            make_float2(a00 * sn0, a01 * sn0);
        *(float2*)&ds[(size_t)r1 * HD + col] =
            make_float2(a10 * sn1, a11 * sn1);
      }
    }
  }
}

// ============================================================================
// Pass A: per-chunk states (unchanged from round 4)
// ============================================================================
__global__ __launch_bounds__(256) void chunk_stats() {
  const int blk = blockIdx.x;
  const int c = blk & (NCH - 1);
  const int bh = blk >> 5;
  const int b = bh >> 4, h = bh & 15;
  const int tid = threadIdx.x, tx = tid & 15, ty = tid >> 4;

  __shared__ __align__(16) float sKc[32][64];
  __shared__ __align__(16) float sKs[32][64];
  __shared__ __align__(16) float sV[32][64];

  float aC[4][4] = {}, aS[4][4] = {};
  float zc[4] = {}, zs[4] = {};
  const size_t rowbase = ((size_t)b * Tc + (size_t)c * CH) * HD + h * DHc;

  for (int t0 = 0; t0 < CH; t0 += 32) {
    __syncthreads();
    for (int l = tid; l < 32 * 16; l += 256) {
      const int r = l >> 4, cc = (l & 15) << 2;
      const size_t g = rowbase + (size_t)(t0 + r) * HD + cc;
      *(float4*)&sKc[r][cc] = *(const float4*)&g_Kc[g];
      *(float4*)&sKs[r][cc] = *(const float4*)&g_Ks[g];
      *(float4*)&sV[r][cc] = *(const float4*)&g_V[g];
    }
    __syncthreads();
#pragma unroll 4
    for (int t = 0; t < 32; ++t) {
      float kc[4], ks[4], v[4];
#pragma unroll
      for (int i = 0; i < 4; ++i) {
        kc[i] = sKc[t][ty * 4 + i];
        ks[i] = sKs[t][ty * 4 + i];
      }
#pragma unroll
      for (int j = 0; j < 4; ++j) v[j] = sV[t][tx * 4 + j];
#pragma unroll
      for (int i = 0; i < 4; ++i)
#pragma unroll
        for (int j = 0; j < 4; ++j) {
          aC[i][j] += kc[i] * v[j];
          aS[i][j] += ks[i] * v[j];
        }
      if (tx == 0) {
#pragma unroll
        for (int i = 0; i < 4; ++i) { zc[i] += kc[i]; zs[i] += ks[i]; }
      }
    }
  }

  const size_t sbse = ((size_t)bh * NCH + c) * (DHc * DHc);
#pragma unroll
  for (int i = 0; i < 4; ++i) {
    *(float4*)&g_Scos[sbse + (size_t)(ty * 4 + i) * 64 + tx * 4] =
        make_float4(aC[i][0], aC[i][1], aC[i][2], aC[i][3]);
    *(float4*)&g_Ssin[sbse + (size_t)(ty * 4 + i) * 64 + tx * 4] =
        make_float4(aS[i][0], aS[i][1], aS[i][2], aS[i][3]);
  }
  if (tx == 0) {
    const size_t zb = ((size_t)bh * NCH + c) * DHc;
#pragma unroll
    for (int i = 0; i < 4; ++i) {
      g_zcos[zb + ty * 4 + i] = zc[i];
      g_zsin[zb + ty * 4 + i] = zs[i];
    }
  }
}

// ============================================================================
// Pass B: exclusive prefix over chunks (unchanged)
// ============================================================================
__global__ __launch_bounds__(256) void chunk_scan2() {
  const int bh = blockIdx.y;
  const int e = blockIdx.x * 256 + threadIdx.x;
  {
    const size_t base = (size_t)bh * NCH * (DHc * DHc) + e;
    float ac = 0.f, as2 = 0.f;
#pragma unroll 1
    for (int c = 0; c < NCH; ++c) {
      const size_t idx = base + (size_t)c * (DHc * DHc);
      const float tc = g_Scos[idx], ts = g_Ssin[idx];
      g_Scos[idx] = ac;
      g_Ssin[idx] = as2;
      ac += tc;
      as2 += ts;
    }
  }
  if (blockIdx.x == 0 && threadIdx.x < DHc) {
    const size_t zb = (size_t)bh * NCH * DHc + threadIdx.x;
    float ac = 0.f, as2 = 0.f;
#pragma unroll 1
    for (int c = 0; c < NCH; ++c) {
      const size_t idx = zb + (size_t)c * DHc;
      const float tc = g_zcos[idx], ts = g_zsin[idx];
      g_zcos[idx] = ac;
      g_zsin[idx] = as2;
      ac += tc;
      as2 += ts;
    }
  }
}

// ============================================================================
// Pass C: per-chunk output. Balanced triangle tiling (272 8x4 tiles),
// folded-row AV with fused rowsum, inter term, bf16-split epilogue.
// ============================================================================
constexpr int SQ_LD = 65;
constexpr int SA_LD = 129;
constexpr int OFF_QC = 0;
constexpr int OFF_QS = CH * SQ_LD;
constexpr int OFF_KC = 2 * CH * SQ_LD;
constexpr int OFF_KS = 3 * CH * SQ_LD;
constexpr int OFF_A = 4 * CH * SQ_LD;
constexpr int OFF_ZC = OFF_A + CH * SA_LD;
constexpr int OFF_ZS = OFF_ZC + DHc;
constexpr int SMEM_FLOATS = OFF_ZS + DHc;

__global__ __launch_bounds__(256, 1) void attn_out() {
  extern __shared__ __align__(16) float sm[];
  const int blk = blockIdx.x;
  const int c = blk & (NCH - 1);
  const int bh = blk >> 5;
  const int b = bh >> 4, h = bh & 15;
  const int tid = threadIdx.x, tx = tid & 15, ty = tid >> 4;

  float* sQc = sm + OFF_QC;
  float* sQs = sm + OFF_QS;
  float* sKc = sm + OFF_KC;
  float* sKs = sm + OFF_KS;
  float* sA = sm + OFF_A;
  float* szc = sm + OFF_ZC;
  float* szs = sm + OFF_ZS;
  float* sV = sKc;
  float* sScos = sKs;
  float* sSsin = sKs + DHc * DHc;

  const size_t gbase = ((size_t)b * Tc + (size_t)c * CH) * HD + h * DHc;

  // load Qc,Qs,Kc,Ks tiles (128 x 64 each)
  for (int l = tid; l < CH * 16; l += 256) {
    const int r = l >> 4, cc = (l & 15) << 2;
    const size_t g = gbase + (size_t)r * HD + cc;
    float4 vq = *(const float4*)&g_Qc[g];
    float4 vs = *(const float4*)&g_Qs[g];
    float4 vk = *(const float4*)&g_Kc[g];
    float4 vx = *(const float4*)&g_Ks[g];
    float* pp;
    pp = &sQc[r * SQ_LD + cc]; pp[0]=vq.x; pp[1]=vq.y; pp[2]=vq.z; pp[3]=vq.w;
    pp = &sQs[r * SQ_LD + cc]; pp[0]=vs.x; pp[1]=vs.y; pp[2]=vs.z; pp[3]=vs.w;
    pp = &sKc[r * SQ_LD + cc]; pp[0]=vk.x; pp[1]=vk.y; pp[2]=vk.z; pp[3]=vk.w;
    pp = &sKs[r * SQ_LD + cc]; pp[0]=vx.x; pp[1]=vx.y; pp[2]=vx.z; pp[3]=vx.w;
  }
  __syncthreads();

  // ---- intra: 272 lower-triangle tiles of 8 rows x 4 cols ----
  // tile (i,j): rows i*8.., cols j*4.., exists for j in [0, 2i+2).
  // cumulative count before row i = i*(i+1).
#pragma unroll 1
  for (int tau = tid; tau < 272; tau += 256) {
    int i = (int)((sqrtf(4.f * (float)tau + 1.f) - 1.f) * 0.5f);
    while ((i + 1) * (i + 2) <= tau) ++i;
    while (i * (i + 1) > tau) --i;
    const int j = tau - i * (i + 1);
    const int t0 = i * 8, s0 = j * 4;
    float a[8][4] = {};
#pragma unroll 2
    for (int d = 0; d < DHc; ++d) {
      float qc[8], qs[8], kc[4], ks[4];
#pragma unroll
      for (int r = 0; r < 8; ++r) {
        qc[r] = sQc[(t0 + r) * SQ_LD + d];
        qs[r] = sQs[(t0 + r) * SQ_LD + d];
      }
#pragma unroll
      for (int cc = 0; cc < 4; ++cc) {
        kc[cc] = sKc[(s0 + cc) * SQ_LD + d];
        ks[cc] = sKs[(s0 + cc) * SQ_LD + d];
      }
#pragma unroll
      for (int r = 0; r < 8; ++r)
#pragma unroll
        for (int cc = 0; cc < 4; ++cc) {
          a[r][cc] += qc[r] * kc[cc];
          a[r][cc] += qs[r] * ks[cc];
        }
    }
#pragma unroll
    for (int r = 0; r < 8; ++r)
#pragma unroll
      for (int cc = 0; cc < 4; ++cc)
        sA[(t0 + r) * SA_LD + s0 + cc] =
            (s0 + cc <= t0 + r) ? a[r][cc] : 0.f;
  }
  __syncthreads();

  // load V (over Kc space), Scos/Ssin (over Ks space), z vectors
  for (int l = tid; l < CH * 16; l += 256) {
    const int r = l >> 4, cc = (l & 15) << 2;
    *(float4*)&sV[r * 64 + cc] =
        *(const float4*)&g_V[gbase + (size_t)r * HD + cc];
  }
  const size_t sbse = ((size_t)bh * NCH + c) * (DHc * DHc);
  for (int l = tid; l < 64 * 16; l += 256) {
    const int r = l >> 4, cc = (l & 15) << 2;
    *(float4*)&sScos[r * 64 + cc] = *(const float4*)&g_Scos[sbse + r * 64 + cc];
    *(float4*)&sSsin[r * 64 + cc] = *(const float4*)&g_Ssin[sbse + r * 64 + cc];
  }
  if (tid < DHc) {
    const size_t zb = ((size_t)bh * NCH + c) * DHc;
    szc[tid] = g_zcos[zb + tid];
    szs[tid] = g_zsin[zb + tid];
  }
  __syncthreads();

  // ---- AV (folded rows for balance) + fused rowsum ----
  const int n0 = tx * 4;
  const int rA = ty * 4;          // rows rA..rA+3   (0..63)
  const int rB = 124 - ty * 4;    // rows rB..rB+3   (64..127)
  float o[8][4] = {};
  float rs[8] = {};
#pragma unroll 1
  for (int s = 0; s < rA + 4; ++s) {
    const float4 v4 = *(const float4*)&sV[s * 64 + n0];
#pragma unroll
    for (int i = 0; i < 4; ++i) {
      const float av = sA[(rA + i) * SA_LD + s];
      o[i][0] += av * v4.x;
      o[i][1] += av * v4.y;
      o[i][2] += av * v4.z;
      o[i][3] += av * v4.w;
      rs[i] += av;
    }
  }
#pragma unroll 1
  for (int s = 0; s < rB + 4; ++s) {
    const float4 v4 = *(const float4*)&sV[s * 64 + n0];
#pragma unroll
    for (int i = 0; i < 4; ++i) {
      const float av = sA[(rB + i) * SA_LD + s];
      o[4 + i][0] += av * v4.x;
      o[4 + i][1] += av * v4.y;
      o[4 + i][2] += av * v4.z;
      o[4 + i][3] += av * v4.w;
      rs[4 + i] += av;
    }
  }

  // ---- inter: Q . S_prev and Q . z_prev ----
  float dden[8] = {};
#pragma unroll 2
  for (int d = 0; d < DHc; ++d) {
    const float4 sc = *(const float4*)&sScos[d * 64 + n0];
    const float4 ss = *(const float4*)&sSsin[d * 64 + n0];
    const float zcv = szc[d], zsv = szs[d];
#pragma unroll
    for (int i = 0; i < 8; ++i) {
      const int t = (i < 4) ? (rA + i) : (rB + i - 4);
      const float qc = sQc[t * SQ_LD + d];
      const float qs = sQs[t * SQ_LD + d];
      o[i][0] += qc * sc.x + qs * ss.x;
      o[i][1] += qc * sc.y + qs * ss.y;
      o[i][2] += qc * sc.z + qs * ss.z;
      o[i][3] += qc * sc.w + qs * ss.w;
      dden[i] += qc * zcv + qs * zsv;
    }
  }

  // ---- normalize + write bf16 split directly (feeds output GEMM) ----
#pragma unroll
  for (int i = 0; i < 8; ++i) {
    const int t = (i < 4) ? (rA + i) : (rB + i - 4);
    const float den = fmaxf(rs[i] + dden[i], 1e-6f);
    const float inv = 1.0f / den;
    __nv_bfloat16 hh[4], ll[4];
#pragma unroll
    for (int e = 0; e < 4; ++e) {
      const float val = o[i][e] * inv;
      hh[e] = __float2bfloat16(val);
      ll[e] = __float2bfloat16(val - __bfloat162float(hh[e]));
    }
    const size_t idx = gbase + (size_t)t * HD + n0;
    *(uint2*)&g_ah[idx] = *(uint2*)hh;
    *(uint2*)&g_al[idx] = *(uint2*)ll;
  }
}

}  // namespace cf

extern "C" void kernel_launch(void* const* d_in, const int* in_sizes, int n_in,
                              void* d_out, int out_size) {
  using namespace cf;
  const float* x = (const float*)d_in[0];
  const float* Wq = (const float*)d_in[1];
  const float* bq = (const float*)d_in[2];
  const float* Wk = (const float*)d_in[3];
  const float* bk = (const float*)d_in[4];
  const float* Wv = (const float*)d_in[5];
  const float* bv = (const float*)d_in[6];
  const float* Wo = (const float*)d_in[7];
  const float* bo = (const float*)d_in[8];
  float* out = (float*)d_out;

  cudaFuncSetAttribute(gemm_mma<1>, cudaFuncAttributeMaxDynamicSharedMemorySize, GEMM_SMEM);
  cudaFuncSetAttribute(gemm_mma<0>, cudaFuncAttributeMaxDynamicSharedMemorySize, GEMM_SMEM);
  cudaFuncSetAttribute(attn_out, cudaFuncAttributeMaxDynamicSharedMemorySize,
                       (int)(SMEM_FLOATS * sizeof(float)));

  // 1) splits
  split_x<<<Mrows * DM / 4 / 256, 256>>>(x);
  dim3 tg(32, 32), tb(32, 8);
  tsplit<0><<<tg, tb>>>(Wq);
  tsplit<1><<<tg, tb>>>(Wk);
  tsplit<2><<<tg, tb>>>(Wv);
  tsplit<3><<<tg, tb>>>(Wo);

  // 2) fused QKV projection GEMMs
  dim3 gq(HD / 128, Mrows / 128, 3);
  gemm_mma<1><<<gq, 256, GEMM_SMEM>>>(bq, bk, bv, nullptr);

  // 3) attention
  chunk_stats<<<BHc * NCH, 256>>>();
  chunk_scan2<<<dim3(16, 32), 256>>>();
  attn_out<<<BHc * NCH, 256, SMEM_FLOATS * sizeof(float)>>>();

  // 4) output GEMM (reads g_ah/g_al written by attn_out)
  dim3 go(HD / 128, Mrows / 128, 1);
  gemm_mma<0><<<go, 256, GEMM_SMEM>>>(bo, nullptr, nullptr, out);
}

// round 7
// speedup vs baseline: 2.3270x; 1.1493x over previous
#include <cuda_runtime.h>
#include <cuda_bf16.h>
#include <cuda_fp16.h>
#include <math.h>
#include <stdint.h>

// ============================================================================
// CosFormer attention (sm_103 base; legacy HMMA mma.sync).
//  - QKV GEMM: bf16x3 split (err ~2^-18), fused Q/K/V via grid.z.
//  - Attention: chunked linear attention fp32; trig identity
//      A[t,s] = cos(th_t - th_s) * (Qp_t . Kp_s)   (halves intra work, exact)
//  - Output GEMM: fp16 2-pass (attn fp16-rounded x Wo fp16 hi/lo), err ~2.8e-4.
// ============================================================================

namespace cf {

constexpr int Bc = 2, Tc = 4096, Hc = 16, DHc = 64;
constexpr int DM = 1024, HD = 1024;
constexpr int Mrows = Bc * Tc;            // 8192
constexpr int CH = 128, NCH = Tc / CH;    // 128, 32
constexpr int BHc = Bc * Hc;              // 32
constexpr float ANGC = 3.14159265358979323846f / (2.0f * (float)Tc);

constexpr int KDIM = 1024;
constexpr int KT = 64;
constexpr int NKT = KDIM / KT;            // 16

// ---- fp32 scratch ----
__device__ __align__(16) float g_Qp[(size_t)Mrows * HD];
__device__ __align__(16) float g_Kp[(size_t)Mrows * HD];
__device__ __align__(16) float g_Kc[(size_t)Mrows * HD];
__device__ __align__(16) float g_Ks[(size_t)Mrows * HD];
__device__ __align__(16) float g_V [(size_t)Mrows * HD];
__device__ __align__(16) float g_Scos[(size_t)BHc * NCH * DHc * DHc];
__device__ __align__(16) float g_Ssin[(size_t)BHc * NCH * DHc * DHc];
__device__ __align__(16) float g_zcos[(size_t)BHc * NCH * DHc];
__device__ __align__(16) float g_zsin[(size_t)BHc * NCH * DHc];

// ---- low precision operands ----
__device__ __align__(16) __nv_bfloat16 g_xh[(size_t)Mrows * DM];
__device__ __align__(16) __nv_bfloat16 g_xl[(size_t)Mrows * DM];
__device__ __align__(16) __nv_bfloat16 g_Wqh[(size_t)HD * DM];
__device__ __align__(16) __nv_bfloat16 g_Wql[(size_t)HD * DM];
__device__ __align__(16) __nv_bfloat16 g_Wkh[(size_t)HD * DM];
__device__ __align__(16) __nv_bfloat16 g_Wkl[(size_t)HD * DM];
__device__ __align__(16) __nv_bfloat16 g_Wvh[(size_t)HD * DM];
__device__ __align__(16) __nv_bfloat16 g_Wvl[(size_t)HD * DM];
__device__ __align__(16) __half g_a16[(size_t)Mrows * HD];
__device__ __align__(16) __half g_Wo16h[(size_t)DM * HD];
__device__ __align__(16) __half g_Wo16l[(size_t)DM * HD];

// ============================================================================
// helpers
// ============================================================================
__device__ __forceinline__ uint32_t smem_u32(const void* p) {
  uint32_t a;
  asm("{ .reg .u64 t; cvta.to.shared.u64 t, %1; cvt.u32.u64 %0, t; }"
      : "=r"(a) : "l"(p));
  return a;
}
__device__ __forceinline__ void ldsm4(uint32_t* r, uint32_t addr) {
  asm volatile(
      "ldmatrix.sync.aligned.m8n8.x4.shared.b16 {%0,%1,%2,%3}, [%4];"
      : "=r"(r[0]), "=r"(r[1]), "=r"(r[2]), "=r"(r[3]) : "r"(addr));
}
__device__ __forceinline__ void mma_bf(float* d, const uint32_t* a,
                                       const uint32_t* b) {
  asm volatile(
      "mma.sync.aligned.m16n8k16.row.col.f32.bf16.bf16.f32 "
      "{%0,%1,%2,%3}, {%4,%5,%6,%7}, {%8,%9}, {%0,%1,%2,%3};"
      : "+f"(d[0]), "+f"(d[1]), "+f"(d[2]), "+f"(d[3])
      : "r"(a[0]), "r"(a[1]), "r"(a[2]), "r"(a[3]), "r"(b[0]), "r"(b[1]));
}
__device__ __forceinline__ void mma_hf(float* d, const uint32_t* a,
                                       const uint32_t* b) {
  asm volatile(
      "mma.sync.aligned.m16n8k16.row.col.f32.f16.f16.f32 "
      "{%0,%1,%2,%3}, {%4,%5,%6,%7}, {%8,%9}, {%0,%1,%2,%3};"
      : "+f"(d[0]), "+f"(d[1]), "+f"(d[2]), "+f"(d[3])
      : "r"(a[0]), "r"(a[1]), "r"(a[2]), "r"(a[3]), "r"(b[0]), "r"(b[1]));
}
__device__ __forceinline__ void cpasync16(uint32_t dst, const void* src) {
  asm volatile("cp.async.cg.shared.global [%0], [%1], 16;"
               ::"r"(dst), "l"(src) : "memory");
}
__device__ __forceinline__ void cp_commit() {
  asm volatile("cp.async.commit_group;" ::: "memory");
}
template <int N>
__device__ __forceinline__ void cp_wait() {
  asm volatile("cp.async.wait_group %0;" ::"n"(N) : "memory");
}

// ============================================================================
// Splits
// ============================================================================
__global__ __launch_bounds__(256) void split_x(const float* __restrict__ in) {
  int i = blockIdx.x * 256 + threadIdx.x;
  float4 v = *(const float4*)(in + (size_t)i * 4);
  __nv_bfloat16 h[4], l[4];
  float f[4] = {v.x, v.y, v.z, v.w};
#pragma unroll
  for (int j = 0; j < 4; ++j) {
    h[j] = __float2bfloat16(f[j]);
    l[j] = __float2bfloat16(f[j] - __bfloat162float(h[j]));
  }
  *(uint2*)(g_xh + (size_t)i * 4) = *(uint2*)h;
  *(uint2*)(g_xl + (size_t)i * 4) = *(uint2*)l;
}

template <int WSEL>  // 0=q 1=k 2=v (bf16)
__global__ __launch_bounds__(256) void tsplit(const float* __restrict__ W) {
  __nv_bfloat16* Th = (WSEL == 0) ? g_Wqh : (WSEL == 1) ? g_Wkh : g_Wvh;
  __nv_bfloat16* Tl = (WSEL == 0) ? g_Wql : (WSEL == 1) ? g_Wkl : g_Wvl;
  __shared__ float tile[32][33];
  const int bx = blockIdx.x * 32, by = blockIdx.y * 32;
  const int tx = threadIdx.x, ty = threadIdx.y;
#pragma unroll
  for (int j = 0; j < 4; ++j)
    tile[ty + j * 8][tx] = W[(size_t)(by + ty + j * 8) * 1024 + bx + tx];
  __syncthreads();
#pragma unroll
  for (int j = 0; j < 4; ++j) {
    float v = tile[tx][ty + j * 8];
    __nv_bfloat16 h = __float2bfloat16(v);
    __nv_bfloat16 l = __float2bfloat16(v - __bfloat162float(h));
    const size_t o = (size_t)(bx + ty + j * 8) * 1024 + by + tx;
    Th[o] = h;
    Tl[o] = l;
  }
}

__global__ __launch_bounds__(256) void tsplit_o(const float* __restrict__ W) {
  __shared__ float tile[32][33];
  const int bx = blockIdx.x * 32, by = blockIdx.y * 32;
  const int tx = threadIdx.x, ty = threadIdx.y;
#pragma unroll
  for (int j = 0; j < 4; ++j)
    tile[ty + j * 8][tx] = W[(size_t)(by + ty + j * 8) * 1024 + bx + tx];
  __syncthreads();
#pragma unroll
  for (int j = 0; j < 4; ++j) {
    float v = tile[tx][ty + j * 8];
    __half h = __float2half(v);
    __half l = __float2half(v - __half2float(h));
    const size_t o = (size_t)(bx + ty + j * 8) * 1024 + by + tx;
    g_Wo16h[o] = h;
    g_Wo16l[o] = l;
  }
}

// ============================================================================
// QKV GEMM (bf16x3, fused via grid.z). Epilogue:
//  w==0: g_Qp = relu   w==1: g_Kp/g_Kc/g_Ks   w==2: g_V
// ============================================================================
constexpr int PIECE_BYTES = 128 * KT * 2;         // 16384
constexpr int STAGE_BYTES = 4 * PIECE_BYTES;      // 65536
constexpr int GEMM_SMEM = 2 * STAGE_BYTES;        // 131072

__global__ __launch_bounds__(256, 1) void gemm_qkv(
    const float* __restrict__ bias_q, const float* __restrict__ bias_k,
    const float* __restrict__ bias_v) {
  extern __shared__ __align__(16) char smem[];
  const uint32_t sb = smem_u32(smem);
  const int tid = threadIdx.x, wid = tid >> 5, lane = tid & 31;
  const int wm = wid >> 2, wn = wid & 3;
  const int bm = blockIdx.y, bn = blockIdx.x;
  const int w = (int)blockIdx.z;

  const __nv_bfloat16* Bh = (w == 0) ? g_Wqh : (w == 1) ? g_Wkh : g_Wvh;
  const __nv_bfloat16* Bl = (w == 0) ? g_Wql : (w == 1) ? g_Wkl : g_Wvl;
  const float* bias = (w == 0) ? bias_q : (w == 1) ? bias_k : bias_v;

  const int p = tid >> 6, q = tid & 63;
  const __nv_bfloat16* psrc;
  {
    const size_t arow = (size_t)bm * 128 * KDIM;
    const size_t brow = (size_t)bn * 128 * KDIM;
    psrc = (p == 0) ? g_xh + arow : (p == 1) ? g_xl + arow
                                  : (p == 2) ? Bh + brow : Bl + brow;
  }
  const __nv_bfloat16* gbase = psrc + (size_t)(q >> 3) * KDIM + (q & 7) * 8;
  const uint32_t loff0 = (uint32_t)((q >> 3) * 128 + (q & 7) * 16);

  auto issue = [&](int kt) {
    const int buf = kt & 1;
    const __nv_bfloat16* g = gbase + kt * KT;
    const uint32_t dstbase = sb + buf * STAGE_BYTES + p * PIECE_BYTES;
#pragma unroll
    for (int j = 0; j < 16; ++j) {
      const uint32_t off = loff0 + j * 1024;
      const uint32_t swz = off ^ ((off >> 3) & 0x70);
      cpasync16(dstbase + swz, g + (size_t)j * 8 * KDIM);
    }
    cp_commit();
  };

  float acc[4][4][4];
#pragma unroll
  for (int i = 0; i < 4; ++i)
#pragma unroll
    for (int j = 0; j < 4; ++j)
#pragma unroll
      for (int k = 0; k < 4; ++k) acc[i][j][k] = 0.f;

  issue(0);
#pragma unroll 1
  for (int kt = 0; kt < NKT; ++kt) {
    if (kt + 1 < NKT) {
      issue(kt + 1);
      cp_wait<1>();
    } else {
      cp_wait<0>();
    }
    __syncthreads();
    const uint32_t base = sb + (kt & 1) * STAGE_BYTES;
#pragma unroll
    for (int ks = 0; ks < 4; ++ks) {
      const int k0 = ks * 16;
      uint32_t ah[4][4], al[4][4], bh[2][4], bl[2][4];
#pragma unroll
      for (int mt = 0; mt < 4; ++mt) {
        const uint32_t row = wm * 64 + mt * 16 + (lane & 15);
        const uint32_t off = row * 128 + k0 * 2 + ((lane >> 4) << 4);
        const uint32_t swz = off ^ ((off >> 3) & 0x70);
        ldsm4(ah[mt], base + swz);
        ldsm4(al[mt], base + PIECE_BYTES + swz);
      }
#pragma unroll
      for (int nt2 = 0; nt2 < 2; ++nt2) {
        const uint32_t row =
            wn * 32 + nt2 * 16 + (lane & 7) + ((lane >> 4) << 3);
        const uint32_t off = row * 128 + k0 * 2 + (((lane >> 3) & 1) << 4);
        const uint32_t swz = off ^ ((off >> 3) & 0x70);
        ldsm4(bh[nt2], base + 2 * PIECE_BYTES + swz);
        ldsm4(bl[nt2], base + 3 * PIECE_BYTES + swz);
      }
#pragma unroll
      for (int mt = 0; mt < 4; ++mt)
#pragma unroll
        for (int nt = 0; nt < 4; ++nt)
          mma_bf(acc[mt][nt], ah[mt], &bh[nt >> 1][(nt & 1) * 2]);
#pragma unroll
      for (int mt = 0; mt < 4; ++mt)
#pragma unroll
        for (int nt = 0; nt < 4; ++nt)
          mma_bf(acc[mt][nt], ah[mt], &bl[nt >> 1][(nt & 1) * 2]);
#pragma unroll
      for (int mt = 0; mt < 4; ++mt)
#pragma unroll
        for (int nt = 0; nt < 4; ++nt)
          mma_bf(acc[mt][nt], al[mt], &bh[nt >> 1][(nt & 1) * 2]);
    }
    __syncthreads();
  }

  const int g = lane >> 2, t2 = (lane & 3) * 2;
#pragma unroll
  for (int mt = 0; mt < 4; ++mt) {
    const int r0 = bm * 128 + wm * 64 + mt * 16 + g;
    const int r1 = r0 + 8;
    float sn0 = 0.f, cs0 = 0.f, sn1 = 0.f, cs1 = 0.f;
    if (w == 1) {
      sincosf(ANGC * (float)(r0 & (Tc - 1)), &sn0, &cs0);
      sincosf(ANGC * (float)(r1 & (Tc - 1)), &sn1, &cs1);
    }
#pragma unroll
    for (int nt = 0; nt < 4; ++nt) {
      const int col = bn * 128 + wn * 32 + nt * 8 + t2;
      const float b0 = __ldg(&bias[col]), b1 = __ldg(&bias[col + 1]);
      const float v00 = acc[mt][nt][0] + b0, v01 = acc[mt][nt][1] + b1;
      const float v10 = acc[mt][nt][2] + b0, v11 = acc[mt][nt][3] + b1;
      if (w == 2) {
        *(float2*)&g_V[(size_t)r0 * HD + col] = make_float2(v00, v01);
        *(float2*)&g_V[(size_t)r1 * HD + col] = make_float2(v10, v11);
      } else if (w == 0) {
        *(float2*)&g_Qp[(size_t)r0 * HD + col] =
            make_float2(fmaxf(v00, 0.f), fmaxf(v01, 0.f));
        *(float2*)&g_Qp[(size_t)r1 * HD + col] =
            make_float2(fmaxf(v10, 0.f), fmaxf(v11, 0.f));
      } else {
        const float a00 = fmaxf(v00, 0.f), a01 = fmaxf(v01, 0.f);
        const float a10 = fmaxf(v10, 0.f), a11 = fmaxf(v11, 0.f);
        *(float2*)&g_Kp[(size_t)r0 * HD + col] = make_float2(a00, a01);
        *(float2*)&g_Kp[(size_t)r1 * HD + col] = make_float2(a10, a11);
        *(float2*)&g_Kc[(size_t)r0 * HD + col] =
            make_float2(a00 * cs0, a01 * cs0);
        *(float2*)&g_Kc[(size_t)r1 * HD + col] =
            make_float2(a10 * cs1, a11 * cs1);
        *(float2*)&g_Ks[(size_t)r0 * HD + col] =
            make_float2(a00 * sn0, a01 * sn0);
        *(float2*)&g_Ks[(size_t)r1 * HD + col] =
            make_float2(a10 * sn1, a11 * sn1);
      }
    }
  }
}

// ============================================================================
// Output GEMM: fp16 2-pass (A = g_a16 single fp16, B = Wo fp16 hi/lo)
// ============================================================================
constexpr int STAGE_O = 3 * PIECE_BYTES;          // 49152
constexpr int GEMM_SMEM_O = 2 * STAGE_O;          // 98304

__global__ __launch_bounds__(256, 1) void gemm_o16(
    const float* __restrict__ bias, float* __restrict__ outO) {
  extern __shared__ __align__(16) char smem[];
  const uint32_t sb = smem_u32(smem);
  const int tid = threadIdx.x, wid = tid >> 5, lane = tid & 31;
  const int wm = wid >> 2, wn = wid & 3;
  const int bm = blockIdx.y, bn = blockIdx.x;

  const int p = tid >> 6, q = tid & 63;
  const __half* psrc = nullptr;
  if (p < 3) {
    const size_t arow = (size_t)bm * 128 * KDIM;
    const size_t brow = (size_t)bn * 128 * KDIM;
    psrc = (p == 0) ? g_a16 + arow : (p == 1) ? g_Wo16h + brow
                                              : g_Wo16l + brow;
    psrc += (size_t)(q >> 3) * KDIM + (q & 7) * 8;
  }
  const uint32_t loff0 = (uint32_t)((q >> 3) * 128 + (q & 7) * 16);

  auto issue = [&](int kt) {
    const int buf = kt & 1;
    if (p < 3) {
      const __half* g = psrc + kt * KT;
      const uint32_t dstbase = sb + buf * STAGE_O + p * PIECE_BYTES;
#pragma unroll
      for (int j = 0; j < 16; ++j) {
        const uint32_t off = loff0 + j * 1024;
        const uint32_t swz = off ^ ((off >> 3) & 0x70);
        cpasync16(dstbase + swz, g + (size_t)j * 8 * KDIM);
      }
    }
    cp_commit();
  };

  float acc[4][4][4];
#pragma unroll
  for (int i = 0; i < 4; ++i)
#pragma unroll
    for (int j = 0; j < 4; ++j)
#pragma unroll
      for (int k = 0; k < 4; ++k) acc[i][j][k] = 0.f;

  issue(0);
#pragma unroll 1
  for (int kt = 0; kt < NKT; ++kt) {
    if (kt + 1 < NKT) {
      issue(kt + 1);
      cp_wait<1>();
    } else {
      cp_wait<0>();
    }
    __syncthreads();
    const uint32_t base = sb + (kt & 1) * STAGE_O;
#pragma unroll
    for (int ks = 0; ks < 4; ++ks) {
      const int k0 = ks * 16;
      uint32_t a[4][4], bh[2][4], bl[2][4];
#pragma unroll
      for (int mt = 0; mt < 4; ++mt) {
        const uint32_t row = wm * 64 + mt * 16 + (lane & 15);
        const uint32_t off = row * 128 + k0 * 2 + ((lane >> 4) << 4);
        const uint32_t swz = off ^ ((off >> 3) & 0x70);
        ldsm4(a[mt], base + swz);
      }
#pragma unroll
      for (int nt2 = 0; nt2 < 2; ++nt2) {
        const uint32_t row =
            wn * 32 + nt2 * 16 + (lane & 7) + ((lane >> 4) << 3);
        const uint32_t off = row * 128 + k0 * 2 + (((lane >> 3) & 1) << 4);
        const uint32_t swz = off ^ ((off >> 3) & 0x70);
        ldsm4(bh[nt2], base + PIECE_BYTES + swz);
        ldsm4(bl[nt2], base + 2 * PIECE_BYTES + swz);
      }
#pragma unroll
      for (int mt = 0; mt < 4; ++mt)
#pragma unroll
        for (int nt = 0; nt < 4; ++nt)
          mma_hf(acc[mt][nt], a[mt], &bh[nt >> 1][(nt & 1) * 2]);
#pragma unroll
      for (int mt = 0; mt < 4; ++mt)
#pragma unroll
        for (int nt = 0; nt < 4; ++nt)
          mma_hf(acc[mt][nt], a[mt], &bl[nt >> 1][(nt & 1) * 2]);
    }
    __syncthreads();
  }

  const int g = lane >> 2, t2 = (lane & 3) * 2;
#pragma unroll
  for (int mt = 0; mt < 4; ++mt) {
    const int r0 = bm * 128 + wm * 64 + mt * 16 + g;
    const int r1 = r0 + 8;
#pragma unroll
    for (int nt = 0; nt < 4; ++nt) {
      const int col = bn * 128 + wn * 32 + nt * 8 + t2;
      const float b0 = __ldg(&bias[col]), b1 = __ldg(&bias[col + 1]);
      *(float2*)&outO[(size_t)r0 * DM + col] =
          make_float2(acc[mt][nt][0] + b0, acc[mt][nt][1] + b1);
      *(float2*)&outO[(size_t)r1 * DM + col] =
          make_float2(acc[mt][nt][2] + b0, acc[mt][nt][3] + b1);
    }
  }
}

// ============================================================================
// Pass A: per-chunk states (reads g_Kc/g_Ks/g_V; unchanged)
// ============================================================================
__global__ __launch_bounds__(256) void chunk_stats() {
  const int blk = blockIdx.x;
  const int c = blk & (NCH - 1);
  const int bh = blk >> 5;
  const int b = bh >> 4, h = bh & 15;
  const int tid = threadIdx.x, tx = tid & 15, ty = tid >> 4;

  __shared__ __align__(16) float sKc[32][64];
  __shared__ __align__(16) float sKs[32][64];
  __shared__ __align__(16) float sV[32][64];

  float aC[4][4] = {}, aS[4][4] = {};
  float zc[4] = {}, zs[4] = {};
  const size_t rowbase = ((size_t)b * Tc + (size_t)c * CH) * HD + h * DHc;

  for (int t0 = 0; t0 < CH; t0 += 32) {
    __syncthreads();
    for (int l = tid; l < 32 * 16; l += 256) {
      const int r = l >> 4, cc = (l & 15) << 2;
      const size_t g = rowbase + (size_t)(t0 + r) * HD + cc;
      *(float4*)&sKc[r][cc] = *(const float4*)&g_Kc[g];
      *(float4*)&sKs[r][cc] = *(const float4*)&g_Ks[g];
      *(float4*)&sV[r][cc] = *(const float4*)&g_V[g];
    }
    __syncthreads();
#pragma unroll 4
    for (int t = 0; t < 32; ++t) {
      float kc[4], ks[4], v[4];
#pragma unroll
      for (int i = 0; i < 4; ++i) {
        kc[i] = sKc[t][ty * 4 + i];
        ks[i] = sKs[t][ty * 4 + i];
      }
#pragma unroll
      for (int j = 0; j < 4; ++j) v[j] = sV[t][tx * 4 + j];
#pragma unroll
      for (int i = 0; i < 4; ++i)
#pragma unroll
        for (int j = 0; j < 4; ++j) {
          aC[i][j] += kc[i] * v[j];
          aS[i][j] += ks[i] * v[j];
        }
      if (tx == 0) {
#pragma unroll
        for (int i = 0; i < 4; ++i) { zc[i] += kc[i]; zs[i] += ks[i]; }
      }
    }
  }

  const size_t sbse = ((size_t)bh * NCH + c) * (DHc * DHc);
#pragma unroll
  for (int i = 0; i < 4; ++i) {
    *(float4*)&g_Scos[sbse + (size_t)(ty * 4 + i) * 64 + tx * 4] =
        make_float4(aC[i][0], aC[i][1], aC[i][2], aC[i][3]);
    *(float4*)&g_Ssin[sbse + (size_t)(ty * 4 + i) * 64 + tx * 4] =
        make_float4(aS[i][0], aS[i][1], aS[i][2], aS[i][3]);
  }
  if (tx == 0) {
    const size_t zb = ((size_t)bh * NCH + c) * DHc;
#pragma unroll
    for (int i = 0; i < 4; ++i) {
      g_zcos[zb + ty * 4 + i] = zc[i];
      g_zsin[zb + ty * 4 + i] = zs[i];
    }
  }
}

// ============================================================================
// Pass B: exclusive prefix over chunks (unchanged)
// ============================================================================
__global__ __launch_bounds__(256) void chunk_scan2() {
  const int bh = blockIdx.y;
  const int e = blockIdx.x * 256 + threadIdx.x;
  {
    const size_t base = (size_t)bh * NCH * (DHc * DHc) + e;
    float ac = 0.f, as2 = 0.f;
#pragma unroll 1
    for (int c = 0; c < NCH; ++c) {
      const size_t idx = base + (size_t)c * (DHc * DHc);
      const float tc = g_Scos[idx], ts = g_Ssin[idx];
      g_Scos[idx] = ac;
      g_Ssin[idx] = as2;
      ac += tc;
      as2 += ts;
    }
  }
  if (blockIdx.x == 0 && threadIdx.x < DHc) {
    const size_t zb = (size_t)bh * NCH * DHc + threadIdx.x;
    float ac = 0.f, as2 = 0.f;
#pragma unroll 1
    for (int c = 0; c < NCH; ++c) {
      const size_t idx = zb + (size_t)c * DHc;
      const float tc = g_zcos[idx], ts = g_zsin[idx];
      g_zcos[idx] = ac;
      g_zsin[idx] = as2;
      ac += tc;
      as2 += ts;
    }
  }
}

// ============================================================================
// Pass C: per-chunk output, 512 threads.
//  intra: P = Qp Kp^T (272 8x4 tiles), A = cos(dt)*P masked.
//  AV + rowsum (folded rows), inter via Qp against Scos/Ssin, fp16 epilogue.
// ============================================================================
constexpr int SQ_LD = 65;
constexpr int SA_LD = 129;
constexpr int OFF_QP = 0;                       // 128*65
constexpr int OFF_KP = 128 * SQ_LD;             // 128*65 (reused as V)
constexpr int OFF_A = 2 * 128 * SQ_LD;          // 128*129
constexpr int OFF_SC = OFF_A + CH * SA_LD;      // 64*64
constexpr int OFF_SS = OFF_SC + DHc * DHc;      // 64*64
constexpr int OFF_ZC = OFF_SS + DHc * DHc;      // 64
constexpr int OFF_ZS = OFF_ZC + DHc;            // 64
constexpr int OFF_TC = OFF_ZS + DHc;            // 128
constexpr int OFF_TS = OFF_TC + CH;             // 128
constexpr int SMEM_FLOATS = OFF_TS + CH;        // 41728 -> 166912 B

__global__ __launch_bounds__(512, 1) void attn_out() {
  extern __shared__ __align__(16) float sm[];
  const int blk = blockIdx.x;
  const int c = blk & (NCH - 1);
  const int bh = blk >> 5;
  const int b = bh >> 4, h = bh & 15;
  const int tid = threadIdx.x;

  float* sQp = sm + OFF_QP;
  float* sKp = sm + OFF_KP;
  float* sA = sm + OFF_A;
  float* sSc = sm + OFF_SC;
  float* sSs = sm + OFF_SS;
  float* szc = sm + OFF_ZC;
  float* szs = sm + OFF_ZS;
  float* strc = sm + OFF_TC;
  float* strs = sm + OFF_TS;
  float* sV = sKp;  // reuse after intra

  const size_t gbase = ((size_t)b * Tc + (size_t)c * CH) * HD + h * DHc;

  if (tid < CH) {
    float sn, cs;
    sincosf(ANGC * (float)(c * CH + tid), &sn, &cs);
    strc[tid] = cs;
    strs[tid] = sn;
  }
  // load Qp, Kp tiles (128 x 64 each)
  for (int l = tid; l < CH * 16; l += 512) {
    const int r = l >> 4, cc = (l & 15) << 2;
    const size_t g = gbase + (size_t)r * HD + cc;
    float4 vq = *(const float4*)&g_Qp[g];
    float4 vk = *(const float4*)&g_Kp[g];
    float* pp;
    pp = &sQp[r * SQ_LD + cc]; pp[0]=vq.x; pp[1]=vq.y; pp[2]=vq.z; pp[3]=vq.w;
    pp = &sKp[r * SQ_LD + cc]; pp[0]=vk.x; pp[1]=vk.y; pp[2]=vk.z; pp[3]=vk.w;
  }
  __syncthreads();

  // ---- intra: 272 lower-triangle tiles of 8x4, one per thread ----
  if (tid < 272) {
    const int tau = tid;
    int i = (int)((sqrtf(4.f * (float)tau + 1.f) - 1.f) * 0.5f);
    while ((i + 1) * (i + 2) <= tau) ++i;
    while (i * (i + 1) > tau) --i;
    const int j = tau - i * (i + 1);
    const int t0 = i * 8, s0 = j * 4;
    float a[8][4] = {};
#pragma unroll 2
    for (int d = 0; d < DHc; ++d) {
      float qp[8], kp[4];
#pragma unroll
      for (int r = 0; r < 8; ++r) qp[r] = sQp[(t0 + r) * SQ_LD + d];
#pragma unroll
      for (int cc = 0; cc < 4; ++cc) kp[cc] = sKp[(s0 + cc) * SQ_LD + d];
#pragma unroll
      for (int r = 0; r < 8; ++r)
#pragma unroll
        for (int cc = 0; cc < 4; ++cc) a[r][cc] += qp[r] * kp[cc];
    }
    float cs4[4], ss4[4];
#pragma unroll
    for (int cc = 0; cc < 4; ++cc) {
      cs4[cc] = strc[s0 + cc];
      ss4[cc] = strs[s0 + cc];
    }
#pragma unroll
    for (int r = 0; r < 8; ++r) {
      const float ct = strc[t0 + r], st = strs[t0 + r];
#pragma unroll
      for (int cc = 0; cc < 4; ++cc)
        sA[(t0 + r) * SA_LD + s0 + cc] =
            (s0 + cc <= t0 + r) ? (ct * cs4[cc] + st * ss4[cc]) * a[r][cc]
                                : 0.f;
    }
  }
  __syncthreads();

  // load V (over Kp), Scos/Ssin, z
  for (int l = tid; l < CH * 16; l += 512) {
    const int r = l >> 4, cc = (l & 15) << 2;
    *(float4*)&sV[r * 64 + cc] =
        *(const float4*)&g_V[gbase + (size_t)r * HD + cc];
  }
  const size_t sbse = ((size_t)bh * NCH + c) * (DHc * DHc);
  for (int l = tid; l < 64 * 16; l += 512) {
    const int r = l >> 4, cc = (l & 15) << 2;
    *(float4*)&sSc[r * 64 + cc] = *(const float4*)&g_Scos[sbse + r * 64 + cc];
    *(float4*)&sSs[r * 64 + cc] = *(const float4*)&g_Ssin[sbse + r * 64 + cc];
  }
  if (tid < DHc) {
    const size_t zb = ((size_t)bh * NCH + c) * DHc;
    szc[tid] = g_zcos[zb + tid];
    szs[tid] = g_zsin[zb + tid];
  }
  __syncthreads();

  // ---- AV + rowsum: 4 rows per thread (2 top, 2 bottom folded) ----
  const int tx = tid & 15, ty = tid >> 4;  // ty in 0..31
  const int n0 = tx * 4;
  const int rA = ty * 2;          // rows rA, rA+1   (0..63)
  const int rB = 126 - ty * 2;    // rows rB, rB+1   (64..127)
  int rowid[4] = {rA, rA + 1, rB, rB + 1};
  float o[4][4] = {};
  float rs[4] = {};
#pragma unroll 1
  for (int s = 0; s <= rA + 1; ++s) {
    const float4 v4 = *(const float4*)&sV[s * 64 + n0];
#pragma unroll
    for (int i = 0; i < 2; ++i) {
      const float av = sA[(rA + i) * SA_LD + s];
      o[i][0] += av * v4.x;
      o[i][1] += av * v4.y;
      o[i][2] += av * v4.z;
      o[i][3] += av * v4.w;
      rs[i] += av;
    }
  }
#pragma unroll 1
  for (int s = 0; s <= rB + 1; ++s) {
    const float4 v4 = *(const float4*)&sV[s * 64 + n0];
#pragma unroll
    for (int i = 0; i < 2; ++i) {
      const float av = sA[(rB + i) * SA_LD + s];
      o[2 + i][0] += av * v4.x;
      o[2 + i][1] += av * v4.y;
      o[2 + i][2] += av * v4.z;
      o[2 + i][3] += av * v4.w;
      rs[2 + i] += av;
    }
  }

  // ---- inter: Qp against Scos/Ssin and z ----
  float uc[4][4] = {}, us[4][4] = {}, dc[4] = {}, ds[4] = {};
#pragma unroll 2
  for (int d = 0; d < DHc; ++d) {
    const float4 sc4 = *(const float4*)&sSc[d * 64 + n0];
    const float4 ss4 = *(const float4*)&sSs[d * 64 + n0];
    const float zcv = szc[d], zsv = szs[d];
#pragma unroll
    for (int i = 0; i < 4; ++i) {
      const float qp = sQp[rowid[i] * SQ_LD + d];
      uc[i][0] += qp * sc4.x;
      uc[i][1] += qp * sc4.y;
      uc[i][2] += qp * sc4.z;
      uc[i][3] += qp * sc4.w;
      us[i][0] += qp * ss4.x;
      us[i][1] += qp * ss4.y;
      us[i][2] += qp * ss4.z;
      us[i][3] += qp * ss4.w;
      dc[i] += qp * zcv;
      ds[i] += qp * zsv;
    }
  }

  // ---- combine, normalize, write fp16 (feeds out-proj GEMM) ----
#pragma unroll
  for (int i = 0; i < 4; ++i) {
    const int t = rowid[i];
    const float ct = strc[t], st = strs[t];
    const float den = fmaxf(rs[i] + ct * dc[i] + st * ds[i], 1e-6f);
    const float inv = 1.0f / den;
    __half hv[4];
#pragma unroll
    for (int e = 0; e < 4; ++e)
      hv[e] = __float2half((o[i][e] + ct * uc[i][e] + st * us[i][e]) * inv);
    *(uint2*)&g_a16[gbase + (size_t)t * HD + n0] = *(uint2*)hv;
  }
}

}  // namespace cf

extern "C" void kernel_launch(void* const* d_in, const int* in_sizes, int n_in,
                              void* d_out, int out_size) {
  using namespace cf;
  const float* x = (const float*)d_in[0];
  const float* Wq = (const float*)d_in[1];
  const float* bq = (const float*)d_in[2];
  const float* Wk = (const float*)d_in[3];
  const float* bk = (const float*)d_in[4];
  const float* Wv = (const float*)d_in[5];
  const float* bv = (const float*)d_in[6];
  const float* Wo = (const float*)d_in[7];
  const float* bo = (const float*)d_in[8];
  float* out = (float*)d_out;

  cudaFuncSetAttribute(gemm_qkv, cudaFuncAttributeMaxDynamicSharedMemorySize,
                       GEMM_SMEM);
  cudaFuncSetAttribute(gemm_o16, cudaFuncAttributeMaxDynamicSharedMemorySize,
                       GEMM_SMEM_O);
  cudaFuncSetAttribute(attn_out, cudaFuncAttributeMaxDynamicSharedMemorySize,
                       (int)(SMEM_FLOATS * sizeof(float)));

  // 1) splits
  split_x<<<Mrows * DM / 4 / 256, 256>>>(x);
  dim3 tg(32, 32), tb(32, 8);
  tsplit<0><<<tg, tb>>>(Wq);
  tsplit<1><<<tg, tb>>>(Wk);
  tsplit<2><<<tg, tb>>>(Wv);
  tsplit_o<<<tg, tb>>>(Wo);

  // 2) fused QKV projection
  dim3 gq(HD / 128, Mrows / 128, 3);
  gemm_qkv<<<gq, 256, GEMM_SMEM>>>(bq, bk, bv);

  // 3) attention
  chunk_stats<<<BHc * NCH, 256>>>();
  chunk_scan2<<<dim3(16, 32), 256>>>();
  attn_out<<<BHc * NCH, 512, SMEM_FLOATS * sizeof(float)>>>();

  // 4) output projection (fp16 2-pass)
  dim3 go(HD / 128, Mrows / 128);
  gemm_o16<<<go, 256, GEMM_SMEM_O>>>(bo, out);
}

// round 8
// speedup vs baseline: 2.5748x; 1.1065x over previous
#include <cuda_runtime.h>
#include <cuda_bf16.h>
#include <cuda_fp16.h>
#include <math.h>
#include <stdint.h>

// ============================================================================
// CosFormer attention (sm_103 base; legacy HMMA mma.sync).
//  - QKV GEMM: fp16 2-pass: x split into fp16 hi/lo (exact to 2^-22),
//      W rounded once to fp16 (2^-11)  ->  x.W16 in 2 MMA passes.
//  - Attention: chunked linear attention fp32; trig identity
//      A[t,s] = cos(th_t - th_s) * (Qp_t . Kp_s).
//  - Output GEMM: fp16 2-pass (attn fp16-rounded x Wo fp16 hi/lo).
// ============================================================================

namespace cf {

constexpr int Bc = 2, Tc = 4096, Hc = 16, DHc = 64;
constexpr int DM = 1024, HD = 1024;
constexpr int Mrows = Bc * Tc;            // 8192
constexpr int CH = 128, NCH = Tc / CH;    // 128, 32
constexpr int BHc = Bc * Hc;              // 32
constexpr float ANGC = 3.14159265358979323846f / (2.0f * (float)Tc);

constexpr int KDIM = 1024;
constexpr int KT = 64;
constexpr int NKT = KDIM / KT;            // 16

// ---- fp32 scratch ----
__device__ __align__(16) float g_Qp[(size_t)Mrows * HD];
__device__ __align__(16) float g_Kp[(size_t)Mrows * HD];
__device__ __align__(16) float g_Kc[(size_t)Mrows * HD];
__device__ __align__(16) float g_Ks[(size_t)Mrows * HD];
__device__ __align__(16) float g_V [(size_t)Mrows * HD];
__device__ __align__(16) float g_Scos[(size_t)BHc * NCH * DHc * DHc];
__device__ __align__(16) float g_Ssin[(size_t)BHc * NCH * DHc * DHc];
__device__ __align__(16) float g_zcos[(size_t)BHc * NCH * DHc];
__device__ __align__(16) float g_zsin[(size_t)BHc * NCH * DHc];

// ---- fp16 operands ----
__device__ __align__(16) __half g_xh[(size_t)Mrows * DM];
__device__ __align__(16) __half g_xl[(size_t)Mrows * DM];
__device__ __align__(16) __half g_Wq16[(size_t)HD * DM];
__device__ __align__(16) __half g_Wk16[(size_t)HD * DM];
__device__ __align__(16) __half g_Wv16[(size_t)HD * DM];
__device__ __align__(16) __half g_a16[(size_t)Mrows * HD];
__device__ __align__(16) __half g_Wo16h[(size_t)DM * HD];
__device__ __align__(16) __half g_Wo16l[(size_t)DM * HD];

// ============================================================================
// helpers
// ============================================================================
__device__ __forceinline__ uint32_t smem_u32(const void* p) {
  uint32_t a;
  asm("{ .reg .u64 t; cvta.to.shared.u64 t, %1; cvt.u32.u64 %0, t; }"
      : "=r"(a) : "l"(p));
  return a;
}
__device__ __forceinline__ void ldsm4(uint32_t* r, uint32_t addr) {
  asm volatile(
      "ldmatrix.sync.aligned.m8n8.x4.shared.b16 {%0,%1,%2,%3}, [%4];"
      : "=r"(r[0]), "=r"(r[1]), "=r"(r[2]), "=r"(r[3]) : "r"(addr));
}
__device__ __forceinline__ void mma_hf(float* d, const uint32_t* a,
                                       const uint32_t* b) {
  asm volatile(
      "mma.sync.aligned.m16n8k16.row.col.f32.f16.f16.f32 "
      "{%0,%1,%2,%3}, {%4,%5,%6,%7}, {%8,%9}, {%0,%1,%2,%3};"
      : "+f"(d[0]), "+f"(d[1]), "+f"(d[2]), "+f"(d[3])
      : "r"(a[0]), "r"(a[1]), "r"(a[2]), "r"(a[3]), "r"(b[0]), "r"(b[1]));
}
__device__ __forceinline__ void cpasync16(uint32_t dst, const void* src) {
  asm volatile("cp.async.cg.shared.global [%0], [%1], 16;"
               ::"r"(dst), "l"(src) : "memory");
}
__device__ __forceinline__ void cp_commit() {
  asm volatile("cp.async.commit_group;" ::: "memory");
}
template <int N>
__device__ __forceinline__ void cp_wait() {
  asm volatile("cp.async.wait_group %0;" ::"n"(N) : "memory");
}

// ============================================================================
// Splits
// ============================================================================
__global__ __launch_bounds__(256) void split_x(const float* __restrict__ in) {
  int i = blockIdx.x * 256 + threadIdx.x;
  float4 v = *(const float4*)(in + (size_t)i * 4);
  __half h[4], l[4];
  float f[4] = {v.x, v.y, v.z, v.w};
#pragma unroll
  for (int j = 0; j < 4; ++j) {
    h[j] = __float2half(f[j]);
    l[j] = __float2half(f[j] - __half2float(h[j]));
  }
  *(uint2*)(g_xh + (size_t)i * 4) = *(uint2*)h;
  *(uint2*)(g_xl + (size_t)i * 4) = *(uint2*)l;
}

// W[K][N] fp32 -> Wt[N][K] fp16 single.  WSEL: 0=q 1=k 2=v
template <int WSEL>
__global__ __launch_bounds__(256) void tsplit(const float* __restrict__ W) {
  __half* T = (WSEL == 0) ? g_Wq16 : (WSEL == 1) ? g_Wk16 : g_Wv16;
  __shared__ float tile[32][33];
  const int bx = blockIdx.x * 32, by = blockIdx.y * 32;
  const int tx = threadIdx.x, ty = threadIdx.y;
#pragma unroll
  for (int j = 0; j < 4; ++j)
    tile[ty + j * 8][tx] = W[(size_t)(by + ty + j * 8) * 1024 + bx + tx];
  __syncthreads();
#pragma unroll
  for (int j = 0; j < 4; ++j) {
    T[(size_t)(bx + ty + j * 8) * 1024 + by + tx] =
        __float2half(tile[tx][ty + j * 8]);
  }
}

__global__ __launch_bounds__(256) void tsplit_o(const float* __restrict__ W) {
  __shared__ float tile[32][33];
  const int bx = blockIdx.x * 32, by = blockIdx.y * 32;
  const int tx = threadIdx.x, ty = threadIdx.y;
#pragma unroll
  for (int j = 0; j < 4; ++j)
    tile[ty + j * 8][tx] = W[(size_t)(by + ty + j * 8) * 1024 + bx + tx];
  __syncthreads();
#pragma unroll
  for (int j = 0; j < 4; ++j) {
    float v = tile[tx][ty + j * 8];
    __half h = __float2half(v);
    __half l = __float2half(v - __half2float(h));
    const size_t o = (size_t)(bx + ty + j * 8) * 1024 + by + tx;
    g_Wo16h[o] = h;
    g_Wo16l[o] = l;
  }
}

// ============================================================================
// QKV GEMM: fp16, 2 term passes (xh*W + xl*W), fused Q/K/V via grid.z.
// 128x128 CTA, 8 warps of 64x32, K staged 64, cp.async double buffer.
// ============================================================================
constexpr int PIECE_BYTES = 128 * KT * 2;         // 16384
constexpr int STAGE_Q = 3 * PIECE_BYTES;          // 49152
constexpr int GEMM_SMEM_Q = 2 * STAGE_Q;          // 98304

__global__ __launch_bounds__(256, 1) void gemm_qkv(
    const float* __restrict__ bias_q, const float* __restrict__ bias_k,
    const float* __restrict__ bias_v) {
  extern __shared__ __align__(16) char smem[];
  const uint32_t sb = smem_u32(smem);
  const int tid = threadIdx.x, wid = tid >> 5, lane = tid & 31;
  const int wm = wid >> 2, wn = wid & 3;
  const int bm = blockIdx.y, bn = blockIdx.x;
  const int w = (int)blockIdx.z;

  const __half* Wt = (w == 0) ? g_Wq16 : (w == 1) ? g_Wk16 : g_Wv16;
  const float* bias = (w == 0) ? bias_q : (w == 1) ? bias_k : bias_v;

  const int p = tid >> 6, q = tid & 63;
  const __half* psrc = nullptr;
  if (p < 3) {
    const size_t arow = (size_t)bm * 128 * KDIM;
    const size_t brow = (size_t)bn * 128 * KDIM;
    psrc = (p == 0) ? g_xh + arow : (p == 1) ? g_xl + arow : Wt + brow;
    psrc += (size_t)(q >> 3) * KDIM + (q & 7) * 8;
  }
  const uint32_t loff0 = (uint32_t)((q >> 3) * 128 + (q & 7) * 16);

  auto issue = [&](int kt) {
    const int buf = kt & 1;
    if (p < 3) {
      const __half* g = psrc + kt * KT;
      const uint32_t dstbase = sb + buf * STAGE_Q + p * PIECE_BYTES;
#pragma unroll
      for (int j = 0; j < 16; ++j) {
        const uint32_t off = loff0 + j * 1024;
        const uint32_t swz = off ^ ((off >> 3) & 0x70);
        cpasync16(dstbase + swz, g + (size_t)j * 8 * KDIM);
      }
    }
    cp_commit();
  };

  float acc[4][4][4];
#pragma unroll
  for (int i = 0; i < 4; ++i)
#pragma unroll
    for (int j = 0; j < 4; ++j)
#pragma unroll
      for (int k = 0; k < 4; ++k) acc[i][j][k] = 0.f;

  issue(0);
#pragma unroll 1
  for (int kt = 0; kt < NKT; ++kt) {
    if (kt + 1 < NKT) {
      issue(kt + 1);
      cp_wait<1>();
    } else {
      cp_wait<0>();
    }
    __syncthreads();
    const uint32_t base = sb + (kt & 1) * STAGE_Q;
#pragma unroll
    for (int ks = 0; ks < 4; ++ks) {
      const int k0 = ks * 16;
      uint32_t ah[4][4], al[4][4], bb[2][4];
#pragma unroll
      for (int mt = 0; mt < 4; ++mt) {
        const uint32_t row = wm * 64 + mt * 16 + (lane & 15);
        const uint32_t off = row * 128 + k0 * 2 + ((lane >> 4) << 4);
        const uint32_t swz = off ^ ((off >> 3) & 0x70);
        ldsm4(ah[mt], base + swz);
        ldsm4(al[mt], base + PIECE_BYTES + swz);
      }
#pragma unroll
      for (int nt2 = 0; nt2 < 2; ++nt2) {
        const uint32_t row =
            wn * 32 + nt2 * 16 + (lane & 7) + ((lane >> 4) << 3);
        const uint32_t off = row * 128 + k0 * 2 + (((lane >> 3) & 1) << 4);
        const uint32_t swz = off ^ ((off >> 3) & 0x70);
        ldsm4(bb[nt2], base + 2 * PIECE_BYTES + swz);
      }
#pragma unroll
      for (int mt = 0; mt < 4; ++mt)
#pragma unroll
        for (int nt = 0; nt < 4; ++nt)
          mma_hf(acc[mt][nt], ah[mt], &bb[nt >> 1][(nt & 1) * 2]);
#pragma unroll
      for (int mt = 0; mt < 4; ++mt)
#pragma unroll
        for (int nt = 0; nt < 4; ++nt)
          mma_hf(acc[mt][nt], al[mt], &bb[nt >> 1][(nt & 1) * 2]);
    }
    __syncthreads();
  }

  const int g = lane >> 2, t2 = (lane & 3) * 2;
#pragma unroll
  for (int mt = 0; mt < 4; ++mt) {
    const int r0 = bm * 128 + wm * 64 + mt * 16 + g;
    const int r1 = r0 + 8;
    float sn0 = 0.f, cs0 = 0.f, sn1 = 0.f, cs1 = 0.f;
    if (w == 1) {
      sincosf(ANGC * (float)(r0 & (Tc - 1)), &sn0, &cs0);
      sincosf(ANGC * (float)(r1 & (Tc - 1)), &sn1, &cs1);
    }
#pragma unroll
    for (int nt = 0; nt < 4; ++nt) {
      const int col = bn * 128 + wn * 32 + nt * 8 + t2;
      const float b0 = __ldg(&bias[col]), b1 = __ldg(&bias[col + 1]);
      const float v00 = acc[mt][nt][0] + b0, v01 = acc[mt][nt][1] + b1;
      const float v10 = acc[mt][nt][2] + b0, v11 = acc[mt][nt][3] + b1;
      if (w == 2) {
        *(float2*)&g_V[(size_t)r0 * HD + col] = make_float2(v00, v01);
        *(float2*)&g_V[(size_t)r1 * HD + col] = make_float2(v10, v11);
      } else if (w == 0) {
        *(float2*)&g_Qp[(size_t)r0 * HD + col] =
            make_float2(fmaxf(v00, 0.f), fmaxf(v01, 0.f));
        *(float2*)&g_Qp[(size_t)r1 * HD + col] =
            make_float2(fmaxf(v10, 0.f), fmaxf(v11, 0.f));
      } else {
        const float a00 = fmaxf(v00, 0.f), a01 = fmaxf(v01, 0.f);
        const float a10 = fmaxf(v10, 0.f), a11 = fmaxf(v11, 0.f);
        *(float2*)&g_Kp[(size_t)r0 * HD + col] = make_float2(a00, a01);
        *(float2*)&g_Kp[(size_t)r1 * HD + col] = make_float2(a10, a11);
        *(float2*)&g_Kc[(size_t)r0 * HD + col] =
            make_float2(a00 * cs0, a01 * cs0);
        *(float2*)&g_Kc[(size_t)r1 * HD + col] =
            make_float2(a10 * cs1, a11 * cs1);
        *(float2*)&g_Ks[(size_t)r0 * HD + col] =
            make_float2(a00 * sn0, a01 * sn0);
        *(float2*)&g_Ks[(size_t)r1 * HD + col] =
            make_float2(a10 * sn1, a11 * sn1);
      }
    }
  }
}

// ============================================================================
// Output GEMM: fp16 2-pass (A = g_a16 single fp16, B = Wo fp16 hi/lo)
// ============================================================================
constexpr int STAGE_O = 3 * PIECE_BYTES;          // 49152
constexpr int GEMM_SMEM_O = 2 * STAGE_O;          // 98304

__global__ __launch_bounds__(256, 1) void gemm_o16(
    const float* __restrict__ bias, float* __restrict__ outO) {
  extern __shared__ __align__(16) char smem[];
  const uint32_t sb = smem_u32(smem);
  const int tid = threadIdx.x, wid = tid >> 5, lane = tid & 31;
  const int wm = wid >> 2, wn = wid & 3;
  const int bm = blockIdx.y, bn = blockIdx.x;

  const int p = tid >> 6, q = tid & 63;
  const __half* psrc = nullptr;
  if (p < 3) {
    const size_t arow = (size_t)bm * 128 * KDIM;
    const size_t brow = (size_t)bn * 128 * KDIM;
    psrc = (p == 0) ? g_a16 + arow : (p == 1) ? g_Wo16h + brow
                                              : g_Wo16l + brow;
    psrc += (size_t)(q >> 3) * KDIM + (q & 7) * 8;
  }
  const uint32_t loff0 = (uint32_t)((q >> 3) * 128 + (q & 7) * 16);

  auto issue = [&](int kt) {
    const int buf = kt & 1;
    if (p < 3) {
      const __half* g = psrc + kt * KT;
      const uint32_t dstbase = sb + buf * STAGE_O + p * PIECE_BYTES;
#pragma unroll
      for (int j = 0; j < 16; ++j) {
        const uint32_t off = loff0 + j * 1024;
        const uint32_t swz = off ^ ((off >> 3) & 0x70);
        cpasync16(dstbase + swz, g + (size_t)j * 8 * KDIM);
      }
    }
    cp_commit();
  };

  float acc[4][4][4];
#pragma unroll
  for (int i = 0; i < 4; ++i)
#pragma unroll
    for (int j = 0; j < 4; ++j)
#pragma unroll
      for (int k = 0; k < 4; ++k) acc[i][j][k] = 0.f;

  issue(0);
#pragma unroll 1
  for (int kt = 0; kt < NKT; ++kt) {
    if (kt + 1 < NKT) {
      issue(kt + 1);
      cp_wait<1>();
    } else {
      cp_wait<0>();
    }
    __syncthreads();
    const uint32_t base = sb + (kt & 1) * STAGE_O;
#pragma unroll
    for (int ks = 0; ks < 4; ++ks) {
      const int k0 = ks * 16;
      uint32_t a[4][4], bh[2][4], bl[2][4];
#pragma unroll
      for (int mt = 0; mt < 4; ++mt) {
        const uint32_t row = wm * 64 + mt * 16 + (lane & 15);
        const uint32_t off = row * 128 + k0 * 2 + ((lane >> 4) << 4);
        const uint32_t swz = off ^ ((off >> 3) & 0x70);
        ldsm4(a[mt], base + swz);
      }
#pragma unroll
      for (int nt2 = 0; nt2 < 2; ++nt2) {
        const uint32_t row =
            wn * 32 + nt2 * 16 + (lane & 7) + ((lane >> 4) << 3);
        const uint32_t off = row * 128 + k0 * 2 + (((lane >> 3) & 1) << 4);
        const uint32_t swz = off ^ ((off >> 3) & 0x70);
        ldsm4(bh[nt2], base + PIECE_BYTES + swz);
        ldsm4(bl[nt2], base + 2 * PIECE_BYTES + swz);
      }
#pragma unroll
      for (int mt = 0; mt < 4; ++mt)
#pragma unroll
        for (int nt = 0; nt < 4; ++nt)
          mma_hf(acc[mt][nt], a[mt], &bh[nt >> 1][(nt & 1) * 2]);
#pragma unroll
      for (int mt = 0; mt < 4; ++mt)
#pragma unroll
        for (int nt = 0; nt < 4; ++nt)
          mma_hf(acc[mt][nt], a[mt], &bl[nt >> 1][(nt & 1) * 2]);
    }
    __syncthreads();
  }

  const int g = lane >> 2, t2 = (lane & 3) * 2;
#pragma unroll
  for (int mt = 0; mt < 4; ++mt) {
    const int r0 = bm * 128 + wm * 64 + mt * 16 + g;
    const int r1 = r0 + 8;
#pragma unroll
    for (int nt = 0; nt < 4; ++nt) {
      const int col = bn * 128 + wn * 32 + nt * 8 + t2;
      const float b0 = __ldg(&bias[col]), b1 = __ldg(&bias[col + 1]);
      *(float2*)&outO[(size_t)r0 * DM + col] =
          make_float2(acc[mt][nt][0] + b0, acc[mt][nt][1] + b1);
      *(float2*)&outO[(size_t)r1 * DM + col] =
          make_float2(acc[mt][nt][2] + b0, acc[mt][nt][3] + b1);
    }
  }
}

// ============================================================================
// Pass A: per-chunk states (reads g_Kc/g_Ks/g_V)
// ============================================================================
__global__ __launch_bounds__(256) void chunk_stats() {
  const int blk = blockIdx.x;
  const int c = blk & (NCH - 1);
  const int bh = blk >> 5;
  const int b = bh >> 4, h = bh & 15;
  const int tid = threadIdx.x, tx = tid & 15, ty = tid >> 4;

  __shared__ __align__(16) float sKc[32][64];
  __shared__ __align__(16) float sKs[32][64];
  __shared__ __align__(16) float sV[32][64];

  float aC[4][4] = {}, aS[4][4] = {};
  float zc[4] = {}, zs[4] = {};
  const size_t rowbase = ((size_t)b * Tc + (size_t)c * CH) * HD + h * DHc;

  for (int t0 = 0; t0 < CH; t0 += 32) {
    __syncthreads();
    for (int l = tid; l < 32 * 16; l += 256) {
      const int r = l >> 4, cc = (l & 15) << 2;
      const size_t g = rowbase + (size_t)(t0 + r) * HD + cc;
      *(float4*)&sKc[r][cc] = *(const float4*)&g_Kc[g];
      *(float4*)&sKs[r][cc] = *(const float4*)&g_Ks[g];
      *(float4*)&sV[r][cc] = *(const float4*)&g_V[g];
    }
    __syncthreads();
#pragma unroll 4
    for (int t = 0; t < 32; ++t) {
      float kc[4], ks[4], v[4];
#pragma unroll
      for (int i = 0; i < 4; ++i) {
        kc[i] = sKc[t][ty * 4 + i];
        ks[i] = sKs[t][ty * 4 + i];
      }
#pragma unroll
      for (int j = 0; j < 4; ++j) v[j] = sV[t][tx * 4 + j];
#pragma unroll
      for (int i = 0; i < 4; ++i)
#pragma unroll
        for (int j = 0; j < 4; ++j) {
          aC[i][j] += kc[i] * v[j];
          aS[i][j] += ks[i] * v[j];
        }
      if (tx == 0) {
#pragma unroll
        for (int i = 0; i < 4; ++i) { zc[i] += kc[i]; zs[i] += ks[i]; }
      }
    }
  }

  const size_t sbse = ((size_t)bh * NCH + c) * (DHc * DHc);
#pragma unroll
  for (int i = 0; i < 4; ++i) {
    *(float4*)&g_Scos[sbse + (size_t)(ty * 4 + i) * 64 + tx * 4] =
        make_float4(aC[i][0], aC[i][1], aC[i][2], aC[i][3]);
    *(float4*)&g_Ssin[sbse + (size_t)(ty * 4 + i) * 64 + tx * 4] =
        make_float4(aS[i][0], aS[i][1], aS[i][2], aS[i][3]);
  }
  if (tx == 0) {
    const size_t zb = ((size_t)bh * NCH + c) * DHc;
#pragma unroll
    for (int i = 0; i < 4; ++i) {
      g_zcos[zb + ty * 4 + i] = zc[i];
      g_zsin[zb + ty * 4 + i] = zs[i];
    }
  }
}

// ============================================================================
// Pass B: exclusive prefix over chunks
// ============================================================================
__global__ __launch_bounds__(256) void chunk_scan2() {
  const int bh = blockIdx.y;
  const int e = blockIdx.x * 256 + threadIdx.x;
  {
    const size_t base = (size_t)bh * NCH * (DHc * DHc) + e;
    float ac = 0.f, as2 = 0.f;
#pragma unroll 1
    for (int c = 0; c < NCH; ++c) {
      const size_t idx = base + (size_t)c * (DHc * DHc);
      const float tc = g_Scos[idx], ts = g_Ssin[idx];
      g_Scos[idx] = ac;
      g_Ssin[idx] = as2;
      ac += tc;
      as2 += ts;
    }
  }
  if (blockIdx.x == 0 && threadIdx.x < DHc) {
    const size_t zb = (size_t)bh * NCH * DHc + threadIdx.x;
    float ac = 0.f, as2 = 0.f;
#pragma unroll 1
    for (int c = 0; c < NCH; ++c) {
      const size_t idx = zb + (size_t)c * DHc;
      const float tc = g_zcos[idx], ts = g_zsin[idx];
      g_zcos[idx] = ac;
      g_zsin[idx] = as2;
      ac += tc;
      as2 += ts;
    }
  }
}

// ============================================================================
// Pass C: per-chunk output, 512 threads (trig identity intra, folded AV,
// fused rowsum, fp16 epilogue).
// ============================================================================
constexpr int SQ_LD = 65;
constexpr int SA_LD = 129;
constexpr int OFF_QP = 0;
constexpr int OFF_KP = 128 * SQ_LD;
constexpr int OFF_A = 2 * 128 * SQ_LD;
constexpr int OFF_SC = OFF_A + CH * SA_LD;
constexpr int OFF_SS = OFF_SC + DHc * DHc;
constexpr int OFF_ZC = OFF_SS + DHc * DHc;
constexpr int OFF_ZS = OFF_ZC + DHc;
constexpr int OFF_TC = OFF_ZS + DHc;
constexpr int OFF_TS = OFF_TC + CH;
constexpr int SMEM_FLOATS = OFF_TS + CH;

__global__ __launch_bounds__(512, 1) void attn_out() {
  extern __shared__ __align__(16) float sm[];
  const int blk = blockIdx.x;
  const int c = blk & (NCH - 1);
  const int bh = blk >> 5;
  const int b = bh >> 4, h = bh & 15;
  const int tid = threadIdx.x;

  float* sQp = sm + OFF_QP;
  float* sKp = sm + OFF_KP;
  float* sA = sm + OFF_A;
  float* sSc = sm + OFF_SC;
  float* sSs = sm + OFF_SS;
  float* szc = sm + OFF_ZC;
  float* szs = sm + OFF_ZS;
  float* strc = sm + OFF_TC;
  float* strs = sm + OFF_TS;
  float* sV = sKp;

  const size_t gbase = ((size_t)b * Tc + (size_t)c * CH) * HD + h * DHc;

  if (tid < CH) {
    float sn, cs;
    sincosf(ANGC * (float)(c * CH + tid), &sn, &cs);
    strc[tid] = cs;
    strs[tid] = sn;
  }
  for (int l = tid; l < CH * 16; l += 512) {
    const int r = l >> 4, cc = (l & 15) << 2;
    const size_t g = gbase + (size_t)r * HD + cc;
    float4 vq = *(const float4*)&g_Qp[g];
    float4 vk = *(const float4*)&g_Kp[g];
    float* pp;
    pp = &sQp[r * SQ_LD + cc]; pp[0]=vq.x; pp[1]=vq.y; pp[2]=vq.z; pp[3]=vq.w;
    pp = &sKp[r * SQ_LD + cc]; pp[0]=vk.x; pp[1]=vk.y; pp[2]=vk.z; pp[3]=vk.w;
  }
  __syncthreads();

  if (tid < 272) {
    const int tau = tid;
    int i = (int)((sqrtf(4.f * (float)tau + 1.f) - 1.f) * 0.5f);
    while ((i + 1) * (i + 2) <= tau) ++i;
    while (i * (i + 1) > tau) --i;
    const int j = tau - i * (i + 1);
    const int t0 = i * 8, s0 = j * 4;
    float a[8][4] = {};
#pragma unroll 2
    for (int d = 0; d < DHc; ++d) {
      float qp[8], kp[4];
#pragma unroll
      for (int r = 0; r < 8; ++r) qp[r] = sQp[(t0 + r) * SQ_LD + d];
#pragma unroll
      for (int cc = 0; cc < 4; ++cc) kp[cc] = sKp[(s0 + cc) * SQ_LD + d];
#pragma unroll
      for (int r = 0; r < 8; ++r)
#pragma unroll
        for (int cc = 0; cc < 4; ++cc) a[r][cc] += qp[r] * kp[cc];
    }
    float cs4[4], ss4[4];
#pragma unroll
    for (int cc = 0; cc < 4; ++cc) {
      cs4[cc] = strc[s0 + cc];
      ss4[cc] = strs[s0 + cc];
    }
#pragma unroll
    for (int r = 0; r < 8; ++r) {
      const float ct = strc[t0 + r], st = strs[t0 + r];
#pragma unroll
      for (int cc = 0; cc < 4; ++cc)
        sA[(t0 + r) * SA_LD + s0 + cc] =
            (s0 + cc <= t0 + r) ? (ct * cs4[cc] + st * ss4[cc]) * a[r][cc]
                                : 0.f;
    }
  }
  __syncthreads();

  for (int l = tid; l < CH * 16; l += 512) {
    const int r = l >> 4, cc = (l & 15) << 2;
    *(float4*)&sV[r * 64 + cc] =
        *(const float4*)&g_V[gbase + (size_t)r * HD + cc];
  }
  const size_t sbse = ((size_t)bh * NCH + c) * (DHc * DHc);
  for (int l = tid; l < 64 * 16; l += 512) {
    const int r = l >> 4, cc = (l & 15) << 2;
    *(float4*)&sSc[r * 64 + cc] = *(const float4*)&g_Scos[sbse + r * 64 + cc];
    *(float4*)&sSs[r * 64 + cc] = *(const float4*)&g_Ssin[sbse + r * 64 + cc];
  }
  if (tid < DHc) {
    const size_t zb = ((size_t)bh * NCH + c) * DHc;
    szc[tid] = g_zcos[zb + tid];
    szs[tid] = g_zsin[zb + tid];
  }
  __syncthreads();

  const int tx = tid & 15, ty = tid >> 4;
  const int n0 = tx * 4;
  const int rA = ty * 2;
  const int rB = 126 - ty * 2;
  int rowid[4] = {rA, rA + 1, rB, rB + 1};
  float o[4][4] = {};
  float rs[4] = {};
#pragma unroll 1
  for (int s = 0; s <= rA + 1; ++s) {
    const float4 v4 = *(const float4*)&sV[s * 64 + n0];
#pragma unroll
    for (int i = 0; i < 2; ++i) {
      const float av = sA[(rA + i) * SA_LD + s];
      o[i][0] += av * v4.x;
      o[i][1] += av * v4.y;
      o[i][2] += av * v4.z;
      o[i][3] += av * v4.w;
      rs[i] += av;
    }
  }
#pragma unroll 1
  for (int s = 0; s <= rB + 1; ++s) {
    const float4 v4 = *(const float4*)&sV[s * 64 + n0];
#pragma unroll
    for (int i = 0; i < 2; ++i) {
      const float av = sA[(rB + i) * SA_LD + s];
      o[2 + i][0] += av * v4.x;
      o[2 + i][1] += av * v4.y;
      o[2 + i][2] += av * v4.z;
      o[2 + i][3] += av * v4.w;
      rs[2 + i] += av;
    }
  }

  float uc[4][4] = {}, us[4][4] = {}, dc[4] = {}, ds[4] = {};
#pragma unroll 2
  for (int d = 0; d < DHc; ++d) {
    const float4 sc4 = *(const float4*)&sSc[d * 64 + n0];
    const float4 ss4 = *(const float4*)&sSs[d * 64 + n0];
    const float zcv = szc[d], zsv = szs[d];
#pragma unroll
    for (int i = 0; i < 4; ++i) {
      const float qp = sQp[rowid[i] * SQ_LD + d];
      uc[i][0] += qp * sc4.x;
      uc[i][1] += qp * sc4.y;
      uc[i][2] += qp * sc4.z;
      uc[i][3] += qp * sc4.w;
      us[i][0] += qp * ss4.x;
      us[i][1] += qp * ss4.y;
      us[i][2] += qp * ss4.z;
      us[i][3] += qp * ss4.w;
      dc[i] += qp * zcv;
      ds[i] += qp * zsv;
    }
  }

#pragma unroll
  for (int i = 0; i < 4; ++i) {
    const int t = rowid[i];
    const float ct = strc[t], st = strs[t];
    const float den = fmaxf(rs[i] + ct * dc[i] + st * ds[i], 1e-6f);
    const float inv = 1.0f / den;
    __half hv[4];
#pragma unroll
    for (int e = 0; e < 4; ++e)
      hv[e] = __float2half((o[i][e] + ct * uc[i][e] + st * us[i][e]) * inv);
    *(uint2*)&g_a16[gbase + (size_t)t * HD + n0] = *(uint2*)hv;
  }
}

}  // namespace cf

extern "C" void kernel_launch(void* const* d_in, const int* in_sizes, int n_in,
                              void* d_out, int out_size) {
  using namespace cf;
  const float* x = (const float*)d_in[0];
  const float* Wq = (const float*)d_in[1];
  const float* bq = (const float*)d_in[2];
  const float* Wk = (const float*)d_in[3];
  const float* bk = (const float*)d_in[4];
  const float* Wv = (const float*)d_in[5];
  const float* bv = (const float*)d_in[6];
  const float* Wo = (const float*)d_in[7];
  const float* bo = (const float*)d_in[8];
  float* out = (float*)d_out;

  cudaFuncSetAttribute(gemm_qkv, cudaFuncAttributeMaxDynamicSharedMemorySize,
                       GEMM_SMEM_Q);
  cudaFuncSetAttribute(gemm_o16, cudaFuncAttributeMaxDynamicSharedMemorySize,
                       GEMM_SMEM_O);
  cudaFuncSetAttribute(attn_out, cudaFuncAttributeMaxDynamicSharedMemorySize,
                       (int)(SMEM_FLOATS * sizeof(float)));

  // 1) splits
  split_x<<<Mrows * DM / 4 / 256, 256>>>(x);
  dim3 tg(32, 32), tb(32, 8);
  tsplit<0><<<tg, tb>>>(Wq);
  tsplit<1><<<tg, tb>>>(Wk);
  tsplit<2><<<tg, tb>>>(Wv);
  tsplit_o<<<tg, tb>>>(Wo);

  // 2) fused QKV projection (fp16, 2 passes)
  dim3 gq(HD / 128, Mrows / 128, 3);
  gemm_qkv<<<gq, 256, GEMM_SMEM_Q>>>(bq, bk, bv);

  // 3) attention
  chunk_stats<<<BHc * NCH, 256>>>();
  chunk_scan2<<<dim3(16, 32), 256>>>();
  attn_out<<<BHc * NCH, 512, SMEM_FLOATS * sizeof(float)>>>();

  // 4) output projection (fp16 2-pass)
  dim3 go(HD / 128, Mrows / 128);
  gemm_o16<<<go, 256, GEMM_SMEM_O>>>(bo, out);
}

// round 10
// speedup vs baseline: 3.1694x; 1.2309x over previous
#include <cuda_runtime.h>
#include <cuda_fp16.h>
#include <math.h>
#include <stdint.h>

// ============================================================================
// CosFormer attention (sm_103 base; legacy HMMA mma.sync).
//  - ALL GEMMs: single-pass fp16 (x, W, attn, Wo all fp16-rounded).
//    Calibrated RSS error model -> ~4.4e-4 total (gate 1e-3).
//  - Attention: chunked linear attention fp32; trig identity
//      A[t,s] = cos(th_t - th_s) * (Qp_t . Kp_s).
//  Round-10 fix: loader geometry (round-9 version overflowed SMEM).
// ============================================================================

namespace cf {

constexpr int Bc = 2, Tc = 4096, Hc = 16, DHc = 64;
constexpr int DM = 1024, HD = 1024;
constexpr int Mrows = Bc * Tc;            // 8192
constexpr int CH = 128, NCH = Tc / CH;    // 128, 32
constexpr int BHc = Bc * Hc;              // 32
constexpr float ANGC = 3.14159265358979323846f / (2.0f * (float)Tc);

constexpr int KDIM = 1024;
constexpr int KT = 64;
constexpr int NKT = KDIM / KT;            // 16

// ---- fp32 scratch ----
__device__ __align__(16) float g_Qp[(size_t)Mrows * HD];
__device__ __align__(16) float g_Kp[(size_t)Mrows * HD];
__device__ __align__(16) float g_Kc[(size_t)Mrows * HD];
__device__ __align__(16) float g_Ks[(size_t)Mrows * HD];
__device__ __align__(16) float g_V [(size_t)Mrows * HD];
__device__ __align__(16) float g_Scos[(size_t)BHc * NCH * DHc * DHc];
__device__ __align__(16) float g_Ssin[(size_t)BHc * NCH * DHc * DHc];
__device__ __align__(16) float g_zcos[(size_t)BHc * NCH * DHc];
__device__ __align__(16) float g_zsin[(size_t)BHc * NCH * DHc];

// ---- fp16 operands ----
__device__ __align__(16) __half g_x16[(size_t)Mrows * DM];
__device__ __align__(16) __half g_Wq16[(size_t)HD * DM];
__device__ __align__(16) __half g_Wk16[(size_t)HD * DM];
__device__ __align__(16) __half g_Wv16[(size_t)HD * DM];
__device__ __align__(16) __half g_Wo16[(size_t)DM * HD];
__device__ __align__(16) __half g_a16[(size_t)Mrows * HD];

// ============================================================================
// helpers
// ============================================================================
__device__ __forceinline__ uint32_t smem_u32(const void* p) {
  uint32_t a;
  asm("{ .reg .u64 t; cvta.to.shared.u64 t, %1; cvt.u32.u64 %0, t; }"
      : "=r"(a) : "l"(p));
  return a;
}
__device__ __forceinline__ void ldsm4(uint32_t* r, uint32_t addr) {
  asm volatile(
      "ldmatrix.sync.aligned.m8n8.x4.shared.b16 {%0,%1,%2,%3}, [%4];"
      : "=r"(r[0]), "=r"(r[1]), "=r"(r[2]), "=r"(r[3]) : "r"(addr));
}
__device__ __forceinline__ void mma_hf(float* d, const uint32_t* a,
                                       const uint32_t* b) {
  asm volatile(
      "mma.sync.aligned.m16n8k16.row.col.f32.f16.f16.f32 "
      "{%0,%1,%2,%3}, {%4,%5,%6,%7}, {%8,%9}, {%0,%1,%2,%3};"
      : "+f"(d[0]), "+f"(d[1]), "+f"(d[2]), "+f"(d[3])
      : "r"(a[0]), "r"(a[1]), "r"(a[2]), "r"(a[3]), "r"(b[0]), "r"(b[1]));
}
__device__ __forceinline__ void cpasync16(uint32_t dst, const void* src) {
  asm volatile("cp.async.cg.shared.global [%0], [%1], 16;"
               ::"r"(dst), "l"(src) : "memory");
}
__device__ __forceinline__ void cp_commit() {
  asm volatile("cp.async.commit_group;" ::: "memory");
}
template <int N>
__device__ __forceinline__ void cp_wait() {
  asm volatile("cp.async.wait_group %0;" ::"n"(N) : "memory");
}

// ============================================================================
// Conversions
// ============================================================================
__global__ __launch_bounds__(256) void conv_x(const float* __restrict__ in) {
  int i = blockIdx.x * 256 + threadIdx.x;
  float4 v = *(const float4*)(in + (size_t)i * 4);
  __half h[4] = {__float2half(v.x), __float2half(v.y), __float2half(v.z),
                 __float2half(v.w)};
  *(uint2*)(g_x16 + (size_t)i * 4) = *(uint2*)h;
}

// W[K][N] fp32 -> Wt[N][K] fp16.  blockIdx.z: 0=q 1=k 2=v 3=o
__global__ __launch_bounds__(256) void tconv(const float* __restrict__ Wq,
                                             const float* __restrict__ Wk,
                                             const float* __restrict__ Wv,
                                             const float* __restrict__ Wo) {
  const int w = blockIdx.z;
  const float* W = (w == 0) ? Wq : (w == 1) ? Wk : (w == 2) ? Wv : Wo;
  __half* T = (w == 0) ? g_Wq16 : (w == 1) ? g_Wk16 : (w == 2) ? g_Wv16
                                                               : g_Wo16;
  __shared__ float tile[32][33];
  const int bx = blockIdx.x * 32, by = blockIdx.y * 32;
  const int tx = threadIdx.x, ty = threadIdx.y;
#pragma unroll
  for (int j = 0; j < 4; ++j)
    tile[ty + j * 8][tx] = W[(size_t)(by + ty + j * 8) * 1024 + bx + tx];
  __syncthreads();
#pragma unroll
  for (int j = 0; j < 4; ++j)
    T[(size_t)(bx + ty + j * 8) * 1024 + by + tx] =
        __float2half(tile[tx][ty + j * 8]);
}

// ============================================================================
// Single-pass fp16 GEMM. FUSED=1: QKV via grid.z (A = g_x16).
// FUSED=0: out proj (A = g_a16, B = g_Wo16, writes outO).
// 128x128 CTA, 8 warps of 64x32, K staged 64, cp.async double buffer.
// Loader: piece p=tid>>7 (0:A 1:B), q=tid&127; thread covers row (q>>3)+16j,
// column 16B-slot (q&7); 8 chunks. Max smem offset 16368 < 16384.  OK.
// ============================================================================
constexpr int PIECE_BYTES = 128 * KT * 2;         // 16384
constexpr int STAGE_1P = 2 * PIECE_BYTES;         // 32768
constexpr int GEMM_SMEM_1P = 2 * STAGE_1P;        // 65536

template <int FUSED>
__global__ __launch_bounds__(256, 1) void gemm_1p(
    const float* __restrict__ bias_q, const float* __restrict__ bias_k,
    const float* __restrict__ bias_v, float* __restrict__ outO) {
  extern __shared__ __align__(16) char smem[];
  const uint32_t sb = smem_u32(smem);
  const int tid = threadIdx.x, wid = tid >> 5, lane = tid & 31;
  const int wm = wid >> 2, wn = wid & 3;
  const int bm = blockIdx.y, bn = blockIdx.x;
  const int w = FUSED ? (int)blockIdx.z : 3;  // 0=Q 1=K 2=V 3=O

  const __half* A = FUSED ? g_x16 : g_a16;
  const __half* Bm = (w == 0) ? g_Wq16 : (w == 1) ? g_Wk16
                       : (w == 2) ? g_Wv16 : g_Wo16;
  const float* bias = FUSED
                          ? ((w == 0) ? bias_q : (w == 1) ? bias_k : bias_v)
                          : bias_q;

  const int p = tid >> 7, q = tid & 127;
  const __half* psrc =
      ((p == 0) ? A + (size_t)bm * 128 * KDIM : Bm + (size_t)bn * 128 * KDIM) +
      (size_t)(q >> 3) * KDIM + (q & 7) * 8;
  const uint32_t loff0 = (uint32_t)((q >> 3) * 128 + (q & 7) * 16);

  auto issue = [&](int kt) {
    const int buf = kt & 1;
    const __half* g = psrc + kt * KT;
    const uint32_t dstbase = sb + buf * STAGE_1P + p * PIECE_BYTES;
#pragma unroll
    for (int j = 0; j < 8; ++j) {
      const uint32_t off = loff0 + j * 2048;  // 16 rows * 128B
      const uint32_t swz = off ^ ((off >> 3) & 0x70);
      cpasync16(dstbase + swz, g + (size_t)j * 16 * KDIM);
    }
    cp_commit();
  };

  float acc[4][4][4];
#pragma unroll
  for (int i = 0; i < 4; ++i)
#pragma unroll
    for (int j = 0; j < 4; ++j)
#pragma unroll
      for (int k = 0; k < 4; ++k) acc[i][j][k] = 0.f;

  issue(0);
#pragma unroll 1
  for (int kt = 0; kt < NKT; ++kt) {
    if (kt + 1 < NKT) {
      issue(kt + 1);
      cp_wait<1>();
    } else {
      cp_wait<0>();
    }
    __syncthreads();
    const uint32_t base = sb + (kt & 1) * STAGE_1P;
#pragma unroll
    for (int ks = 0; ks < 4; ++ks) {
      const int k0 = ks * 16;
      uint32_t a[4][4], bb[2][4];
#pragma unroll
      for (int mt = 0; mt < 4; ++mt) {
        const uint32_t row = wm * 64 + mt * 16 + (lane & 15);
        const uint32_t off = row * 128 + k0 * 2 + ((lane >> 4) << 4);
        const uint32_t swz = off ^ ((off >> 3) & 0x70);
        ldsm4(a[mt], base + swz);
      }
#pragma unroll
      for (int nt2 = 0; nt2 < 2; ++nt2) {
        const uint32_t row =
            wn * 32 + nt2 * 16 + (lane & 7) + ((lane >> 4) << 3);
        const uint32_t off = row * 128 + k0 * 2 + (((lane >> 3) & 1) << 4);
        const uint32_t swz = off ^ ((off >> 3) & 0x70);
        ldsm4(bb[nt2], base + PIECE_BYTES + swz);
      }
#pragma unroll
      for (int mt = 0; mt < 4; ++mt)
#pragma unroll
        for (int nt = 0; nt < 4; ++nt)
          mma_hf(acc[mt][nt], a[mt], &bb[nt >> 1][(nt & 1) * 2]);
    }
    __syncthreads();
  }

  const int g = lane >> 2, t2 = (lane & 3) * 2;
#pragma unroll
  for (int mt = 0; mt < 4; ++mt) {
    const int r0 = bm * 128 + wm * 64 + mt * 16 + g;
    const int r1 = r0 + 8;
    float sn0 = 0.f, cs0 = 0.f, sn1 = 0.f, cs1 = 0.f;
    if (FUSED && w == 1) {
      sincosf(ANGC * (float)(r0 & (Tc - 1)), &sn0, &cs0);
      sincosf(ANGC * (float)(r1 & (Tc - 1)), &sn1, &cs1);
    }
#pragma unroll
    for (int nt = 0; nt < 4; ++nt) {
      const int col = bn * 128 + wn * 32 + nt * 8 + t2;
      const float b0 = __ldg(&bias[col]), b1 = __ldg(&bias[col + 1]);
      const float v00 = acc[mt][nt][0] + b0, v01 = acc[mt][nt][1] + b1;
      const float v10 = acc[mt][nt][2] + b0, v11 = acc[mt][nt][3] + b1;
      if (!FUSED) {
        *(float2*)&outO[(size_t)r0 * DM + col] = make_float2(v00, v01);
        *(float2*)&outO[(size_t)r1 * DM + col] = make_float2(v10, v11);
      } else if (w == 2) {
        *(float2*)&g_V[(size_t)r0 * HD + col] = make_float2(v00, v01);
        *(float2*)&g_V[(size_t)r1 * HD + col] = make_float2(v10, v11);
      } else if (w == 0) {
        *(float2*)&g_Qp[(size_t)r0 * HD + col] =
            make_float2(fmaxf(v00, 0.f), fmaxf(v01, 0.f));
        *(float2*)&g_Qp[(size_t)r1 * HD + col] =
            make_float2(fmaxf(v10, 0.f), fmaxf(v11, 0.f));
      } else {
        const float a00 = fmaxf(v00, 0.f), a01 = fmaxf(v01, 0.f);
        const float a10 = fmaxf(v10, 0.f), a11 = fmaxf(v11, 0.f);
        *(float2*)&g_Kp[(size_t)r0 * HD + col] = make_float2(a00, a01);
        *(float2*)&g_Kp[(size_t)r1 * HD + col] = make_float2(a10, a11);
        *(float2*)&g_Kc[(size_t)r0 * HD + col] =
            make_float2(a00 * cs0, a01 * cs0);
        *(float2*)&g_Kc[(size_t)r1 * HD + col] =
            make_float2(a10 * cs1, a11 * cs1);
        *(float2*)&g_Ks[(size_t)r0 * HD + col] =
            make_float2(a00 * sn0, a01 * sn0);
        *(float2*)&g_Ks[(size_t)r1 * HD + col] =
            make_float2(a10 * sn1, a11 * sn1);
      }
    }
  }
}

// ============================================================================
// Pass A: per-chunk states
// ============================================================================
__global__ __launch_bounds__(256) void chunk_stats() {
  const int blk = blockIdx.x;
  const int c = blk & (NCH - 1);
  const int bh = blk >> 5;
  const int b = bh >> 4, h = bh & 15;
  const int tid = threadIdx.x, tx = tid & 15, ty = tid >> 4;

  __shared__ __align__(16) float sKc[32][64];
  __shared__ __align__(16) float sKs[32][64];
  __shared__ __align__(16) float sV[32][64];

  float aC[4][4] = {}, aS[4][4] = {};
  float zc[4] = {}, zs[4] = {};
  const size_t rowbase = ((size_t)b * Tc + (size_t)c * CH) * HD + h * DHc;

  for (int t0 = 0; t0 < CH; t0 += 32) {
    __syncthreads();
    for (int l = tid; l < 32 * 16; l += 256) {
      const int r = l >> 4, cc = (l & 15) << 2;
      const size_t g = rowbase + (size_t)(t0 + r) * HD + cc;
      *(float4*)&sKc[r][cc] = *(const float4*)&g_Kc[g];
      *(float4*)&sKs[r][cc] = *(const float4*)&g_Ks[g];
      *(float4*)&sV[r][cc] = *(const float4*)&g_V[g];
    }
    __syncthreads();
#pragma unroll 4
    for (int t = 0; t < 32; ++t) {
      float kc[4], ks[4], v[4];
#pragma unroll
      for (int i = 0; i < 4; ++i) {
        kc[i] = sKc[t][ty * 4 + i];
        ks[i] = sKs[t][ty * 4 + i];
      }
#pragma unroll
      for (int j = 0; j < 4; ++j) v[j] = sV[t][tx * 4 + j];
#pragma unroll
      for (int i = 0; i < 4; ++i)
#pragma unroll
        for (int j = 0; j < 4; ++j) {
          aC[i][j] += kc[i] * v[j];
          aS[i][j] += ks[i] * v[j];
        }
      if (tx == 0) {
#pragma unroll
        for (int i = 0; i < 4; ++i) { zc[i] += kc[i]; zs[i] += ks[i]; }
      }
    }
  }

  const size_t sbse = ((size_t)bh * NCH + c) * (DHc * DHc);
#pragma unroll
  for (int i = 0; i < 4; ++i) {
    *(float4*)&g_Scos[sbse + (size_t)(ty * 4 + i) * 64 + tx * 4] =
        make_float4(aC[i][0], aC[i][1], aC[i][2], aC[i][3]);
    *(float4*)&g_Ssin[sbse + (size_t)(ty * 4 + i) * 64 + tx * 4] =
        make_float4(aS[i][0], aS[i][1], aS[i][2], aS[i][3]);
  }
  if (tx == 0) {
    const size_t zb = ((size_t)bh * NCH + c) * DHc;
#pragma unroll
    for (int i = 0; i < 4; ++i) {
      g_zcos[zb + ty * 4 + i] = zc[i];
      g_zsin[zb + ty * 4 + i] = zs[i];
    }
  }
}

// ============================================================================
// Pass B: exclusive prefix over chunks
// ============================================================================
__global__ __launch_bounds__(256) void chunk_scan2() {
  const int bh = blockIdx.y;
  const int e = blockIdx.x * 256 + threadIdx.x;
  {
    const size_t base = (size_t)bh * NCH * (DHc * DHc) + e;
    float ac = 0.f, as2 = 0.f;
#pragma unroll 1
    for (int c = 0; c < NCH; ++c) {
      const size_t idx = base + (size_t)c * (DHc * DHc);
      const float tc = g_Scos[idx], ts = g_Ssin[idx];
      g_Scos[idx] = ac;
      g_Ssin[idx] = as2;
      ac += tc;
      as2 += ts;
    }
  }
  if (blockIdx.x == 0 && threadIdx.x < DHc) {
    const size_t zb = (size_t)bh * NCH * DHc + threadIdx.x;
    float ac = 0.f, as2 = 0.f;
#pragma unroll 1
    for (int c = 0; c < NCH; ++c) {
      const size_t idx = zb + (size_t)c * DHc;
      const float tc = g_zcos[idx], ts = g_zsin[idx];
      g_zcos[idx] = ac;
      g_zsin[idx] = as2;
      ac += tc;
      as2 += ts;
    }
  }
}

// ============================================================================
// Pass C: per-chunk output, 512 threads
// ============================================================================
constexpr int SQ_LD = 65;
constexpr int SA_LD = 129;
constexpr int OFF_QP = 0;
constexpr int OFF_KP = 128 * SQ_LD;
constexpr int OFF_A = 2 * 128 * SQ_LD;
constexpr int OFF_SC = OFF_A + CH * SA_LD;
constexpr int OFF_SS = OFF_SC + DHc * DHc;
constexpr int OFF_ZC = OFF_SS + DHc * DHc;
constexpr int OFF_ZS = OFF_ZC + DHc;
constexpr int OFF_TC = OFF_ZS + DHc;
constexpr int OFF_TS = OFF_TC + CH;
constexpr int SMEM_FLOATS = OFF_TS + CH;

__global__ __launch_bounds__(512, 1) void attn_out() {
  extern __shared__ __align__(16) float sm[];
  const int blk = blockIdx.x;
  const int c = blk & (NCH - 1);
  const int bh = blk >> 5;
  const int b = bh >> 4, h = bh & 15;
  const int tid = threadIdx.x;

  float* sQp = sm + OFF_QP;
  float* sKp = sm + OFF_KP;
  float* sA = sm + OFF_A;
  float* sSc = sm + OFF_SC;
  float* sSs = sm + OFF_SS;
  float* szc = sm + OFF_ZC;
  float* szs = sm + OFF_ZS;
  float* strc = sm + OFF_TC;
  float* strs = sm + OFF_TS;
  float* sV = sKp;

  const size_t gbase = ((size_t)b * Tc + (size_t)c * CH) * HD + h * DHc;

  if (tid < CH) {
    float sn, cs;
    sincosf(ANGC * (float)(c * CH + tid), &sn, &cs);
    strc[tid] = cs;
    strs[tid] = sn;
  }
  for (int l = tid; l < CH * 16; l += 512) {
    const int r = l >> 4, cc = (l & 15) << 2;
    const size_t g = gbase + (size_t)r * HD + cc;
    float4 vq = *(const float4*)&g_Qp[g];
    float4 vk = *(const float4*)&g_Kp[g];
    float* pp;
    pp = &sQp[r * SQ_LD + cc]; pp[0]=vq.x; pp[1]=vq.y; pp[2]=vq.z; pp[3]=vq.w;
    pp = &sKp[r * SQ_LD + cc]; pp[0]=vk.x; pp[1]=vk.y; pp[2]=vk.z; pp[3]=vk.w;
  }
  __syncthreads();

  if (tid < 272) {
    const int tau = tid;
    int i = (int)((sqrtf(4.f * (float)tau + 1.f) - 1.f) * 0.5f);
    while ((i + 1) * (i + 2) <= tau) ++i;
    while (i * (i + 1) > tau) --i;
    const int j = tau - i * (i + 1);
    const int t0 = i * 8, s0 = j * 4;
    float a[8][4] = {};
#pragma unroll 2
    for (int d = 0; d < DHc; ++d) {
      float qp[8], kp[4];
#pragma unroll
      for (int r = 0; r < 8; ++r) qp[r] = sQp[(t0 + r) * SQ_LD + d];
#pragma unroll
      for (int cc = 0; cc < 4; ++cc) kp[cc] = sKp[(s0 + cc) * SQ_LD + d];
#pragma unroll
      for (int r = 0; r < 8; ++r)
#pragma unroll
        for (int cc = 0; cc < 4; ++cc) a[r][cc] += qp[r] * kp[cc];
    }
    float cs4[4], ss4[4];
#pragma unroll
    for (int cc = 0; cc < 4; ++cc) {
      cs4[cc] = strc[s0 + cc];
      ss4[cc] = strs[s0 + cc];
    }
#pragma unroll
    for (int r = 0; r < 8; ++r) {
      const float ct = strc[t0 + r], st = strs[t0 + r];
#pragma unroll
      for (int cc = 0; cc < 4; ++cc)
        sA[(t0 + r) * SA_LD + s0 + cc] =
            (s0 + cc <= t0 + r) ? (ct * cs4[cc] + st * ss4[cc]) * a[r][cc]
                                : 0.f;
    }
  }
  __syncthreads();

  for (int l = tid; l < CH * 16; l += 512) {
    const int r = l >> 4, cc = (l & 15) << 2;
    *(float4*)&sV[r * 64 + cc] =
        *(const float4*)&g_V[gbase + (size_t)r * HD + cc];
  }
  const size_t sbse = ((size_t)bh * NCH + c) * (DHc * DHc);
  for (int l = tid; l < 64 * 16; l += 512) {
    const int r = l >> 4, cc = (l & 15) << 2;
    *(float4*)&sSc[r * 64 + cc] = *(const float4*)&g_Scos[sbse + r * 64 + cc];
    *(float4*)&sSs[r * 64 + cc] = *(const float4*)&g_Ssin[sbse + r * 64 + cc];
  }
  if (tid < DHc) {
    const size_t zb = ((size_t)bh * NCH + c) * DHc;
    szc[tid] = g_zcos[zb + tid];
    szs[tid] = g_zsin[zb + tid];
  }
  __syncthreads();

  const int tx = tid & 15, ty = tid >> 4;
  const int n0 = tx * 4;
  const int rA = ty * 2;
  const int rB = 126 - ty * 2;
  int rowid[4] = {rA, rA + 1, rB, rB + 1};
  float o[4][4] = {};
  float rs[4] = {};
#pragma unroll 1
  for (int s = 0; s <= rA + 1; ++s) {
    const float4 v4 = *(const float4*)&sV[s * 64 + n0];
#pragma unroll
    for (int i = 0; i < 2; ++i) {
      const float av = sA[(rA + i) * SA_LD + s];
      o[i][0] += av * v4.x;
      o[i][1] += av * v4.y;
      o[i][2] += av * v4.z;
      o[i][3] += av * v4.w;
      rs[i] += av;
    }
  }
#pragma unroll 1
  for (int s = 0; s <= rB + 1; ++s) {
    const float4 v4 = *(const float4*)&sV[s * 64 + n0];
#pragma unroll
    for (int i = 0; i < 2; ++i) {
      const float av = sA[(rB + i) * SA_LD + s];
      o[2 + i][0] += av * v4.x;
      o[2 + i][1] += av * v4.y;
      o[2 + i][2] += av * v4.z;
      o[2 + i][3] += av * v4.w;
      rs[2 + i] += av;
    }
  }

  float uc[4][4] = {}, us[4][4] = {}, dc[4] = {}, ds[4] = {};
#pragma unroll 2
  for (int d = 0; d < DHc; ++d) {
    const float4 sc4 = *(const float4*)&sSc[d * 64 + n0];
    const float4 ss4 = *(const float4*)&sSs[d * 64 + n0];
    const float zcv = szc[d], zsv = szs[d];
#pragma unroll
    for (int i = 0; i < 4; ++i) {
      const float qp = sQp[rowid[i] * SQ_LD + d];
      uc[i][0] += qp * sc4.x;
      uc[i][1] += qp * sc4.y;
      uc[i][2] += qp * sc4.z;
      uc[i][3] += qp * sc4.w;
      us[i][0] += qp * ss4.x;
      us[i][1] += qp * ss4.y;
      us[i][2] += qp * ss4.z;
      us[i][3] += qp * ss4.w;
      dc[i] += qp * zcv;
      ds[i] += qp * zsv;
    }
  }

#pragma unroll
  for (int i = 0; i < 4; ++i) {
    const int t = rowid[i];
    const float ct = strc[t], st = strs[t];
    const float den = fmaxf(rs[i] + ct * dc[i] + st * ds[i], 1e-6f);
    const float inv = 1.0f / den;
    __half hv[4];
#pragma unroll
    for (int e = 0; e < 4; ++e)
      hv[e] = __float2half((o[i][e] + ct * uc[i][e] + st * us[i][e]) * inv);
    *(uint2*)&g_a16[gbase + (size_t)t * HD + n0] = *(uint2*)hv;
  }
}

}  // namespace cf

extern "C" void kernel_launch(void* const* d_in, const int* in_sizes, int n_in,
                              void* d_out, int out_size) {
  using namespace cf;
  const float* x = (const float*)d_in[0];
  const float* Wq = (const float*)d_in[1];
  const float* bq = (const float*)d_in[2];
  const float* Wk = (const float*)d_in[3];
  const float* bk = (const float*)d_in[4];
  const float* Wv = (const float*)d_in[5];
  const float* bv = (const float*)d_in[6];
  const float* Wo = (const float*)d_in[7];
  const float* bo = (const float*)d_in[8];
  float* out = (float*)d_out;

  cudaFuncSetAttribute(gemm_1p<1>, cudaFuncAttributeMaxDynamicSharedMemorySize,
                       GEMM_SMEM_1P);
  cudaFuncSetAttribute(gemm_1p<0>, cudaFuncAttributeMaxDynamicSharedMemorySize,
                       GEMM_SMEM_1P);
  cudaFuncSetAttribute(attn_out, cudaFuncAttributeMaxDynamicSharedMemorySize,
                       (int)(SMEM_FLOATS * sizeof(float)));

  // 1) conversions
  conv_x<<<Mrows * DM / 4 / 256, 256>>>(x);
  dim3 tg(32, 32, 4), tb(32, 8);
  tconv<<<tg, tb>>>(Wq, Wk, Wv, Wo);

  // 2) fused QKV projection (fp16, 1 pass each)
  dim3 gq(HD / 128, Mrows / 128, 3);
  gemm_1p<1><<<gq, 256, GEMM_SMEM_1P>>>(bq, bk, bv, nullptr);

  // 3) attention
  chunk_stats<<<BHc * NCH, 256>>>();
  chunk_scan2<<<dim3(16, 32), 256>>>();
  attn_out<<<BHc * NCH, 512, SMEM_FLOATS * sizeof(float)>>>();

  // 4) output projection (fp16, 1 pass)
  dim3 go(HD / 128, Mrows / 128);
  gemm_1p<0><<<go, 256, GEMM_SMEM_1P>>>(bo, nullptr, nullptr, out);
}

// round 11
// speedup vs baseline: 3.7015x; 1.1679x over previous
#include <cuda_runtime.h>
#include <cuda_fp16.h>
#include <math.h>
#include <stdint.h>

// ============================================================================
// CosFormer attention (sm_103 base; legacy HMMA mma.sync).
//  - ALL GEMMs: single-pass fp16.
//  - chunk_stats: now fp16 tensor-core batched GEMM (S = K16^T V16) using
//    ldmatrix.x4.trans on [t][dh]-major smem (no transpose copy).
//  - Attention combine: fp32, trig identity A[t,s]=cos(dth)*(Qp.Kp).
// ============================================================================

namespace cf {

constexpr int Bc = 2, Tc = 4096, Hc = 16, DHc = 64;
constexpr int DM = 1024, HD = 1024;
constexpr int Mrows = Bc * Tc;            // 8192
constexpr int CH = 128, NCH = Tc / CH;    // 128, 32
constexpr int BHc = Bc * Hc;              // 32
constexpr float ANGC = 3.14159265358979323846f / (2.0f * (float)Tc);

constexpr int KDIM = 1024;
constexpr int KT = 64;
constexpr int NKT = KDIM / KT;            // 16

// ---- fp32 scratch ----
__device__ __align__(16) float g_Qp[(size_t)Mrows * HD];
__device__ __align__(16) float g_Kp[(size_t)Mrows * HD];
__device__ __align__(16) float g_V [(size_t)Mrows * HD];
__device__ __align__(16) float g_Scos[(size_t)BHc * NCH * DHc * DHc];
__device__ __align__(16) float g_Ssin[(size_t)BHc * NCH * DHc * DHc];
__device__ __align__(16) float g_zcos[(size_t)BHc * NCH * DHc];
__device__ __align__(16) float g_zsin[(size_t)BHc * NCH * DHc];

// ---- fp16 operands ----
__device__ __align__(16) __half g_x16[(size_t)Mrows * DM];
__device__ __align__(16) __half g_Wq16[(size_t)HD * DM];
__device__ __align__(16) __half g_Wk16[(size_t)HD * DM];
__device__ __align__(16) __half g_Wv16[(size_t)HD * DM];
__device__ __align__(16) __half g_Wo16[(size_t)DM * HD];
__device__ __align__(16) __half g_a16[(size_t)Mrows * HD];
__device__ __align__(16) __half g_Kc16[(size_t)Mrows * HD];
__device__ __align__(16) __half g_Ks16[(size_t)Mrows * HD];
__device__ __align__(16) __half g_V16[(size_t)Mrows * HD];

// ============================================================================
// helpers
// ============================================================================
__device__ __forceinline__ uint32_t smem_u32(const void* p) {
  uint32_t a;
  asm("{ .reg .u64 t; cvta.to.shared.u64 t, %1; cvt.u32.u64 %0, t; }"
      : "=r"(a) : "l"(p));
  return a;
}
__device__ __forceinline__ void ldsm4(uint32_t* r, uint32_t addr) {
  asm volatile(
      "ldmatrix.sync.aligned.m8n8.x4.shared.b16 {%0,%1,%2,%3}, [%4];"
      : "=r"(r[0]), "=r"(r[1]), "=r"(r[2]), "=r"(r[3]) : "r"(addr));
}
__device__ __forceinline__ void ldsm4t(uint32_t* r, uint32_t addr) {
  asm volatile(
      "ldmatrix.sync.aligned.m8n8.x4.trans.shared.b16 {%0,%1,%2,%3}, [%4];"
      : "=r"(r[0]), "=r"(r[1]), "=r"(r[2]), "=r"(r[3]) : "r"(addr));
}
__device__ __forceinline__ void mma_hf(float* d, const uint32_t* a,
                                       const uint32_t* b) {
  asm volatile(
      "mma.sync.aligned.m16n8k16.row.col.f32.f16.f16.f32 "
      "{%0,%1,%2,%3}, {%4,%5,%6,%7}, {%8,%9}, {%0,%1,%2,%3};"
      : "+f"(d[0]), "+f"(d[1]), "+f"(d[2]), "+f"(d[3])
      : "r"(a[0]), "r"(a[1]), "r"(a[2]), "r"(a[3]), "r"(b[0]), "r"(b[1]));
}
__device__ __forceinline__ void cpasync16(uint32_t dst, const void* src) {
  asm volatile("cp.async.cg.shared.global [%0], [%1], 16;"
               ::"r"(dst), "l"(src) : "memory");
}
__device__ __forceinline__ void cp_commit() {
  asm volatile("cp.async.commit_group;" ::: "memory");
}
template <int N>
__device__ __forceinline__ void cp_wait() {
  asm volatile("cp.async.wait_group %0;" ::"n"(N) : "memory");
}

// ============================================================================
// Conversions
// ============================================================================
__global__ __launch_bounds__(256) void conv_x(const float* __restrict__ in) {
  int i = blockIdx.x * 256 + threadIdx.x;
  float4 v = *(const float4*)(in + (size_t)i * 4);
  __half h[4] = {__float2half(v.x), __float2half(v.y), __float2half(v.z),
                 __float2half(v.w)};
  *(uint2*)(g_x16 + (size_t)i * 4) = *(uint2*)h;
}

__global__ __launch_bounds__(256) void tconv(const float* __restrict__ Wq,
                                             const float* __restrict__ Wk,
                                             const float* __restrict__ Wv,
                                             const float* __restrict__ Wo) {
  const int w = blockIdx.z;
  const float* W = (w == 0) ? Wq : (w == 1) ? Wk : (w == 2) ? Wv : Wo;
  __half* T = (w == 0) ? g_Wq16 : (w == 1) ? g_Wk16 : (w == 2) ? g_Wv16
                                                               : g_Wo16;
  __shared__ float tile[32][33];
  const int bx = blockIdx.x * 32, by = blockIdx.y * 32;
  const int tx = threadIdx.x, ty = threadIdx.y;
#pragma unroll
  for (int j = 0; j < 4; ++j)
    tile[ty + j * 8][tx] = W[(size_t)(by + ty + j * 8) * 1024 + bx + tx];
  __syncthreads();
#pragma unroll
  for (int j = 0; j < 4; ++j)
    T[(size_t)(bx + ty + j * 8) * 1024 + by + tx] =
        __float2half(tile[tx][ty + j * 8]);
}

// ============================================================================
// Single-pass fp16 GEMM. FUSED=1: QKV via grid.z.  FUSED=0: out proj.
// ============================================================================
constexpr int PIECE_BYTES = 128 * KT * 2;         // 16384
constexpr int STAGE_1P = 2 * PIECE_BYTES;         // 32768
constexpr int GEMM_SMEM_1P = 2 * STAGE_1P;        // 65536

template <int FUSED>
__global__ __launch_bounds__(256, 1) void gemm_1p(
    const float* __restrict__ bias_q, const float* __restrict__ bias_k,
    const float* __restrict__ bias_v, float* __restrict__ outO) {
  extern __shared__ __align__(16) char smem[];
  const uint32_t sb = smem_u32(smem);
  const int tid = threadIdx.x, wid = tid >> 5, lane = tid & 31;
  const int wm = wid >> 2, wn = wid & 3;
  const int bm = blockIdx.y, bn = blockIdx.x;
  const int w = FUSED ? (int)blockIdx.z : 3;  // 0=Q 1=K 2=V 3=O

  const __half* A = FUSED ? g_x16 : g_a16;
  const __half* Bm = (w == 0) ? g_Wq16 : (w == 1) ? g_Wk16
                       : (w == 2) ? g_Wv16 : g_Wo16;
  const float* bias = FUSED
                          ? ((w == 0) ? bias_q : (w == 1) ? bias_k : bias_v)
                          : bias_q;

  const int p = tid >> 7, q = tid & 127;
  const __half* psrc =
      ((p == 0) ? A + (size_t)bm * 128 * KDIM : Bm + (size_t)bn * 128 * KDIM) +
      (size_t)(q >> 3) * KDIM + (q & 7) * 8;
  const uint32_t loff0 = (uint32_t)((q >> 3) * 128 + (q & 7) * 16);

  auto issue = [&](int kt) {
    const int buf = kt & 1;
    const __half* g = psrc + kt * KT;
    const uint32_t dstbase = sb + buf * STAGE_1P + p * PIECE_BYTES;
#pragma unroll
    for (int j = 0; j < 8; ++j) {
      const uint32_t off = loff0 + j * 2048;  // 16 rows * 128B
      const uint32_t swz = off ^ ((off >> 3) & 0x70);
      cpasync16(dstbase + swz, g + (size_t)j * 16 * KDIM);
    }
    cp_commit();
  };

  float acc[4][4][4];
#pragma unroll
  for (int i = 0; i < 4; ++i)
#pragma unroll
    for (int j = 0; j < 4; ++j)
#pragma unroll
      for (int k = 0; k < 4; ++k) acc[i][j][k] = 0.f;

  issue(0);
#pragma unroll 1
  for (int kt = 0; kt < NKT; ++kt) {
    if (kt + 1 < NKT) {
      issue(kt + 1);
      cp_wait<1>();
    } else {
      cp_wait<0>();
    }
    __syncthreads();
    const uint32_t base = sb + (kt & 1) * STAGE_1P;
#pragma unroll
    for (int ks = 0; ks < 4; ++ks) {
      const int k0 = ks * 16;
      uint32_t a[4][4], bb[2][4];
#pragma unroll
      for (int mt = 0; mt < 4; ++mt) {
        const uint32_t row = wm * 64 + mt * 16 + (lane & 15);
        const uint32_t off = row * 128 + k0 * 2 + ((lane >> 4) << 4);
        const uint32_t swz = off ^ ((off >> 3) & 0x70);
        ldsm4(a[mt], base + swz);
      }
#pragma unroll
      for (int nt2 = 0; nt2 < 2; ++nt2) {
        const uint32_t row =
            wn * 32 + nt2 * 16 + (lane & 7) + ((lane >> 4) << 3);
        const uint32_t off = row * 128 + k0 * 2 + (((lane >> 3) & 1) << 4);
        const uint32_t swz = off ^ ((off >> 3) & 0x70);
        ldsm4(bb[nt2], base + PIECE_BYTES + swz);
      }
#pragma unroll
      for (int mt = 0; mt < 4; ++mt)
#pragma unroll
        for (int nt = 0; nt < 4; ++nt)
          mma_hf(acc[mt][nt], a[mt], &bb[nt >> 1][(nt & 1) * 2]);
    }
    __syncthreads();
  }

  const int g = lane >> 2, t2 = (lane & 3) * 2;
#pragma unroll
  for (int mt = 0; mt < 4; ++mt) {
    const int r0 = bm * 128 + wm * 64 + mt * 16 + g;
    const int r1 = r0 + 8;
    float sn0 = 0.f, cs0 = 0.f, sn1 = 0.f, cs1 = 0.f;
    if (FUSED && w == 1) {
      sincosf(ANGC * (float)(r0 & (Tc - 1)), &sn0, &cs0);
      sincosf(ANGC * (float)(r1 & (Tc - 1)), &sn1, &cs1);
    }
#pragma unroll
    for (int nt = 0; nt < 4; ++nt) {
      const int col = bn * 128 + wn * 32 + nt * 8 + t2;
      const float b0 = __ldg(&bias[col]), b1 = __ldg(&bias[col + 1]);
      const float v00 = acc[mt][nt][0] + b0, v01 = acc[mt][nt][1] + b1;
      const float v10 = acc[mt][nt][2] + b0, v11 = acc[mt][nt][3] + b1;
      if (!FUSED) {
        *(float2*)&outO[(size_t)r0 * DM + col] = make_float2(v00, v01);
        *(float2*)&outO[(size_t)r1 * DM + col] = make_float2(v10, v11);
      } else if (w == 2) {
        *(float2*)&g_V[(size_t)r0 * HD + col] = make_float2(v00, v01);
        *(float2*)&g_V[(size_t)r1 * HD + col] = make_float2(v10, v11);
        *(uint32_t*)&g_V16[(size_t)r0 * HD + col] =
            __half2_raw(__floats2half2_rn(v00, v01)).x |
            ((uint32_t)__half2_raw(__floats2half2_rn(v00, v01)).y << 16);
        *(uint32_t*)&g_V16[(size_t)r1 * HD + col] =
            __half2_raw(__floats2half2_rn(v10, v11)).x |
            ((uint32_t)__half2_raw(__floats2half2_rn(v10, v11)).y << 16);
      } else if (w == 0) {
        *(float2*)&g_Qp[(size_t)r0 * HD + col] =
            make_float2(fmaxf(v00, 0.f), fmaxf(v01, 0.f));
        *(float2*)&g_Qp[(size_t)r1 * HD + col] =
            make_float2(fmaxf(v10, 0.f), fmaxf(v11, 0.f));
      } else {
        const float a00 = fmaxf(v00, 0.f), a01 = fmaxf(v01, 0.f);
        const float a10 = fmaxf(v10, 0.f), a11 = fmaxf(v11, 0.f);
        *(float2*)&g_Kp[(size_t)r0 * HD + col] = make_float2(a00, a01);
        *(float2*)&g_Kp[(size_t)r1 * HD + col] = make_float2(a10, a11);
        __half2 kc0 = __floats2half2_rn(a00 * cs0, a01 * cs0);
        __half2 kc1 = __floats2half2_rn(a10 * cs1, a11 * cs1);
        __half2 ks0 = __floats2half2_rn(a00 * sn0, a01 * sn0);
        __half2 ks1 = __floats2half2_rn(a10 * sn1, a11 * sn1);
        *(__half2*)&g_Kc16[(size_t)r0 * HD + col] = kc0;
        *(__half2*)&g_Kc16[(size_t)r1 * HD + col] = kc1;
        *(__half2*)&g_Ks16[(size_t)r0 * HD + col] = ks0;
        *(__half2*)&g_Ks16[(size_t)r1 * HD + col] = ks1;
      }
    }
  }
}

// ============================================================================
// Pass A (tensor cores): per-chunk states S_cos = Kc16^T V16, S_sin = Ks16^T
// V16 (64x64, K=128), z = column sums.  SMEM keeps [t][dh] layout (144B rows);
// ldmatrix.x4.trans supplies transposed fragments.  grid 1024, block 128.
// ============================================================================
constexpr int CS_LDH = 72;                       // halves per padded row
constexpr int CS_OP = 128 * CS_LDH * 2;          // 18432 B per operand
constexpr int CS_SMEM = 3 * CS_OP;               // 55296 B

__global__ __launch_bounds__(128, 1) void chunk_stats16() {
  extern __shared__ __align__(16) char smem[];
  const uint32_t sb = smem_u32(smem);
  const int blk = blockIdx.x;
  const int c = blk & (NCH - 1);
  const int bh = blk >> 5;
  const int b = bh >> 4, h = bh & 15;
  const int tid = threadIdx.x, wid = tid >> 5, lane = tid & 31;

  // ---- load 3 operands (coalesced, layout-preserving) ----
  const size_t gb16 = ((size_t)b * Tc + (size_t)c * CH) * HD + h * DHc;
  {
    const int r = tid >> 3, cb = tid & 7;
#pragma unroll
    for (int op = 0; op < 3; ++op) {
      const __half* src =
          ((op == 0) ? g_Kc16 : (op == 1) ? g_Ks16 : g_V16) + gb16;
#pragma unroll
      for (int j = 0; j < 8; ++j) {
        const int row = r + 16 * j;
        cpasync16(sb + op * CS_OP + (uint32_t)(row * CS_LDH + cb * 8) * 2,
                  src + (size_t)row * HD + cb * 8);
      }
    }
    cp_commit();
    cp_wait<0>();
  }
  __syncthreads();

  // ---- z vectors: column sums (tid -> (vec, dh)) ----
  {
    const int vec = tid >> 6, d = tid & 63;
    const __half* sK = (const __half*)(smem + vec * CS_OP);
    float z = 0.f;
#pragma unroll 4
    for (int t = 0; t < CH; ++t) z += __half2float(sK[t * CS_LDH + d]);
    const size_t zb = ((size_t)bh * NCH + c) * DHc;
    ((vec == 0) ? g_zcos : g_zsin)[zb + d] = z;
  }

  // ---- tensor-core S: warp w handles m-rows [16w, 16w+16) ----
  const int m0 = wid * 16;
  float accC[8][4], accS[8][4];
#pragma unroll
  for (int i = 0; i < 8; ++i)
#pragma unroll
    for (int j = 0; j < 4; ++j) {
      accC[i][j] = 0.f;
      accS[i][j] = 0.f;
    }

  const uint32_t bKc = sb, bKs = sb + CS_OP, bV = sb + 2 * CS_OP;
#pragma unroll 1
  for (int ks = 0; ks < 8; ++ks) {
    const int k0 = ks * 16;
    // A fragment (trans): rows k, cols m
    const uint32_t akk = (uint32_t)(k0 + (lane & 7) + ((lane >> 4) << 3));
    const uint32_t amm = (uint32_t)(m0 + (((lane >> 3) & 1) << 3));
    const uint32_t aoff = akk * (CS_LDH * 2) + amm * 2;
    uint32_t aC[4], aS[4];
    ldsm4t(aC, bKc + aoff);
    ldsm4t(aS, bKs + aoff);
    // B fragments (trans): rows k, cols n; x4 covers 16 n
    const uint32_t bkk = (uint32_t)(k0 + (lane & 7) + (((lane >> 3) & 1) << 3));
#pragma unroll
    for (int n4 = 0; n4 < 4; ++n4) {
      const uint32_t bnn = (uint32_t)(n4 * 16 + ((lane >> 4) << 3));
      uint32_t bb[4];
      ldsm4t(bb, bV + bkk * (CS_LDH * 2) + bnn * 2);
      mma_hf(accC[2 * n4], aC, &bb[0]);
      mma_hf(accC[2 * n4 + 1], aC, &bb[2]);
      mma_hf(accS[2 * n4], aS, &bb[0]);
      mma_hf(accS[2 * n4 + 1], aS, &bb[2]);
    }
  }

  // ---- epilogue ----
  const size_t sbse = ((size_t)bh * NCH + c) * (DHc * DHc);
  const int r = lane >> 2, c2 = (lane & 3) * 2;
#pragma unroll
  for (int nt = 0; nt < 8; ++nt) {
    const int col = nt * 8 + c2;
    *(float2*)&g_Scos[sbse + (size_t)(m0 + r) * 64 + col] =
        make_float2(accC[nt][0], accC[nt][1]);
    *(float2*)&g_Scos[sbse + (size_t)(m0 + r + 8) * 64 + col] =
        make_float2(accC[nt][2], accC[nt][3]);
    *(float2*)&g_Ssin[sbse + (size_t)(m0 + r) * 64 + col] =
        make_float2(accS[nt][0], accS[nt][1]);
    *(float2*)&g_Ssin[sbse + (size_t)(m0 + r + 8) * 64 + col] =
        make_float2(accS[nt][2], accS[nt][3]);
  }
}

// ============================================================================
// Pass B: exclusive prefix over chunks
// ============================================================================
__global__ __launch_bounds__(256) void chunk_scan2() {
  const int bh = blockIdx.y;
  const int e = blockIdx.x * 256 + threadIdx.x;
  {
    const size_t base = (size_t)bh * NCH * (DHc * DHc) + e;
    float ac = 0.f, as2 = 0.f;
#pragma unroll 1
    for (int c = 0; c < NCH; ++c) {
      const size_t idx = base + (size_t)c * (DHc * DHc);
      const float tc = g_Scos[idx], ts = g_Ssin[idx];
      g_Scos[idx] = ac;
      g_Ssin[idx] = as2;
      ac += tc;
      as2 += ts;
    }
  }
  if (blockIdx.x == 0 && threadIdx.x < DHc) {
    const size_t zb = (size_t)bh * NCH * DHc + threadIdx.x;
    float ac = 0.f, as2 = 0.f;
#pragma unroll 1
    for (int c = 0; c < NCH; ++c) {
      const size_t idx = zb + (size_t)c * DHc;
      const float tc = g_zcos[idx], ts = g_zsin[idx];
      g_zcos[idx] = ac;
      g_zsin[idx] = as2;
      ac += tc;
      as2 += ts;
    }
  }
}

// ============================================================================
// Pass C: per-chunk output, 512 threads
// ============================================================================
constexpr int SQ_LD = 65;
constexpr int SA_LD = 129;
constexpr int OFF_QP = 0;
constexpr int OFF_KP = 128 * SQ_LD;
constexpr int OFF_A = 2 * 128 * SQ_LD;
constexpr int OFF_SC = OFF_A + CH * SA_LD;
constexpr int OFF_SS = OFF_SC + DHc * DHc;
constexpr int OFF_ZC = OFF_SS + DHc * DHc;
constexpr int OFF_ZS = OFF_ZC + DHc;
constexpr int OFF_TC = OFF_ZS + DHc;
constexpr int OFF_TS = OFF_TC + CH;
constexpr int SMEM_FLOATS = OFF_TS + CH;

__global__ __launch_bounds__(512, 1) void attn_out() {
  extern __shared__ __align__(16) float sm[];
  const int blk = blockIdx.x;
  const int c = blk & (NCH - 1);
  const int bh = blk >> 5;
  const int b = bh >> 4, h = bh & 15;
  const int tid = threadIdx.x;

  float* sQp = sm + OFF_QP;
  float* sKp = sm + OFF_KP;
  float* sA = sm + OFF_A;
  float* sSc = sm + OFF_SC;
  float* sSs = sm + OFF_SS;
  float* szc = sm + OFF_ZC;
  float* szs = sm + OFF_ZS;
  float* strc = sm + OFF_TC;
  float* strs = sm + OFF_TS;
  float* sV = sKp;

  const size_t gbase = ((size_t)b * Tc + (size_t)c * CH) * HD + h * DHc;

  if (tid < CH) {
    float sn, cs;
    sincosf(ANGC * (float)(c * CH + tid), &sn, &cs);
    strc[tid] = cs;
    strs[tid] = sn;
  }
  for (int l = tid; l < CH * 16; l += 512) {
    const int r = l >> 4, cc = (l & 15) << 2;
    const size_t g = gbase + (size_t)r * HD + cc;
    float4 vq = *(const float4*)&g_Qp[g];
    float4 vk = *(const float4*)&g_Kp[g];
    float* pp;
    pp = &sQp[r * SQ_LD + cc]; pp[0]=vq.x; pp[1]=vq.y; pp[2]=vq.z; pp[3]=vq.w;
    pp = &sKp[r * SQ_LD + cc]; pp[0]=vk.x; pp[1]=vk.y; pp[2]=vk.z; pp[3]=vk.w;
  }
  __syncthreads();

  if (tid < 272) {
    const int tau = tid;
    int i = (int)((sqrtf(4.f * (float)tau + 1.f) - 1.f) * 0.5f);
    while ((i + 1) * (i + 2) <= tau) ++i;
    while (i * (i + 1) > tau) --i;
    const int j = tau - i * (i + 1);
    const int t0 = i * 8, s0 = j * 4;
    float a[8][4] = {};
#pragma unroll 2
    for (int d = 0; d < DHc; ++d) {
      float qp[8], kp[4];
#pragma unroll
      for (int r = 0; r < 8; ++r) qp[r] = sQp[(t0 + r) * SQ_LD + d];
#pragma unroll
      for (int cc = 0; cc < 4; ++cc) kp[cc] = sKp[(s0 + cc) * SQ_LD + d];
#pragma unroll
      for (int r = 0; r < 8; ++r)
#pragma unroll
        for (int cc = 0; cc < 4; ++cc) a[r][cc] += qp[r] * kp[cc];
    }
    float cs4[4], ss4[4];
#pragma unroll
    for (int cc = 0; cc < 4; ++cc) {
      cs4[cc] = strc[s0 + cc];
      ss4[cc] = strs[s0 + cc];
    }
#pragma unroll
    for (int r = 0; r < 8; ++r) {
      const float ct = strc[t0 + r], st = strs[t0 + r];
#pragma unroll
      for (int cc = 0; cc < 4; ++cc)
        sA[(t0 + r) * SA_LD + s0 + cc] =
            (s0 + cc <= t0 + r) ? (ct * cs4[cc] + st * ss4[cc]) * a[r][cc]
                                : 0.f;
    }
  }
  __syncthreads();

  for (int l = tid; l < CH * 16; l += 512) {
    const int r = l >> 4, cc = (l & 15) << 2;
    *(float4*)&sV[r * 64 + cc] =
        *(const float4*)&g_V[gbase + (size_t)r * HD + cc];
  }
  const size_t sbse = ((size_t)bh * NCH + c) * (DHc * DHc);
  for (int l = tid; l < 64 * 16; l += 512) {
    const int r = l >> 4, cc = (l & 15) << 2;
    *(float4*)&sSc[r * 64 + cc] = *(const float4*)&g_Scos[sbse + r * 64 + cc];
    *(float4*)&sSs[r * 64 + cc] = *(const float4*)&g_Ssin[sbse + r * 64 + cc];
  }
  if (tid < DHc) {
    const size_t zb = ((size_t)bh * NCH + c) * DHc;
    szc[tid] = g_zcos[zb + tid];
    szs[tid] = g_zsin[zb + tid];
  }
  __syncthreads();

  const int tx = tid & 15, ty = tid >> 4;
  const int n0 = tx * 4;
  const int rA = ty * 2;
  const int rB = 126 - ty * 2;
  int rowid[4] = {rA, rA + 1, rB, rB + 1};
  float o[4][4] = {};
  float rs[4] = {};
#pragma unroll 1
  for (int s = 0; s <= rA + 1; ++s) {
    const float4 v4 = *(const float4*)&sV[s * 64 + n0];
#pragma unroll
    for (int i = 0; i < 2; ++i) {
      const float av = sA[(rA + i) * SA_LD + s];
      o[i][0] += av * v4.x;
      o[i][1] += av * v4.y;
      o[i][2] += av * v4.z;
      o[i][3] += av * v4.w;
      rs[i] += av;
    }
  }
#pragma unroll 1
  for (int s = 0; s <= rB + 1; ++s) {
    const float4 v4 = *(const float4*)&sV[s * 64 + n0];
#pragma unroll
    for (int i = 0; i < 2; ++i) {
      const float av = sA[(rB + i) * SA_LD + s];
      o[2 + i][0] += av * v4.x;
      o[2 + i][1] += av * v4.y;
      o[2 + i][2] += av * v4.z;
      o[2 + i][3] += av * v4.w;
      rs[2 + i] += av;
    }
  }

  float uc[4][4] = {}, us[4][4] = {}, dc[4] = {}, ds[4] = {};
#pragma unroll 2
  for (int d = 0; d < DHc; ++d) {
    const float4 sc4 = *(const float4*)&sSc[d * 64 + n0];
    const float4 ss4 = *(const float4*)&sSs[d * 64 + n0];
    const float zcv = szc[d], zsv = szs[d];
#pragma unroll
    for (int i = 0; i < 4; ++i) {
      const float qp = sQp[rowid[i] * SQ_LD + d];
      uc[i][0] += qp * sc4.x;
      uc[i][1] += qp * sc4.y;
      uc[i][2] += qp * sc4.z;
      uc[i][3] += qp * sc4.w;
      us[i][0] += qp * ss4.x;
      us[i][1] += qp * ss4.y;
      us[i][2] += qp * ss4.z;
      us[i][3] += qp * ss4.w;
      dc[i] += qp * zcv;
      ds[i] += qp * zsv;
    }
  }

#pragma unroll
  for (int i = 0; i < 4; ++i) {
    const int t = rowid[i];
    const float ct = strc[t], st = strs[t];
    const float den = fmaxf(rs[i] + ct * dc[i] + st * ds[i], 1e-6f);
    const float inv = 1.0f / den;
    __half hv[4];
#pragma unroll
    for (int e = 0; e < 4; ++e)
      hv[e] = __float2half((o[i][e] + ct * uc[i][e] + st * us[i][e]) * inv);
    *(uint2*)&g_a16[gbase + (size_t)t * HD + n0] = *(uint2*)hv;
  }
}

}  // namespace cf

extern "C" void kernel_launch(void* const* d_in, const int* in_sizes, int n_in,
                              void* d_out, int out_size) {
  using namespace cf;
  const float* x = (const float*)d_in[0];
  const float* Wq = (const float*)d_in[1];
  const float* bq = (const float*)d_in[2];
  const float* Wk = (const float*)d_in[3];
  const float* bk = (const float*)d_in[4];
  const float* Wv = (const float*)d_in[5];
  const float* bv = (const float*)d_in[6];
  const float* Wo = (const float*)d_in[7];
  const float* bo = (const float*)d_in[8];
  float* out = (float*)d_out;

  cudaFuncSetAttribute(gemm_1p<1>, cudaFuncAttributeMaxDynamicSharedMemorySize,
                       GEMM_SMEM_1P);
  cudaFuncSetAttribute(gemm_1p<0>, cudaFuncAttributeMaxDynamicSharedMemorySize,
                       GEMM_SMEM_1P);
  cudaFuncSetAttribute(chunk_stats16,
                       cudaFuncAttributeMaxDynamicSharedMemorySize, CS_SMEM);
  cudaFuncSetAttribute(attn_out, cudaFuncAttributeMaxDynamicSharedMemorySize,
                       (int)(SMEM_FLOATS * sizeof(float)));

  // 1) conversions
  conv_x<<<Mrows * DM / 4 / 256, 256>>>(x);
  dim3 tg(32, 32, 4), tb(32, 8);
  tconv<<<tg, tb>>>(Wq, Wk, Wv, Wo);

  // 2) fused QKV projection (fp16, 1 pass each)
  dim3 gq(HD / 128, Mrows / 128, 3);
  gemm_1p<1><<<gq, 256, GEMM_SMEM_1P>>>(bq, bk, bv, nullptr);

  // 3) attention
  chunk_stats16<<<BHc * NCH, 128, CS_SMEM>>>();
  chunk_scan2<<<dim3(16, 32), 256>>>();
  attn_out<<<BHc * NCH, 512, SMEM_FLOATS * sizeof(float)>>>();

  // 4) output projection (fp16, 1 pass)
  dim3 go(HD / 128, Mrows / 128);
  gemm_1p<0><<<go, 256, GEMM_SMEM_1P>>>(bo, nullptr, nullptr, out);
}

// round 12
// speedup vs baseline: 6.0458x; 1.6333x over previous
#include <cuda_runtime.h>
#include <cuda_fp16.h>
#include <math.h>
#include <stdint.h>

// ============================================================================
// CosFormer attention (sm_103 base; legacy HMMA mma.sync).
//  - ALL GEMMs fp16 single-pass, incl. attention:
//    * chunk_stats: S = K16^T V16 (tensor cores, ldmatrix.trans)
//    * attn_out: P = Qp Kp^T (HMMA, causal tile-skip, trig mask) then
//      num|den = [A|Qc|Qs] @ [V;Sc;Ss | ones;zc;zs]  (K=256 HMMA, den as
//      a 65th output column).
// ============================================================================

namespace cf {

constexpr int Bc = 2, Tc = 4096, Hc = 16, DHc = 64;
constexpr int DM = 1024, HD = 1024;
constexpr int Mrows = Bc * Tc;            // 8192
constexpr int CH = 128, NCH = Tc / CH;    // 128, 32
constexpr int BHc = Bc * Hc;              // 32
constexpr float ANGC = 3.14159265358979323846f / (2.0f * (float)Tc);

constexpr int KDIM = 1024;
constexpr int KT = 64;
constexpr int NKT = KDIM / KT;            // 16

// ---- fp32 scratch (chunk stats + z) ----
__device__ __align__(16) float g_Scos[(size_t)BHc * NCH * DHc * DHc];
__device__ __align__(16) float g_Ssin[(size_t)BHc * NCH * DHc * DHc];
__device__ __align__(16) float g_zcos[(size_t)BHc * NCH * DHc];
__device__ __align__(16) float g_zsin[(size_t)BHc * NCH * DHc];

// ---- fp16 operands ----
__device__ __align__(16) __half g_x16[(size_t)Mrows * DM];
__device__ __align__(16) __half g_Wq16[(size_t)HD * DM];
__device__ __align__(16) __half g_Wk16[(size_t)HD * DM];
__device__ __align__(16) __half g_Wv16[(size_t)HD * DM];
__device__ __align__(16) __half g_Wo16[(size_t)DM * HD];
__device__ __align__(16) __half g_a16[(size_t)Mrows * HD];
__device__ __align__(16) __half g_Qp16[(size_t)Mrows * HD];
__device__ __align__(16) __half g_Kp16[(size_t)Mrows * HD];
__device__ __align__(16) __half g_Kc16[(size_t)Mrows * HD];
__device__ __align__(16) __half g_Ks16[(size_t)Mrows * HD];
__device__ __align__(16) __half g_V16[(size_t)Mrows * HD];
__device__ __align__(16) __half g_Sc16[(size_t)BHc * NCH * DHc * DHc];
__device__ __align__(16) __half g_Ss16[(size_t)BHc * NCH * DHc * DHc];

// ============================================================================
// helpers
// ============================================================================
__device__ __forceinline__ uint32_t smem_u32(const void* p) {
  uint32_t a;
  asm("{ .reg .u64 t; cvta.to.shared.u64 t, %1; cvt.u32.u64 %0, t; }"
      : "=r"(a) : "l"(p));
  return a;
}
__device__ __forceinline__ void ldsm4(uint32_t* r, uint32_t addr) {
  asm volatile(
      "ldmatrix.sync.aligned.m8n8.x4.shared.b16 {%0,%1,%2,%3}, [%4];"
      : "=r"(r[0]), "=r"(r[1]), "=r"(r[2]), "=r"(r[3]) : "r"(addr));
}
__device__ __forceinline__ void ldsm4t(uint32_t* r, uint32_t addr) {
  asm volatile(
      "ldmatrix.sync.aligned.m8n8.x4.trans.shared.b16 {%0,%1,%2,%3}, [%4];"
      : "=r"(r[0]), "=r"(r[1]), "=r"(r[2]), "=r"(r[3]) : "r"(addr));
}
__device__ __forceinline__ void mma_hf(float* d, const uint32_t* a,
                                       const uint32_t* b) {
  asm volatile(
      "mma.sync.aligned.m16n8k16.row.col.f32.f16.f16.f32 "
      "{%0,%1,%2,%3}, {%4,%5,%6,%7}, {%8,%9}, {%0,%1,%2,%3};"
      : "+f"(d[0]), "+f"(d[1]), "+f"(d[2]), "+f"(d[3])
      : "r"(a[0]), "r"(a[1]), "r"(a[2]), "r"(a[3]), "r"(b[0]), "r"(b[1]));
}
__device__ __forceinline__ void cpasync16(uint32_t dst, const void* src) {
  asm volatile("cp.async.cg.shared.global [%0], [%1], 16;"
               ::"r"(dst), "l"(src) : "memory");
}
__device__ __forceinline__ void cp_commit() {
  asm volatile("cp.async.commit_group;" ::: "memory");
}
template <int N>
__device__ __forceinline__ void cp_wait() {
  asm volatile("cp.async.wait_group %0;" ::"n"(N) : "memory");
}

// ============================================================================
// Conversions
// ============================================================================
__global__ __launch_bounds__(256) void conv_x(const float* __restrict__ in) {
  int i = blockIdx.x * 256 + threadIdx.x;
  float4 v = *(const float4*)(in + (size_t)i * 4);
  __half h[4] = {__float2half(v.x), __float2half(v.y), __float2half(v.z),
                 __float2half(v.w)};
  *(uint2*)(g_x16 + (size_t)i * 4) = *(uint2*)h;
}

__global__ __launch_bounds__(256) void tconv(const float* __restrict__ Wq,
                                             const float* __restrict__ Wk,
                                             const float* __restrict__ Wv,
                                             const float* __restrict__ Wo) {
  const int w = blockIdx.z;
  const float* W = (w == 0) ? Wq : (w == 1) ? Wk : (w == 2) ? Wv : Wo;
  __half* T = (w == 0) ? g_Wq16 : (w == 1) ? g_Wk16 : (w == 2) ? g_Wv16
                                                               : g_Wo16;
  __shared__ float tile[32][33];
  const int bx = blockIdx.x * 32, by = blockIdx.y * 32;
  const int tx = threadIdx.x, ty = threadIdx.y;
#pragma unroll
  for (int j = 0; j < 4; ++j)
    tile[ty + j * 8][tx] = W[(size_t)(by + ty + j * 8) * 1024 + bx + tx];
  __syncthreads();
#pragma unroll
  for (int j = 0; j < 4; ++j)
    T[(size_t)(bx + ty + j * 8) * 1024 + by + tx] =
        __float2half(tile[tx][ty + j * 8]);
}

// ============================================================================
// Single-pass fp16 GEMM. FUSED=1: QKV via grid.z (fp16-only epilogue).
// FUSED=0: out proj.
// ============================================================================
constexpr int PIECE_BYTES = 128 * KT * 2;         // 16384
constexpr int STAGE_1P = 2 * PIECE_BYTES;         // 32768
constexpr int GEMM_SMEM_1P = 2 * STAGE_1P;        // 65536

template <int FUSED>
__global__ __launch_bounds__(256, 1) void gemm_1p(
    const float* __restrict__ bias_q, const float* __restrict__ bias_k,
    const float* __restrict__ bias_v, float* __restrict__ outO) {
  extern __shared__ __align__(16) char smem[];
  const uint32_t sb = smem_u32(smem);
  const int tid = threadIdx.x, wid = tid >> 5, lane = tid & 31;
  const int wm = wid >> 2, wn = wid & 3;
  const int bm = blockIdx.y, bn = blockIdx.x;
  const int w = FUSED ? (int)blockIdx.z : 3;  // 0=Q 1=K 2=V 3=O

  const __half* A = FUSED ? g_x16 : g_a16;
  const __half* Bm = (w == 0) ? g_Wq16 : (w == 1) ? g_Wk16
                       : (w == 2) ? g_Wv16 : g_Wo16;
  const float* bias = FUSED
                          ? ((w == 0) ? bias_q : (w == 1) ? bias_k : bias_v)
                          : bias_q;

  const int p = tid >> 7, q = tid & 127;
  const __half* psrc =
      ((p == 0) ? A + (size_t)bm * 128 * KDIM : Bm + (size_t)bn * 128 * KDIM) +
      (size_t)(q >> 3) * KDIM + (q & 7) * 8;
  const uint32_t loff0 = (uint32_t)((q >> 3) * 128 + (q & 7) * 16);

  auto issue = [&](int kt) {
    const int buf = kt & 1;
    const __half* g = psrc + kt * KT;
    const uint32_t dstbase = sb + buf * STAGE_1P + p * PIECE_BYTES;
#pragma unroll
    for (int j = 0; j < 8; ++j) {
      const uint32_t off = loff0 + j * 2048;
      const uint32_t swz = off ^ ((off >> 3) & 0x70);
      cpasync16(dstbase + swz, g + (size_t)j * 16 * KDIM);
    }
    cp_commit();
  };

  float acc[4][4][4];
#pragma unroll
  for (int i = 0; i < 4; ++i)
#pragma unroll
    for (int j = 0; j < 4; ++j)
#pragma unroll
      for (int k = 0; k < 4; ++k) acc[i][j][k] = 0.f;

  issue(0);
#pragma unroll 1
  for (int kt = 0; kt < NKT; ++kt) {
    if (kt + 1 < NKT) {
      issue(kt + 1);
      cp_wait<1>();
    } else {
      cp_wait<0>();
    }
    __syncthreads();
    const uint32_t base = sb + (kt & 1) * STAGE_1P;
#pragma unroll
    for (int ks = 0; ks < 4; ++ks) {
      const int k0 = ks * 16;
      uint32_t a[4][4], bb[2][4];
#pragma unroll
      for (int mt = 0; mt < 4; ++mt) {
        const uint32_t row = wm * 64 + mt * 16 + (lane & 15);
        const uint32_t off = row * 128 + k0 * 2 + ((lane >> 4) << 4);
        const uint32_t swz = off ^ ((off >> 3) & 0x70);
        ldsm4(a[mt], base + swz);
      }
#pragma unroll
      for (int nt2 = 0; nt2 < 2; ++nt2) {
        const uint32_t row =
            wn * 32 + nt2 * 16 + (lane & 7) + ((lane >> 4) << 3);
        const uint32_t off = row * 128 + k0 * 2 + (((lane >> 3) & 1) << 4);
        const uint32_t swz = off ^ ((off >> 3) & 0x70);
        ldsm4(bb[nt2], base + PIECE_BYTES + swz);
      }
#pragma unroll
      for (int mt = 0; mt < 4; ++mt)
#pragma unroll
        for (int nt = 0; nt < 4; ++nt)
          mma_hf(acc[mt][nt], a[mt], &bb[nt >> 1][(nt & 1) * 2]);
    }
    __syncthreads();
  }

  const int g = lane >> 2, t2 = (lane & 3) * 2;
#pragma unroll
  for (int mt = 0; mt < 4; ++mt) {
    const int r0 = bm * 128 + wm * 64 + mt * 16 + g;
    const int r1 = r0 + 8;
    float sn0 = 0.f, cs0 = 0.f, sn1 = 0.f, cs1 = 0.f;
    if (FUSED && w == 1) {
      sincosf(ANGC * (float)(r0 & (Tc - 1)), &sn0, &cs0);
      sincosf(ANGC * (float)(r1 & (Tc - 1)), &sn1, &cs1);
    }
#pragma unroll
    for (int nt = 0; nt < 4; ++nt) {
      const int col = bn * 128 + wn * 32 + nt * 8 + t2;
      const float b0 = __ldg(&bias[col]), b1 = __ldg(&bias[col + 1]);
      const float v00 = acc[mt][nt][0] + b0, v01 = acc[mt][nt][1] + b1;
      const float v10 = acc[mt][nt][2] + b0, v11 = acc[mt][nt][3] + b1;
      if (!FUSED) {
        *(float2*)&outO[(size_t)r0 * DM + col] = make_float2(v00, v01);
        *(float2*)&outO[(size_t)r1 * DM + col] = make_float2(v10, v11);
      } else if (w == 2) {
        *(__half2*)&g_V16[(size_t)r0 * HD + col] = __floats2half2_rn(v00, v01);
        *(__half2*)&g_V16[(size_t)r1 * HD + col] = __floats2half2_rn(v10, v11);
      } else if (w == 0) {
        *(__half2*)&g_Qp16[(size_t)r0 * HD + col] =
            __floats2half2_rn(fmaxf(v00, 0.f), fmaxf(v01, 0.f));
        *(__half2*)&g_Qp16[(size_t)r1 * HD + col] =
            __floats2half2_rn(fmaxf(v10, 0.f), fmaxf(v11, 0.f));
      } else {
        const float a00 = fmaxf(v00, 0.f), a01 = fmaxf(v01, 0.f);
        const float a10 = fmaxf(v10, 0.f), a11 = fmaxf(v11, 0.f);
        *(__half2*)&g_Kp16[(size_t)r0 * HD + col] = __floats2half2_rn(a00, a01);
        *(__half2*)&g_Kp16[(size_t)r1 * HD + col] = __floats2half2_rn(a10, a11);
        *(__half2*)&g_Kc16[(size_t)r0 * HD + col] =
            __floats2half2_rn(a00 * cs0, a01 * cs0);
        *(__half2*)&g_Kc16[(size_t)r1 * HD + col] =
            __floats2half2_rn(a10 * cs1, a11 * cs1);
        *(__half2*)&g_Ks16[(size_t)r0 * HD + col] =
            __floats2half2_rn(a00 * sn0, a01 * sn0);
        *(__half2*)&g_Ks16[(size_t)r1 * HD + col] =
            __floats2half2_rn(a10 * sn1, a11 * sn1);
      }
    }
  }
}

// ============================================================================
// Pass A (tensor cores): per-chunk states (unchanged from round 11)
// ============================================================================
constexpr int CS_LDH = 72;
constexpr int CS_OP = 128 * CS_LDH * 2;          // 18432
constexpr int CS_SMEM = 3 * CS_OP;               // 55296

__global__ __launch_bounds__(128, 1) void chunk_stats16() {
  extern __shared__ __align__(16) char smem[];
  const uint32_t sb = smem_u32(smem);
  const int blk = blockIdx.x;
  const int c = blk & (NCH - 1);
  const int bh = blk >> 5;
  const int b = bh >> 4, h = bh & 15;
  const int tid = threadIdx.x, wid = tid >> 5, lane = tid & 31;

  const size_t gb16 = ((size_t)b * Tc + (size_t)c * CH) * HD + h * DHc;
  {
    const int r = tid >> 3, cb = tid & 7;
#pragma unroll
    for (int op = 0; op < 3; ++op) {
      const __half* src =
          ((op == 0) ? g_Kc16 : (op == 1) ? g_Ks16 : g_V16) + gb16;
#pragma unroll
      for (int j = 0; j < 8; ++j) {
        const int row = r + 16 * j;
        cpasync16(sb + op * CS_OP + (uint32_t)(row * CS_LDH + cb * 8) * 2,
                  src + (size_t)row * HD + cb * 8);
      }
    }
    cp_commit();
    cp_wait<0>();
  }
  __syncthreads();

  {
    const int vec = tid >> 6, d = tid & 63;
    const __half* sK = (const __half*)(smem + vec * CS_OP);
    float z = 0.f;
#pragma unroll 4
    for (int t = 0; t < CH; ++t) z += __half2float(sK[t * CS_LDH + d]);
    const size_t zb = ((size_t)bh * NCH + c) * DHc;
    ((vec == 0) ? g_zcos : g_zsin)[zb + d] = z;
  }

  const int m0 = wid * 16;
  float accC[8][4], accS[8][4];
#pragma unroll
  for (int i = 0; i < 8; ++i)
#pragma unroll
    for (int j = 0; j < 4; ++j) {
      accC[i][j] = 0.f;
      accS[i][j] = 0.f;
    }

  const uint32_t bKc = sb, bKs = sb + CS_OP, bV = sb + 2 * CS_OP;
#pragma unroll 1
  for (int ks = 0; ks < 8; ++ks) {
    const int k0 = ks * 16;
    const uint32_t akk = (uint32_t)(k0 + (lane & 7) + ((lane >> 4) << 3));
    const uint32_t amm = (uint32_t)(m0 + (((lane >> 3) & 1) << 3));
    const uint32_t aoff = akk * (CS_LDH * 2) + amm * 2;
    uint32_t aC[4], aS[4];
    ldsm4t(aC, bKc + aoff);
    ldsm4t(aS, bKs + aoff);
    const uint32_t bkk = (uint32_t)(k0 + (lane & 7) + (((lane >> 3) & 1) << 3));
#pragma unroll
    for (int n4 = 0; n4 < 4; ++n4) {
      const uint32_t bnn = (uint32_t)(n4 * 16 + ((lane >> 4) << 3));
      uint32_t bb[4];
      ldsm4t(bb, bV + bkk * (CS_LDH * 2) + bnn * 2);
      mma_hf(accC[2 * n4], aC, &bb[0]);
      mma_hf(accC[2 * n4 + 1], aC, &bb[2]);
      mma_hf(accS[2 * n4], aS, &bb[0]);
      mma_hf(accS[2 * n4 + 1], aS, &bb[2]);
    }
  }

  const size_t sbse = ((size_t)bh * NCH + c) * (DHc * DHc);
  const int r = lane >> 2, c2 = (lane & 3) * 2;
#pragma unroll
  for (int nt = 0; nt < 8; ++nt) {
    const int col = nt * 8 + c2;
    *(float2*)&g_Scos[sbse + (size_t)(m0 + r) * 64 + col] =
        make_float2(accC[nt][0], accC[nt][1]);
    *(float2*)&g_Scos[sbse + (size_t)(m0 + r + 8) * 64 + col] =
        make_float2(accC[nt][2], accC[nt][3]);
    *(float2*)&g_Ssin[sbse + (size_t)(m0 + r) * 64 + col] =
        make_float2(accS[nt][0], accS[nt][1]);
    *(float2*)&g_Ssin[sbse + (size_t)(m0 + r + 8) * 64 + col] =
        make_float2(accS[nt][2], accS[nt][3]);
  }
}

// ============================================================================
// Pass B: exclusive prefix over chunks; emits fp16 prefix states.
// ============================================================================
__global__ __launch_bounds__(256) void chunk_scan2() {
  const int bh = blockIdx.y;
  const int e = blockIdx.x * 256 + threadIdx.x;
  {
    const size_t base = (size_t)bh * NCH * (DHc * DHc) + e;
    float ac = 0.f, as2 = 0.f;
#pragma unroll 1
    for (int c = 0; c < NCH; ++c) {
      const size_t idx = base + (size_t)c * (DHc * DHc);
      const float tc = g_Scos[idx], ts = g_Ssin[idx];
      g_Sc16[idx] = __float2half(ac);
      g_Ss16[idx] = __float2half(as2);
      ac += tc;
      as2 += ts;
    }
  }
  if (blockIdx.x == 0 && threadIdx.x < DHc) {
    const size_t zb = (size_t)bh * NCH * DHc + threadIdx.x;
    float ac = 0.f, as2 = 0.f;
#pragma unroll 1
    for (int c = 0; c < NCH; ++c) {
      const size_t idx = zb + (size_t)c * DHc;
      const float tc = g_zcos[idx], ts = g_zsin[idx];
      g_zcos[idx] = ac;
      g_zsin[idx] = as2;
      ac += tc;
      as2 += ts;
    }
  }
}

// ============================================================================
// Pass C (tensor cores): per-chunk output, 256 threads (8 warps x 16 rows).
// Phase 1: P = Qp Kp^T, trig-masked into sAx fp16 (cols 0..127).
// Qc/Qs fill cols 128..255.  Phase 2: [A|Qc|Qs] @ [V;Sc;Ss] with den as
// the 65th output column (B col 64 = [1;zc;zs]).
// ============================================================================
constexpr int AT_LDQ = 72;                          // Qp/Kp rows (halves)
constexpr int AT_LDB = 80;                          // stacked B rows (halves)
constexpr int AT_LDA = 264;                         // A-extended rows (halves)
constexpr int AOF_QP = 0;                           // 128*72*2 = 18432
constexpr int AOF_KP = 18432;                       // 18432
constexpr int AOF_B = 36864;                        // 256*80*2 = 40960
constexpr int AOF_AX = 77824;                       // 128*264*2 = 67584
constexpr int AOF_TRC = 145408;                     // 128 f32
constexpr int AOF_TRS = 145920;
constexpr int AOF_ZC = 146432;                      // 64 f32
constexpr int AOF_ZS = 146688;
constexpr int AT_SMEM = 146944;

__global__ __launch_bounds__(256, 1) void attn_tc() {
  extern __shared__ __align__(16) char smem[];
  const uint32_t sb = smem_u32(smem);
  const int blk = blockIdx.x;
  const int c = blk & (NCH - 1);
  const int bh = blk >> 5;
  const int b = bh >> 4, h = bh & 15;
  const int tid = threadIdx.x, wid = tid >> 5, lane = tid & 31;

  float* strc = (float*)(smem + AOF_TRC);
  float* strs = (float*)(smem + AOF_TRS);
  float* szc = (float*)(smem + AOF_ZC);
  float* szs = (float*)(smem + AOF_ZS);

  const size_t gb16 = ((size_t)b * Tc + (size_t)c * CH) * HD + h * DHc;
  const size_t sbse = ((size_t)bh * NCH + c) * (DHc * DHc);
  const size_t zb = ((size_t)bh * NCH + c) * DHc;

  // trig + z
  if (tid < CH) {
    float sn, cs;
    sincosf(ANGC * (float)(c * CH + tid), &sn, &cs);
    strc[tid] = cs;
    strs[tid] = sn;
  }
  if (tid < 64) szc[tid] = g_zcos[zb + tid];
  else if (tid < 128) szs[tid - 64] = g_zsin[zb + tid - 64];

  // async loads: Qp, Kp, V(->B rows 0..127), Sc(->128..191), Ss(->192..255)
  {
    const int r = tid >> 3, cb = tid & 7;  // r 0..31
#pragma unroll
    for (int j = 0; j < 4; ++j) {
      const int row = r + 32 * j;
      cpasync16(sb + AOF_QP + (uint32_t)(row * AT_LDQ + cb * 8) * 2,
                g_Qp16 + gb16 + (size_t)row * HD + cb * 8);
      cpasync16(sb + AOF_KP + (uint32_t)(row * AT_LDQ + cb * 8) * 2,
                g_Kp16 + gb16 + (size_t)row * HD + cb * 8);
      cpasync16(sb + AOF_B + (uint32_t)(row * AT_LDB + cb * 8) * 2,
                g_V16 + gb16 + (size_t)row * HD + cb * 8);
    }
#pragma unroll
    for (int j = 0; j < 2; ++j) {
      const int row = r + 32 * j;  // 0..63
      cpasync16(sb + AOF_B + (uint32_t)((row + 128) * AT_LDB + cb * 8) * 2,
                g_Sc16 + sbse + (size_t)row * 64 + cb * 8);
      cpasync16(sb + AOF_B + (uint32_t)((row + 192) * AT_LDB + cb * 8) * 2,
                g_Ss16 + sbse + (size_t)row * 64 + cb * 8);
    }
    cp_commit();
    cp_wait<0>();
  }
  __syncthreads();

  // fill B cols 64..79 (col64 = 1 / zc / zs, rest 0)
  {
    const int row = tid;  // 0..255
    float cv = (row < 128) ? 1.f
               : (row < 192) ? szc[row - 128] : szs[row - 192];
    __half hv[8] = {__float2half(cv), __half(0), __half(0), __half(0),
                    __half(0), __half(0), __half(0), __half(0)};
    *(uint4*)(smem + AOF_B + (uint32_t)(row * AT_LDB + 64) * 2) =
        *(uint4*)hv;
    uint4 z4 = make_uint4(0, 0, 0, 0);
    *(uint4*)(smem + AOF_B + (uint32_t)(row * AT_LDB + 72) * 2) = z4;
  }
  // fill sAx cols 128..255: Qc = ct*Qp, Qs = st*Qp  (2 threads/row)
  {
    const int row = tid >> 1, half = tid & 1;  // halves 32 cols each
    const float ct = strc[row], st = strs[row];
    const __half* qrow = (const __half*)(smem + AOF_QP + row * AT_LDQ * 2);
    __half* arow = (__half*)(smem + AOF_AX + row * AT_LDA * 2);
#pragma unroll
    for (int j = 0; j < 8; ++j) {
      const int d = half * 32 + j * 4;
      float q0 = __half2float(qrow[d]), q1 = __half2float(qrow[d + 1]);
      float q2 = __half2float(qrow[d + 2]), q3 = __half2float(qrow[d + 3]);
      __half qc[4] = {__float2half(ct * q0), __float2half(ct * q1),
                      __float2half(ct * q2), __float2half(ct * q3)};
      __half qs[4] = {__float2half(st * q0), __float2half(st * q1),
                      __float2half(st * q2), __float2half(st * q3)};
      *(uint2*)&arow[128 + d] = *(uint2*)qc;
      *(uint2*)&arow[192 + d] = *(uint2*)qs;
    }
  }
  __syncthreads();

  // ---- phase 1: P = Qp Kp^T, warp w rows [16w,16w+16) ----
  const int m0 = wid * 16;
  {
    uint32_t a[4][4];
#pragma unroll
    for (int ks = 0; ks < 4; ++ks) {
      const uint32_t row = (uint32_t)(m0 + (lane & 15));
      const uint32_t off = row * (AT_LDQ * 2) + ks * 32 + ((lane >> 4) << 4);
      ldsm4(a[ks], sb + AOF_QP + off);
    }
    const int r = lane >> 2, c2 = (lane & 3) * 2;
#pragma unroll 1
    for (int nt2 = 0; nt2 < 8; ++nt2) {
      if (nt2 <= wid) {
        uint32_t bbf[4][4];
#pragma unroll
        for (int ks = 0; ks < 4; ++ks) {
          const uint32_t row =
              (uint32_t)(nt2 * 16 + (lane & 7) + ((lane >> 4) << 3));
          const uint32_t off =
              row * (AT_LDQ * 2) + ks * 32 + (((lane >> 3) & 1) << 4);
          ldsm4(bbf[ks], sb + AOF_KP + off);
        }
        float pacc[2][4] = {};
#pragma unroll
        for (int ks = 0; ks < 4; ++ks) {
          mma_hf(pacc[0], a[ks], &bbf[ks][0]);
          mma_hf(pacc[1], a[ks], &bbf[ks][2]);
        }
#pragma unroll
        for (int ntl = 0; ntl < 2; ++ntl) {
          const int s0 = nt2 * 16 + ntl * 8 + c2;
          const float cs0 = strc[s0], ss0 = strs[s0];
          const float cs1 = strc[s0 + 1], ss1 = strs[s0 + 1];
#pragma unroll
          for (int rr = 0; rr < 2; ++rr) {
            const int t = m0 + r + rr * 8;
            const float ct = strc[t], st = strs[t];
            const float v0 =
                (s0 <= t) ? (ct * cs0 + st * ss0) * pacc[ntl][rr * 2] : 0.f;
            const float v1 =
                (s0 + 1 <= t) ? (ct * cs1 + st * ss1) * pacc[ntl][rr * 2 + 1]
                              : 0.f;
            *(__half2*)(smem + AOF_AX + ((uint32_t)t * AT_LDA + s0) * 2) =
                __floats2half2_rn(v0, v1);
          }
        }
      } else {
#pragma unroll
        for (int ntl = 0; ntl < 2; ++ntl) {
          const int s0 = nt2 * 16 + ntl * 8 + c2;
          *(uint32_t*)(smem + AOF_AX +
                       ((uint32_t)(m0 + r) * AT_LDA + s0) * 2) = 0u;
          *(uint32_t*)(smem + AOF_AX +
                       ((uint32_t)(m0 + r + 8) * AT_LDA + s0) * 2) = 0u;
        }
      }
    }
  }
  __syncthreads();

  // ---- phase 2: [A|Qc|Qs] @ B, K=256, N=72 (col 64 = den) ----
  float acc[9][4];
#pragma unroll
  for (int i = 0; i < 9; ++i)
#pragma unroll
    for (int j = 0; j < 4; ++j) acc[i][j] = 0.f;

#pragma unroll 1
  for (int ks = 0; ks < 16; ++ks) {
    const int kk = ks * 16;
    uint32_t a[4];
    {
      const uint32_t row = (uint32_t)(m0 + (lane & 15));
      const uint32_t off = row * (AT_LDA * 2) + kk * 2 + ((lane >> 4) << 4);
      ldsm4(a, sb + AOF_AX + off);
    }
    uint32_t bbf[5][4];
    {
      const uint32_t kr =
          (uint32_t)(kk + (lane & 7) + (((lane >> 3) & 1) << 3));
#pragma unroll
      for (int g = 0; g < 5; ++g) {
        const uint32_t nn = (uint32_t)(g * 16 + ((lane >> 4) << 3));
        ldsm4t(bbf[g], sb + AOF_B + (kr * AT_LDB + nn) * 2);
      }
    }
#pragma unroll
    for (int nt = 0; nt < 9; ++nt)
      mma_hf(acc[nt], a, &bbf[nt >> 1][(nt & 1) * 2]);
  }

  // ---- epilogue: den = col 64; write g_a16 ----
  const int r = lane >> 2, c2 = (lane & 3) * 2;
  const float den0r =
      __shfl_sync(0xffffffffu, acc[8][0], lane & ~3);
  const float den1r =
      __shfl_sync(0xffffffffu, acc[8][2], lane & ~3);
  const float inv0 = 1.f / fmaxf(den0r, 1e-6f);
  const float inv1 = 1.f / fmaxf(den1r, 1e-6f);
#pragma unroll
  for (int nt = 0; nt < 8; ++nt) {
    const int col = nt * 8 + c2;
    const int t0 = m0 + r;
    *(__half2*)&g_a16[gb16 + (size_t)t0 * HD + col] =
        __floats2half2_rn(acc[nt][0] * inv0, acc[nt][1] * inv0);
    *(__half2*)&g_a16[gb16 + (size_t)(t0 + 8) * HD + col] =
        __floats2half2_rn(acc[nt][2] * inv1, acc[nt][3] * inv1);
  }
}

}  // namespace cf

extern "C" void kernel_launch(void* const* d_in, const int* in_sizes, int n_in,
                              void* d_out, int out_size) {
  using namespace cf;
  const float* x = (const float*)d_in[0];
  const float* Wq = (const float*)d_in[1];
  const float* bq = (const float*)d_in[2];
  const float* Wk = (const float*)d_in[3];
  const float* bk = (const float*)d_in[4];
  const float* Wv = (const float*)d_in[5];
  const float* bv = (const float*)d_in[6];
  const float* Wo = (const float*)d_in[7];
  const float* bo = (const float*)d_in[8];
  float* out = (float*)d_out;

  cudaFuncSetAttribute(gemm_1p<1>, cudaFuncAttributeMaxDynamicSharedMemorySize,
                       GEMM_SMEM_1P);
  cudaFuncSetAttribute(gemm_1p<0>, cudaFuncAttributeMaxDynamicSharedMemorySize,
                       GEMM_SMEM_1P);
  cudaFuncSetAttribute(chunk_stats16,
                       cudaFuncAttributeMaxDynamicSharedMemorySize, CS_SMEM);
  cudaFuncSetAttribute(attn_tc, cudaFuncAttributeMaxDynamicSharedMemorySize,
                       AT_SMEM);

  // 1) conversions
  conv_x<<<Mrows * DM / 4 / 256, 256>>>(x);
  dim3 tg(32, 32, 4), tb(32, 8);
  tconv<<<tg, tb>>>(Wq, Wk, Wv, Wo);

  // 2) fused QKV projection
  dim3 gq(HD / 128, Mrows / 128, 3);
  gemm_1p<1><<<gq, 256, GEMM_SMEM_1P>>>(bq, bk, bv, nullptr);

  // 3) attention
  chunk_stats16<<<BHc * NCH, 128, CS_SMEM>>>();
  chunk_scan2<<<dim3(16, 32), 256>>>();
  attn_tc<<<BHc * NCH, 256, AT_SMEM>>>();

  // 4) output projection
  dim3 go(HD / 128, Mrows / 128);
  gemm_1p<0><<<go, 256, GEMM_SMEM_1P>>>(bo, nullptr, nullptr, out);
}

// round 13
// speedup vs baseline: 6.6576x; 1.1012x over previous
#include <cuda_runtime.h>
#include <cuda_fp16.h>
#include <math.h>
#include <stdint.h>

// ============================================================================
// CosFormer attention (sm_103 base; legacy HMMA mma.sync).
//  All heavy math on tensor cores (fp16, fp32 accum):
//   - QKV + out-proj GEMMs: B kept in natural [K][N] layout, fragments via
//     ldmatrix.trans (no weight transpose kernel); 2 CTAs/SM.
//   - chunk_stats: S = K16^T V16.
//   - attn_tc: P = Qp Kp^T (causal tile-skip, trig mask), then
//     [A|Qc|Qs] @ [V;Sc;Ss | 1;zc;zs]  (den = 65th output column).
// ============================================================================

namespace cf {

constexpr int Bc = 2, Tc = 4096, Hc = 16, DHc = 64;
constexpr int DM = 1024, HD = 1024;
constexpr int Mrows = Bc * Tc;            // 8192
constexpr int CH = 128, NCH = Tc / CH;    // 128, 32
constexpr int BHc = Bc * Hc;              // 32
constexpr float ANGC = 3.14159265358979323846f / (2.0f * (float)Tc);

constexpr int KDIM = 1024;
constexpr int KT = 64;
constexpr int NKT = KDIM / KT;            // 16

// ---- fp32 scratch ----
__device__ __align__(16) float g_Scos[(size_t)BHc * NCH * DHc * DHc];
__device__ __align__(16) float g_Ssin[(size_t)BHc * NCH * DHc * DHc];
__device__ __align__(16) float g_zcos[(size_t)BHc * NCH * DHc];
__device__ __align__(16) float g_zsin[(size_t)BHc * NCH * DHc];

// ---- fp16 operands ----
__device__ __align__(16) __half g_x16[(size_t)Mrows * DM];
__device__ __align__(16) __half g_Wq16[(size_t)DM * HD];   // [K][N]
__device__ __align__(16) __half g_Wk16[(size_t)DM * HD];
__device__ __align__(16) __half g_Wv16[(size_t)DM * HD];
__device__ __align__(16) __half g_Wo16[(size_t)HD * DM];
__device__ __align__(16) __half g_a16[(size_t)Mrows * HD];
__device__ __align__(16) __half g_Qp16[(size_t)Mrows * HD];
__device__ __align__(16) __half g_Kp16[(size_t)Mrows * HD];
__device__ __align__(16) __half g_Kc16[(size_t)Mrows * HD];
__device__ __align__(16) __half g_Ks16[(size_t)Mrows * HD];
__device__ __align__(16) __half g_V16[(size_t)Mrows * HD];
__device__ __align__(16) __half g_Sc16[(size_t)BHc * NCH * DHc * DHc];
__device__ __align__(16) __half g_Ss16[(size_t)BHc * NCH * DHc * DHc];

// ============================================================================
// helpers
// ============================================================================
__device__ __forceinline__ uint32_t smem_u32(const void* p) {
  uint32_t a;
  asm("{ .reg .u64 t; cvta.to.shared.u64 t, %1; cvt.u32.u64 %0, t; }"
      : "=r"(a) : "l"(p));
  return a;
}
__device__ __forceinline__ void ldsm4(uint32_t* r, uint32_t addr) {
  asm volatile(
      "ldmatrix.sync.aligned.m8n8.x4.shared.b16 {%0,%1,%2,%3}, [%4];"
      : "=r"(r[0]), "=r"(r[1]), "=r"(r[2]), "=r"(r[3]) : "r"(addr));
}
__device__ __forceinline__ void ldsm4t(uint32_t* r, uint32_t addr) {
  asm volatile(
      "ldmatrix.sync.aligned.m8n8.x4.trans.shared.b16 {%0,%1,%2,%3}, [%4];"
      : "=r"(r[0]), "=r"(r[1]), "=r"(r[2]), "=r"(r[3]) : "r"(addr));
}
__device__ __forceinline__ void mma_hf(float* d, const uint32_t* a,
                                       const uint32_t* b) {
  asm volatile(
      "mma.sync.aligned.m16n8k16.row.col.f32.f16.f16.f32 "
      "{%0,%1,%2,%3}, {%4,%5,%6,%7}, {%8,%9}, {%0,%1,%2,%3};"
      : "+f"(d[0]), "+f"(d[1]), "+f"(d[2]), "+f"(d[3])
      : "r"(a[0]), "r"(a[1]), "r"(a[2]), "r"(a[3]), "r"(b[0]), "r"(b[1]));
}
__device__ __forceinline__ void cpasync16(uint32_t dst, const void* src) {
  asm volatile("cp.async.cg.shared.global [%0], [%1], 16;"
               ::"r"(dst), "l"(src) : "memory");
}
__device__ __forceinline__ void cp_commit() {
  asm volatile("cp.async.commit_group;" ::: "memory");
}
template <int N>
__device__ __forceinline__ void cp_wait() {
  asm volatile("cp.async.wait_group %0;" ::"n"(N) : "memory");
}

// ============================================================================
// Conversions (pure casts; no transpose)
// ============================================================================
__global__ __launch_bounds__(256) void conv_x(const float* __restrict__ in) {
  int i = blockIdx.x * 256 + threadIdx.x;
  float4 v = *(const float4*)(in + (size_t)i * 4);
  __half h[4] = {__float2half(v.x), __float2half(v.y), __float2half(v.z),
                 __float2half(v.w)};
  *(uint2*)(g_x16 + (size_t)i * 4) = *(uint2*)h;
}

__global__ __launch_bounds__(256) void wcast(const float* __restrict__ Wq,
                                             const float* __restrict__ Wk,
                                             const float* __restrict__ Wv,
                                             const float* __restrict__ Wo) {
  const int w = blockIdx.y;
  const float* W = (w == 0) ? Wq : (w == 1) ? Wk : (w == 2) ? Wv : Wo;
  __half* T = (w == 0) ? g_Wq16 : (w == 1) ? g_Wk16 : (w == 2) ? g_Wv16
                                                               : g_Wo16;
  int i = blockIdx.x * 256 + threadIdx.x;
  float4 v = *(const float4*)(W + (size_t)i * 4);
  __half h[4] = {__float2half(v.x), __float2half(v.y), __float2half(v.z),
                 __float2half(v.w)};
  *(uint2*)(T + (size_t)i * 4) = *(uint2*)h;
}

// ============================================================================
// Single-pass fp16 GEMM with B in [K][N] layout (ldsm.trans fragments).
// 128x128 CTA, 8 warps of 64x32, K staged 64, cp.async double buffer,
// 2 CTAs/SM.  FUSED=1: QKV via grid.z.  FUSED=0: out proj.
// ============================================================================
constexpr int A_PIECE = 128 * KT * 2;            // 16384 (swizzled, 128B rows)
constexpr int B_LDH = 136;                       // 128 + 8 pad halves per row
constexpr int B_PIECE = KT * B_LDH * 2;          // 17408
constexpr int STAGE_G = A_PIECE + B_PIECE;       // 33792
constexpr int GEMM_SMEM = 2 * STAGE_G;           // 67584

template <int FUSED>
__global__ __launch_bounds__(256, 2) void gemm_1p(
    const float* __restrict__ bias_q, const float* __restrict__ bias_k,
    const float* __restrict__ bias_v, float* __restrict__ outO) {
  extern __shared__ __align__(16) char smem[];
  const uint32_t sb = smem_u32(smem);
  const int tid = threadIdx.x, wid = tid >> 5, lane = tid & 31;
  const int wm = wid >> 2, wn = wid & 3;
  const int bm = blockIdx.y, bn = blockIdx.x;
  const int w = FUSED ? (int)blockIdx.z : 3;  // 0=Q 1=K 2=V 3=O

  const __half* A = FUSED ? g_x16 : g_a16;
  const __half* Bm = (w == 0) ? g_Wq16 : (w == 1) ? g_Wk16
                       : (w == 2) ? g_Wv16 : g_Wo16;
  const float* bias = FUSED
                          ? ((w == 0) ? bias_q : (w == 1) ? bias_k : bias_v)
                          : bias_q;

  // loader: p=0 -> A (swizzled rows), p=1 -> B ([k][n] tile, padded rows)
  const int p = tid >> 7, q = tid & 127;
  // A mapping
  const __half* psrcA =
      A + (size_t)bm * 128 * KDIM + (size_t)(q >> 3) * KDIM + (q & 7) * 8;
  const uint32_t aoff0 = (uint32_t)((q >> 3) * 128 + (q & 7) * 16);
  // B mapping: row = (q>>4) + 8j (0..63), chunk = q&15 (16B = 8 halves)
  const __half* psrcB = Bm + (size_t)(q >> 4) * 1024 + bn * 128 + (q & 15) * 8;
  const uint32_t boff0 = (uint32_t)((q >> 4) * B_LDH + (q & 15) * 8) * 2;

  auto issue = [&](int kt) {
    const int buf = kt & 1;
    if (p == 0) {
      const __half* g = psrcA + kt * KT;
      const uint32_t dstbase = sb + buf * STAGE_G;
#pragma unroll
      for (int j = 0; j < 8; ++j) {
        const uint32_t off = aoff0 + j * 2048;
        const uint32_t swz = off ^ ((off >> 3) & 0x70);
        cpasync16(dstbase + swz, g + (size_t)j * 16 * KDIM);
      }
    } else {
      const __half* g = psrcB + (size_t)kt * KT * 1024;
      const uint32_t dstbase = sb + buf * STAGE_G + A_PIECE;
#pragma unroll
      for (int j = 0; j < 8; ++j)
        cpasync16(dstbase + boff0 + (uint32_t)(j * 8 * B_LDH) * 2,
                  g + (size_t)j * 8 * 1024);
    }
    cp_commit();
  };

  float acc[4][4][4];
#pragma unroll
  for (int i = 0; i < 4; ++i)
#pragma unroll
    for (int j = 0; j < 4; ++j)
#pragma unroll
      for (int k = 0; k < 4; ++k) acc[i][j][k] = 0.f;

  issue(0);
#pragma unroll 1
  for (int kt = 0; kt < NKT; ++kt) {
    if (kt + 1 < NKT) {
      issue(kt + 1);
      cp_wait<1>();
    } else {
      cp_wait<0>();
    }
    __syncthreads();
    const uint32_t base = sb + (kt & 1) * STAGE_G;
#pragma unroll
    for (int ks = 0; ks < 4; ++ks) {
      const int k0 = ks * 16;
      uint32_t a[4][4], bb[2][4];
#pragma unroll
      for (int mt = 0; mt < 4; ++mt) {
        const uint32_t row = wm * 64 + mt * 16 + (lane & 15);
        const uint32_t off = row * 128 + k0 * 2 + ((lane >> 4) << 4);
        const uint32_t swz = off ^ ((off >> 3) & 0x70);
        ldsm4(a[mt], base + swz);
      }
      // B fragments via ldsm.trans on [k][n] tile
      const uint32_t kr =
          (uint32_t)(k0 + (lane & 7) + (((lane >> 3) & 1) << 3));
#pragma unroll
      for (int nt2 = 0; nt2 < 2; ++nt2) {
        const uint32_t nn =
            (uint32_t)(wn * 32 + nt2 * 16 + ((lane >> 4) << 3));
        ldsm4t(bb[nt2], base + A_PIECE + (kr * B_LDH + nn) * 2);
      }
#pragma unroll
      for (int mt = 0; mt < 4; ++mt)
#pragma unroll
        for (int nt = 0; nt < 4; ++nt)
          mma_hf(acc[mt][nt], a[mt], &bb[nt >> 1][(nt & 1) * 2]);
    }
    __syncthreads();
  }

  const int g = lane >> 2, t2 = (lane & 3) * 2;
#pragma unroll
  for (int mt = 0; mt < 4; ++mt) {
    const int r0 = bm * 128 + wm * 64 + mt * 16 + g;
    const int r1 = r0 + 8;
    float sn0 = 0.f, cs0 = 0.f, sn1 = 0.f, cs1 = 0.f;
    if (FUSED && w == 1) {
      sincosf(ANGC * (float)(r0 & (Tc - 1)), &sn0, &cs0);
      sincosf(ANGC * (float)(r1 & (Tc - 1)), &sn1, &cs1);
    }
#pragma unroll
    for (int nt = 0; nt < 4; ++nt) {
      const int col = bn * 128 + wn * 32 + nt * 8 + t2;
      const float b0 = __ldg(&bias[col]), b1 = __ldg(&bias[col + 1]);
      const float v00 = acc[mt][nt][0] + b0, v01 = acc[mt][nt][1] + b1;
      const float v10 = acc[mt][nt][2] + b0, v11 = acc[mt][nt][3] + b1;
      if (!FUSED) {
        *(float2*)&outO[(size_t)r0 * DM + col] = make_float2(v00, v01);
        *(float2*)&outO[(size_t)r1 * DM + col] = make_float2(v10, v11);
      } else if (w == 2) {
        *(__half2*)&g_V16[(size_t)r0 * HD + col] = __floats2half2_rn(v00, v01);
        *(__half2*)&g_V16[(size_t)r1 * HD + col] = __floats2half2_rn(v10, v11);
      } else if (w == 0) {
        *(__half2*)&g_Qp16[(size_t)r0 * HD + col] =
            __floats2half2_rn(fmaxf(v00, 0.f), fmaxf(v01, 0.f));
        *(__half2*)&g_Qp16[(size_t)r1 * HD + col] =
            __floats2half2_rn(fmaxf(v10, 0.f), fmaxf(v11, 0.f));
      } else {
        const float a00 = fmaxf(v00, 0.f), a01 = fmaxf(v01, 0.f);
        const float a10 = fmaxf(v10, 0.f), a11 = fmaxf(v11, 0.f);
        *(__half2*)&g_Kp16[(size_t)r0 * HD + col] = __floats2half2_rn(a00, a01);
        *(__half2*)&g_Kp16[(size_t)r1 * HD + col] = __floats2half2_rn(a10, a11);
        *(__half2*)&g_Kc16[(size_t)r0 * HD + col] =
            __floats2half2_rn(a00 * cs0, a01 * cs0);
        *(__half2*)&g_Kc16[(size_t)r1 * HD + col] =
            __floats2half2_rn(a10 * cs1, a11 * cs1);
        *(__half2*)&g_Ks16[(size_t)r0 * HD + col] =
            __floats2half2_rn(a00 * sn0, a01 * sn0);
        *(__half2*)&g_Ks16[(size_t)r1 * HD + col] =
            __floats2half2_rn(a10 * sn1, a11 * sn1);
      }
    }
  }
}

// ============================================================================
// Pass A (tensor cores): per-chunk states
// ============================================================================
constexpr int CS_LDH = 72;
constexpr int CS_OP = 128 * CS_LDH * 2;
constexpr int CS_SMEM = 3 * CS_OP;

__global__ __launch_bounds__(128, 4) void chunk_stats16() {
  extern __shared__ __align__(16) char smem[];
  const uint32_t sb = smem_u32(smem);
  const int blk = blockIdx.x;
  const int c = blk & (NCH - 1);
  const int bh = blk >> 5;
  const int b = bh >> 4, h = bh & 15;
  const int tid = threadIdx.x, wid = tid >> 5, lane = tid & 31;

  const size_t gb16 = ((size_t)b * Tc + (size_t)c * CH) * HD + h * DHc;
  {
    const int r = tid >> 3, cb = tid & 7;
#pragma unroll
    for (int op = 0; op < 3; ++op) {
      const __half* src =
          ((op == 0) ? g_Kc16 : (op == 1) ? g_Ks16 : g_V16) + gb16;
#pragma unroll
      for (int j = 0; j < 8; ++j) {
        const int row = r + 16 * j;
        cpasync16(sb + op * CS_OP + (uint32_t)(row * CS_LDH + cb * 8) * 2,
                  src + (size_t)row * HD + cb * 8);
      }
    }
    cp_commit();
    cp_wait<0>();
  }
  __syncthreads();

  {
    const int vec = tid >> 6, d = tid & 63;
    const __half* sK = (const __half*)(smem + vec * CS_OP);
    float z = 0.f;
#pragma unroll 4
    for (int t = 0; t < CH; ++t) z += __half2float(sK[t * CS_LDH + d]);
    const size_t zb = ((size_t)bh * NCH + c) * DHc;
    ((vec == 0) ? g_zcos : g_zsin)[zb + d] = z;
  }

  const int m0 = wid * 16;
  float accC[8][4], accS[8][4];
#pragma unroll
  for (int i = 0; i < 8; ++i)
#pragma unroll
    for (int j = 0; j < 4; ++j) {
      accC[i][j] = 0.f;
      accS[i][j] = 0.f;
    }

  const uint32_t bKc = sb, bKs = sb + CS_OP, bV = sb + 2 * CS_OP;
#pragma unroll 1
  for (int ks = 0; ks < 8; ++ks) {
    const int k0 = ks * 16;
    const uint32_t akk = (uint32_t)(k0 + (lane & 7) + ((lane >> 4) << 3));
    const uint32_t amm = (uint32_t)(m0 + (((lane >> 3) & 1) << 3));
    const uint32_t aoff = akk * (CS_LDH * 2) + amm * 2;
    uint32_t aC[4], aS[4];
    ldsm4t(aC, bKc + aoff);
    ldsm4t(aS, bKs + aoff);
    const uint32_t bkk = (uint32_t)(k0 + (lane & 7) + (((lane >> 3) & 1) << 3));
#pragma unroll
    for (int n4 = 0; n4 < 4; ++n4) {
      const uint32_t bnn = (uint32_t)(n4 * 16 + ((lane >> 4) << 3));
      uint32_t bb[4];
      ldsm4t(bb, bV + bkk * (CS_LDH * 2) + bnn * 2);
      mma_hf(accC[2 * n4], aC, &bb[0]);
      mma_hf(accC[2 * n4 + 1], aC, &bb[2]);
      mma_hf(accS[2 * n4], aS, &bb[0]);
      mma_hf(accS[2 * n4 + 1], aS, &bb[2]);
    }
  }

  const size_t sbse = ((size_t)bh * NCH + c) * (DHc * DHc);
  const int r = lane >> 2, c2 = (lane & 3) * 2;
#pragma unroll
  for (int nt = 0; nt < 8; ++nt) {
    const int col = nt * 8 + c2;
    *(float2*)&g_Scos[sbse + (size_t)(m0 + r) * 64 + col] =
        make_float2(accC[nt][0], accC[nt][1]);
    *(float2*)&g_Scos[sbse + (size_t)(m0 + r + 8) * 64 + col] =
        make_float2(accC[nt][2], accC[nt][3]);
    *(float2*)&g_Ssin[sbse + (size_t)(m0 + r) * 64 + col] =
        make_float2(accS[nt][0], accS[nt][1]);
    *(float2*)&g_Ssin[sbse + (size_t)(m0 + r + 8) * 64 + col] =
        make_float2(accS[nt][2], accS[nt][3]);
  }
}

// ============================================================================
// Pass B: exclusive prefix over chunks; emits fp16 prefix states.
// ============================================================================
__global__ __launch_bounds__(256) void chunk_scan2() {
  const int bh = blockIdx.y;
  const int e = blockIdx.x * 256 + threadIdx.x;
  {
    const size_t base = (size_t)bh * NCH * (DHc * DHc) + e;
    float ac = 0.f, as2 = 0.f;
#pragma unroll 1
    for (int c = 0; c < NCH; ++c) {
      const size_t idx = base + (size_t)c * (DHc * DHc);
      const float tc = g_Scos[idx], ts = g_Ssin[idx];
      g_Sc16[idx] = __float2half(ac);
      g_Ss16[idx] = __float2half(as2);
      ac += tc;
      as2 += ts;
    }
  }
  if (blockIdx.x == 0 && threadIdx.x < DHc) {
    const size_t zb = (size_t)bh * NCH * DHc + threadIdx.x;
    float ac = 0.f, as2 = 0.f;
#pragma unroll 1
    for (int c = 0; c < NCH; ++c) {
      const size_t idx = zb + (size_t)c * DHc;
      const float tc = g_zcos[idx], ts = g_zsin[idx];
      g_zcos[idx] = ac;
      g_zsin[idx] = as2;
      ac += tc;
      as2 += ts;
    }
  }
}

// ============================================================================
// Pass C (tensor cores): per-chunk output (unchanged from round 12)
// ============================================================================
constexpr int AT_LDQ = 72;
constexpr int AT_LDB = 80;
constexpr int AT_LDA = 264;
constexpr int AOF_QP = 0;
constexpr int AOF_KP = 18432;
constexpr int AOF_B = 36864;
constexpr int AOF_AX = 77824;
constexpr int AOF_TRC = 145408;
constexpr int AOF_TRS = 145920;
constexpr int AOF_ZC = 146432;
constexpr int AOF_ZS = 146688;
constexpr int AT_SMEM = 146944;

__global__ __launch_bounds__(256, 1) void attn_tc() {
  extern __shared__ __align__(16) char smem[];
  const uint32_t sb = smem_u32(smem);
  const int blk = blockIdx.x;
  const int c = blk & (NCH - 1);
  const int bh = blk >> 5;
  const int b = bh >> 4, h = bh & 15;
  const int tid = threadIdx.x, wid = tid >> 5, lane = tid & 31;

  float* strc = (float*)(smem + AOF_TRC);
  float* strs = (float*)(smem + AOF_TRS);
  float* szc = (float*)(smem + AOF_ZC);
  float* szs = (float*)(smem + AOF_ZS);

  const size_t gb16 = ((size_t)b * Tc + (size_t)c * CH) * HD + h * DHc;
  const size_t sbse = ((size_t)bh * NCH + c) * (DHc * DHc);
  const size_t zb = ((size_t)bh * NCH + c) * DHc;

  if (tid < CH) {
    float sn, cs;
    sincosf(ANGC * (float)(c * CH + tid), &sn, &cs);
    strc[tid] = cs;
    strs[tid] = sn;
  }
  if (tid < 64) szc[tid] = g_zcos[zb + tid];
  else if (tid < 128) szs[tid - 64] = g_zsin[zb + tid - 64];

  {
    const int r = tid >> 3, cb = tid & 7;
#pragma unroll
    for (int j = 0; j < 4; ++j) {
      const int row = r + 32 * j;
      cpasync16(sb + AOF_QP + (uint32_t)(row * AT_LDQ + cb * 8) * 2,
                g_Qp16 + gb16 + (size_t)row * HD + cb * 8);
      cpasync16(sb + AOF_KP + (uint32_t)(row * AT_LDQ + cb * 8) * 2,
                g_Kp16 + gb16 + (size_t)row * HD + cb * 8);
      cpasync16(sb + AOF_B + (uint32_t)(row * AT_LDB + cb * 8) * 2,
                g_V16 + gb16 + (size_t)row * HD + cb * 8);
    }
#pragma unroll
    for (int j = 0; j < 2; ++j) {
      const int row = r + 32 * j;
      cpasync16(sb + AOF_B + (uint32_t)((row + 128) * AT_LDB + cb * 8) * 2,
                g_Sc16 + sbse + (size_t)row * 64 + cb * 8);
      cpasync16(sb + AOF_B + (uint32_t)((row + 192) * AT_LDB + cb * 8) * 2,
                g_Ss16 + sbse + (size_t)row * 64 + cb * 8);
    }
    cp_commit();
    cp_wait<0>();
  }
  __syncthreads();

  {
    const int row = tid;
    float cv = (row < 128) ? 1.f
               : (row < 192) ? szc[row - 128] : szs[row - 192];
    __half hv[8] = {__float2half(cv), __half(0), __half(0), __half(0),
                    __half(0), __half(0), __half(0), __half(0)};
    *(uint4*)(smem + AOF_B + (uint32_t)(row * AT_LDB + 64) * 2) = *(uint4*)hv;
    uint4 z4 = make_uint4(0, 0, 0, 0);
    *(uint4*)(smem + AOF_B + (uint32_t)(row * AT_LDB + 72) * 2) = z4;
  }
  {
    const int row = tid >> 1, half = tid & 1;
    const float ct = strc[row], st = strs[row];
    const __half* qrow = (const __half*)(smem + AOF_QP + row * AT_LDQ * 2);
    __half* arow = (__half*)(smem + AOF_AX + row * AT_LDA * 2);
#pragma unroll
    for (int j = 0; j < 8; ++j) {
      const int d = half * 32 + j * 4;
      float q0 = __half2float(qrow[d]), q1 = __half2float(qrow[d + 1]);
      float q2 = __half2float(qrow[d + 2]), q3 = __half2float(qrow[d + 3]);
      __half qc[4] = {__float2half(ct * q0), __float2half(ct * q1),
                      __float2half(ct * q2), __float2half(ct * q3)};
      __half qs[4] = {__float2half(st * q0), __float2half(st * q1),
                      __float2half(st * q2), __float2half(st * q3)};
      *(uint2*)&arow[128 + d] = *(uint2*)qc;
      *(uint2*)&arow[192 + d] = *(uint2*)qs;
    }
  }
  __syncthreads();

  const int m0 = wid * 16;
  {
    uint32_t a[4][4];
#pragma unroll
    for (int ks = 0; ks < 4; ++ks) {
      const uint32_t row = (uint32_t)(m0 + (lane & 15));
      const uint32_t off = row * (AT_LDQ * 2) + ks * 32 + ((lane >> 4) << 4);
      ldsm4(a[ks], sb + AOF_QP + off);
    }
    const int r = lane >> 2, c2 = (lane & 3) * 2;
#pragma unroll 1
    for (int nt2 = 0; nt2 < 8; ++nt2) {
      if (nt2 <= wid) {
        uint32_t bbf[4][4];
#pragma unroll
        for (int ks = 0; ks < 4; ++ks) {
          const uint32_t row =
              (uint32_t)(nt2 * 16 + (lane & 7) + ((lane >> 4) << 3));
          const uint32_t off =
              row * (AT_LDQ * 2) + ks * 32 + (((lane >> 3) & 1) << 4);
          ldsm4(bbf[ks], sb + AOF_KP + off);
        }
        float pacc[2][4] = {};
#pragma unroll
        for (int ks = 0; ks < 4; ++ks) {
          mma_hf(pacc[0], a[ks], &bbf[ks][0]);
          mma_hf(pacc[1], a[ks], &bbf[ks][2]);
        }
#pragma unroll
        for (int ntl = 0; ntl < 2; ++ntl) {
          const int s0 = nt2 * 16 + ntl * 8 + c2;
          const float cs0 = strc[s0], ss0 = strs[s0];
          const float cs1 = strc[s0 + 1], ss1 = strs[s0 + 1];
#pragma unroll
          for (int rr = 0; rr < 2; ++rr) {
            const int t = m0 + r + rr * 8;
            const float ct = strc[t], st = strs[t];
            const float v0 =
                (s0 <= t) ? (ct * cs0 + st * ss0) * pacc[ntl][rr * 2] : 0.f;
            const float v1 =
                (s0 + 1 <= t) ? (ct * cs1 + st * ss1) * pacc[ntl][rr * 2 + 1]
                              : 0.f;
            *(__half2*)(smem + AOF_AX + ((uint32_t)t * AT_LDA + s0) * 2) =
                __floats2half2_rn(v0, v1);
          }
        }
      } else {
#pragma unroll
        for (int ntl = 0; ntl < 2; ++ntl) {
          const int s0 = nt2 * 16 + ntl * 8 + c2;
          *(uint32_t*)(smem + AOF_AX +
                       ((uint32_t)(m0 + r) * AT_LDA + s0) * 2) = 0u;
          *(uint32_t*)(smem + AOF_AX +
                       ((uint32_t)(m0 + r + 8) * AT_LDA + s0) * 2) = 0u;
        }
      }
    }
  }
  __syncthreads();

  float acc[9][4];
#pragma unroll
  for (int i = 0; i < 9; ++i)
#pragma unroll
    for (int j = 0; j < 4; ++j) acc[i][j] = 0.f;

#pragma unroll 1
  for (int ks = 0; ks < 16; ++ks) {
    const int kk = ks * 16;
    uint32_t a[4];
    {
      const uint32_t row = (uint32_t)(m0 + (lane & 15));
      const uint32_t off = row * (AT_LDA * 2) + kk * 2 + ((lane >> 4) << 4);
      ldsm4(a, sb + AOF_AX + off);
    }
    uint32_t bbf[5][4];
    {
      const uint32_t kr =
          (uint32_t)(kk + (lane & 7) + (((lane >> 3) & 1) << 3));
#pragma unroll
      for (int g = 0; g < 5; ++g) {
        const uint32_t nn = (uint32_t)(g * 16 + ((lane >> 4) << 3));
        ldsm4t(bbf[g], sb + AOF_B + (kr * AT_LDB + nn) * 2);
      }
    }
#pragma unroll
    for (int nt = 0; nt < 9; ++nt)
      mma_hf(acc[nt], a, &bbf[nt >> 1][(nt & 1) * 2]);
  }

  const int r = lane >> 2, c2 = (lane & 3) * 2;
  const float den0r = __shfl_sync(0xffffffffu, acc[8][0], lane & ~3);
  const float den1r = __shfl_sync(0xffffffffu, acc[8][2], lane & ~3);
  const float inv0 = 1.f / fmaxf(den0r, 1e-6f);
  const float inv1 = 1.f / fmaxf(den1r, 1e-6f);
#pragma unroll
  for (int nt = 0; nt < 8; ++nt) {
    const int col = nt * 8 + c2;
    const int t0 = m0 + r;
    *(__half2*)&g_a16[gb16 + (size_t)t0 * HD + col] =
        __floats2half2_rn(acc[nt][0] * inv0, acc[nt][1] * inv0);
    *(__half2*)&g_a16[gb16 + (size_t)(t0 + 8) * HD + col] =
        __floats2half2_rn(acc[nt][2] * inv1, acc[nt][3] * inv1);
  }
}

}  // namespace cf

extern "C" void kernel_launch(void* const* d_in, const int* in_sizes, int n_in,
                              void* d_out, int out_size) {
  using namespace cf;
  const float* x = (const float*)d_in[0];
  const float* Wq = (const float*)d_in[1];
  const float* bq = (const float*)d_in[2];
  const float* Wk = (const float*)d_in[3];
  const float* bk = (const float*)d_in[4];
  const float* Wv = (const float*)d_in[5];
  const float* bv = (const float*)d_in[6];
  const float* Wo = (const float*)d_in[7];
  const float* bo = (const float*)d_in[8];
  float* out = (float*)d_out;

  cudaFuncSetAttribute(gemm_1p<1>, cudaFuncAttributeMaxDynamicSharedMemorySize,
                       GEMM_SMEM);
  cudaFuncSetAttribute(gemm_1p<0>, cudaFuncAttributeMaxDynamicSharedMemorySize,
                       GEMM_SMEM);
  cudaFuncSetAttribute(chunk_stats16,
                       cudaFuncAttributeMaxDynamicSharedMemorySize, CS_SMEM);
  cudaFuncSetAttribute(attn_tc, cudaFuncAttributeMaxDynamicSharedMemorySize,
                       AT_SMEM);

  // 1) conversions (pure casts)
  conv_x<<<Mrows * DM / 4 / 256, 256>>>(x);
  wcast<<<dim3(1024 * 1024 / 4 / 256, 4), 256>>>(Wq, Wk, Wv, Wo);

  // 2) fused QKV projection
  dim3 gq(HD / 128, Mrows / 128, 3);
  gemm_1p<1><<<gq, 256, GEMM_SMEM>>>(bq, bk, bv, nullptr);

  // 3) attention
  chunk_stats16<<<BHc * NCH, 128, CS_SMEM>>>();
  chunk_scan2<<<dim3(16, 32), 256>>>();
  attn_tc<<<BHc * NCH, 256, AT_SMEM>>>();

  // 4) output projection
  dim3 go(HD / 128, Mrows / 128);
  gemm_1p<0><<<go, 256, GEMM_SMEM>>>(bo, nullptr, nullptr, out);
}

// round 15
// speedup vs baseline: 7.1220x; 1.0697x over previous
#include <cuda_runtime.h>
#include <cuda_fp16.h>
#include <math.h>
#include <stdint.h>

// ============================================================================
// CosFormer attention (sm_103 base; legacy HMMA mma.sync).
//  All heavy math on tensor cores (fp16, fp32 accum):
//   - QKV + out-proj GEMMs: B in natural [K][N] layout (ldsm.trans), 2 CTA/SM.
//   - chunk_stats: S = K16^T V16.
//   - attn_tc: P = Qp Kp^T with register-resident acc->A-operand reuse
//     (no A smem round-trip), then [A|Qc|Qs] @ [V;Sc;Ss | 1;zc;zs] with
//     den as the 65th output column and triangular k-tile skipping.
// ============================================================================

namespace cf {

constexpr int Bc = 2, Tc = 4096, Hc = 16, DHc = 64;
constexpr int DM = 1024, HD = 1024;
constexpr int Mrows = Bc * Tc;            // 8192
constexpr int CH = 128, NCH = Tc / CH;    // 128, 32
constexpr int BHc = Bc * Hc;              // 32
constexpr float ANGC = 3.14159265358979323846f / (2.0f * (float)Tc);

constexpr int KDIM = 1024;
constexpr int KT = 64;
constexpr int NKT = KDIM / KT;            // 16

// ---- fp32 scratch ----
__device__ __align__(16) float g_Scos[(size_t)BHc * NCH * DHc * DHc];
__device__ __align__(16) float g_Ssin[(size_t)BHc * NCH * DHc * DHc];
__device__ __align__(16) float g_zcos[(size_t)BHc * NCH * DHc];
__device__ __align__(16) float g_zsin[(size_t)BHc * NCH * DHc];

// ---- fp16 operands ----
__device__ __align__(16) __half g_x16[(size_t)Mrows * DM];
__device__ __align__(16) __half g_Wq16[(size_t)DM * HD];   // [K][N]
__device__ __align__(16) __half g_Wk16[(size_t)DM * HD];
__device__ __align__(16) __half g_Wv16[(size_t)DM * HD];
__device__ __align__(16) __half g_Wo16[(size_t)HD * DM];
__device__ __align__(16) __half g_a16[(size_t)Mrows * HD];
__device__ __align__(16) __half g_Qp16[(size_t)Mrows * HD];
__device__ __align__(16) __half g_Kp16[(size_t)Mrows * HD];
__device__ __align__(16) __half g_Kc16[(size_t)Mrows * HD];
__device__ __align__(16) __half g_Ks16[(size_t)Mrows * HD];
__device__ __align__(16) __half g_V16[(size_t)Mrows * HD];
__device__ __align__(16) __half g_Sc16[(size_t)BHc * NCH * DHc * DHc];
__device__ __align__(16) __half g_Ss16[(size_t)BHc * NCH * DHc * DHc];

// ============================================================================
// helpers
// ============================================================================
__device__ __forceinline__ uint32_t smem_u32(const void* p) {
  uint32_t a;
  asm("{ .reg .u64 t; cvta.to.shared.u64 t, %1; cvt.u32.u64 %0, t; }"
      : "=r"(a) : "l"(p));
  return a;
}
__device__ __forceinline__ void ldsm4(uint32_t* r, uint32_t addr) {
  asm volatile(
      "ldmatrix.sync.aligned.m8n8.x4.shared.b16 {%0,%1,%2,%3}, [%4];"
      : "=r"(r[0]), "=r"(r[1]), "=r"(r[2]), "=r"(r[3]) : "r"(addr));
}
__device__ __forceinline__ void ldsm4t(uint32_t* r, uint32_t addr) {
  asm volatile(
      "ldmatrix.sync.aligned.m8n8.x4.trans.shared.b16 {%0,%1,%2,%3}, [%4];"
      : "=r"(r[0]), "=r"(r[1]), "=r"(r[2]), "=r"(r[3]) : "r"(addr));
}
__device__ __forceinline__ void mma_hf(float* d, const uint32_t* a,
                                       const uint32_t* b) {
  asm volatile(
      "mma.sync.aligned.m16n8k16.row.col.f32.f16.f16.f32 "
      "{%0,%1,%2,%3}, {%4,%5,%6,%7}, {%8,%9}, {%0,%1,%2,%3};"
      : "+f"(d[0]), "+f"(d[1]), "+f"(d[2]), "+f"(d[3])
      : "r"(a[0]), "r"(a[1]), "r"(a[2]), "r"(a[3]), "r"(b[0]), "r"(b[1]));
}
__device__ __forceinline__ void cpasync16(uint32_t dst, const void* src) {
  asm volatile("cp.async.cg.shared.global [%0], [%1], 16;"
               ::"r"(dst), "l"(src) : "memory");
}
__device__ __forceinline__ void cp_commit() {
  asm volatile("cp.async.commit_group;" ::: "memory");
}
template <int N>
__device__ __forceinline__ void cp_wait() {
  asm volatile("cp.async.wait_group %0;" ::"n"(N) : "memory");
}
__device__ __forceinline__ uint32_t pack_h2(float lo, float hi) {
  __half2 h = __floats2half2_rn(lo, hi);
  return *(uint32_t*)&h;
}
__device__ __forceinline__ uint32_t hmul2_u(uint32_t a, uint32_t s) {
  __half2 r = __hmul2(*(const __half2*)&a, *(const __half2*)&s);
  return *(uint32_t*)&r;
}

// ============================================================================
// Conversions (pure casts)
// ============================================================================
__global__ __launch_bounds__(256) void conv_x(const float* __restrict__ in) {
  int i = blockIdx.x * 256 + threadIdx.x;
  float4 v = *(const float4*)(in + (size_t)i * 4);
  __half h[4] = {__float2half(v.x), __float2half(v.y), __float2half(v.z),
                 __float2half(v.w)};
  *(uint2*)(g_x16 + (size_t)i * 4) = *(uint2*)h;
}

__global__ __launch_bounds__(256) void wcast(const float* __restrict__ Wq,
                                             const float* __restrict__ Wk,
                                             const float* __restrict__ Wv,
                                             const float* __restrict__ Wo) {
  const int w = blockIdx.y;
  const float* W = (w == 0) ? Wq : (w == 1) ? Wk : (w == 2) ? Wv : Wo;
  __half* T = (w == 0) ? g_Wq16 : (w == 1) ? g_Wk16 : (w == 2) ? g_Wv16
                                                               : g_Wo16;
  int i = blockIdx.x * 256 + threadIdx.x;
  float4 v = *(const float4*)(W + (size_t)i * 4);
  __half h[4] = {__float2half(v.x), __float2half(v.y), __float2half(v.z),
                 __float2half(v.w)};
  *(uint2*)(T + (size_t)i * 4) = *(uint2*)h;
}

// ============================================================================
// Single-pass fp16 GEMM (round-13 proven). FUSED=1: QKV.  FUSED=0: out proj.
// ============================================================================
constexpr int A_PIECE = 128 * KT * 2;            // 16384
constexpr int B_LDH = 136;
constexpr int B_PIECE = KT * B_LDH * 2;          // 17408
constexpr int STAGE_G = A_PIECE + B_PIECE;       // 33792
constexpr int GEMM_SMEM = 2 * STAGE_G;           // 67584

template <int FUSED>
__global__ __launch_bounds__(256, 2) void gemm_1p(
    const float* __restrict__ bias_q, const float* __restrict__ bias_k,
    const float* __restrict__ bias_v, float* __restrict__ outO) {
  extern __shared__ __align__(16) char smem[];
  const uint32_t sb = smem_u32(smem);
  const int tid = threadIdx.x, wid = tid >> 5, lane = tid & 31;
  const int wm = wid >> 2, wn = wid & 3;
  const int bm = blockIdx.y, bn = blockIdx.x;
  const int w = FUSED ? (int)blockIdx.z : 3;

  const __half* A = FUSED ? g_x16 : g_a16;
  const __half* Bm = (w == 0) ? g_Wq16 : (w == 1) ? g_Wk16
                       : (w == 2) ? g_Wv16 : g_Wo16;
  const float* bias = FUSED
                          ? ((w == 0) ? bias_q : (w == 1) ? bias_k : bias_v)
                          : bias_q;

  const int p = tid >> 7, q = tid & 127;
  const __half* psrcA =
      A + (size_t)bm * 128 * KDIM + (size_t)(q >> 3) * KDIM + (q & 7) * 8;
  const uint32_t aoff0 = (uint32_t)((q >> 3) * 128 + (q & 7) * 16);
  const __half* psrcB = Bm + (size_t)(q >> 4) * 1024 + bn * 128 + (q & 15) * 8;
  const uint32_t boff0 = (uint32_t)((q >> 4) * B_LDH + (q & 15) * 8) * 2;

  auto issue = [&](int kt) {
    const int buf = kt & 1;
    if (p == 0) {
      const __half* g = psrcA + kt * KT;
      const uint32_t dstbase = sb + buf * STAGE_G;
#pragma unroll
      for (int j = 0; j < 8; ++j) {
        const uint32_t off = aoff0 + j * 2048;
        const uint32_t swz = off ^ ((off >> 3) & 0x70);
        cpasync16(dstbase + swz, g + (size_t)j * 16 * KDIM);
      }
    } else {
      const __half* g = psrcB + (size_t)kt * KT * 1024;
      const uint32_t dstbase = sb + buf * STAGE_G + A_PIECE;
#pragma unroll
      for (int j = 0; j < 8; ++j)
        cpasync16(dstbase + boff0 + (uint32_t)(j * 8 * B_LDH) * 2,
                  g + (size_t)j * 8 * 1024);
    }
    cp_commit();
  };

  float acc[4][4][4];
#pragma unroll
  for (int i = 0; i < 4; ++i)
#pragma unroll
    for (int j = 0; j < 4; ++j)
#pragma unroll
      for (int k = 0; k < 4; ++k) acc[i][j][k] = 0.f;

  issue(0);
#pragma unroll 1
  for (int kt = 0; kt < NKT; ++kt) {
    if (kt + 1 < NKT) {
      issue(kt + 1);
      cp_wait<1>();
    } else {
      cp_wait<0>();
    }
    __syncthreads();
    const uint32_t base = sb + (kt & 1) * STAGE_G;
#pragma unroll
    for (int ks = 0; ks < 4; ++ks) {
      const int k0 = ks * 16;
      uint32_t a[4][4], bb[2][4];
#pragma unroll
      for (int mt = 0; mt < 4; ++mt) {
        const uint32_t row = wm * 64 + mt * 16 + (lane & 15);
        const uint32_t off = row * 128 + k0 * 2 + ((lane >> 4) << 4);
        const uint32_t swz = off ^ ((off >> 3) & 0x70);
        ldsm4(a[mt], base + swz);
      }
      const uint32_t kr =
          (uint32_t)(k0 + (lane & 7) + (((lane >> 3) & 1) << 3));
#pragma unroll
      for (int nt2 = 0; nt2 < 2; ++nt2) {
        const uint32_t nn =
            (uint32_t)(wn * 32 + nt2 * 16 + ((lane >> 4) << 3));
        ldsm4t(bb[nt2], base + A_PIECE + (kr * B_LDH + nn) * 2);
      }
#pragma unroll
      for (int mt = 0; mt < 4; ++mt)
#pragma unroll
        for (int nt = 0; nt < 4; ++nt)
          mma_hf(acc[mt][nt], a[mt], &bb[nt >> 1][(nt & 1) * 2]);
    }
    __syncthreads();
  }

  const int g = lane >> 2, t2 = (lane & 3) * 2;
#pragma unroll
  for (int mt = 0; mt < 4; ++mt) {
    const int r0 = bm * 128 + wm * 64 + mt * 16 + g;
    const int r1 = r0 + 8;
    float sn0 = 0.f, cs0 = 0.f, sn1 = 0.f, cs1 = 0.f;
    if (FUSED && w == 1) {
      sincosf(ANGC * (float)(r0 & (Tc - 1)), &sn0, &cs0);
      sincosf(ANGC * (float)(r1 & (Tc - 1)), &sn1, &cs1);
    }
#pragma unroll
    for (int nt = 0; nt < 4; ++nt) {
      const int col = bn * 128 + wn * 32 + nt * 8 + t2;
      const float b0 = __ldg(&bias[col]), b1 = __ldg(&bias[col + 1]);
      const float v00 = acc[mt][nt][0] + b0, v01 = acc[mt][nt][1] + b1;
      const float v10 = acc[mt][nt][2] + b0, v11 = acc[mt][nt][3] + b1;
      if (!FUSED) {
        *(float2*)&outO[(size_t)r0 * DM + col] = make_float2(v00, v01);
        *(float2*)&outO[(size_t)r1 * DM + col] = make_float2(v10, v11);
      } else if (w == 2) {
        *(__half2*)&g_V16[(size_t)r0 * HD + col] = __floats2half2_rn(v00, v01);
        *(__half2*)&g_V16[(size_t)r1 * HD + col] = __floats2half2_rn(v10, v11);
      } else if (w == 0) {
        *(__half2*)&g_Qp16[(size_t)r0 * HD + col] =
            __floats2half2_rn(fmaxf(v00, 0.f), fmaxf(v01, 0.f));
        *(__half2*)&g_Qp16[(size_t)r1 * HD + col] =
            __floats2half2_rn(fmaxf(v10, 0.f), fmaxf(v11, 0.f));
      } else {
        const float a00 = fmaxf(v00, 0.f), a01 = fmaxf(v01, 0.f);
        const float a10 = fmaxf(v10, 0.f), a11 = fmaxf(v11, 0.f);
        *(__half2*)&g_Kp16[(size_t)r0 * HD + col] = __floats2half2_rn(a00, a01);
        *(__half2*)&g_Kp16[(size_t)r1 * HD + col] = __floats2half2_rn(a10, a11);
        *(__half2*)&g_Kc16[(size_t)r0 * HD + col] =
            __floats2half2_rn(a00 * cs0, a01 * cs0);
        *(__half2*)&g_Kc16[(size_t)r1 * HD + col] =
            __floats2half2_rn(a10 * cs1, a11 * cs1);
        *(__half2*)&g_Ks16[(size_t)r0 * HD + col] =
            __floats2half2_rn(a00 * sn0, a01 * sn0);
        *(__half2*)&g_Ks16[(size_t)r1 * HD + col] =
            __floats2half2_rn(a10 * sn1, a11 * sn1);
      }
    }
  }
}

// ============================================================================
// Pass A (tensor cores): per-chunk states (unchanged)
// ============================================================================
constexpr int CS_LDH = 72;
constexpr int CS_OP = 128 * CS_LDH * 2;
constexpr int CS_SMEM = 3 * CS_OP;

__global__ __launch_bounds__(128, 4) void chunk_stats16() {
  extern __shared__ __align__(16) char smem[];
  const uint32_t sb = smem_u32(smem);
  const int blk = blockIdx.x;
  const int c = blk & (NCH - 1);
  const int bh = blk >> 5;
  const int b = bh >> 4, h = bh & 15;
  const int tid = threadIdx.x, wid = tid >> 5, lane = tid & 31;

  const size_t gb16 = ((size_t)b * Tc + (size_t)c * CH) * HD + h * DHc;
  {
    const int r = tid >> 3, cb = tid & 7;
#pragma unroll
    for (int op = 0; op < 3; ++op) {
      const __half* src =
          ((op == 0) ? g_Kc16 : (op == 1) ? g_Ks16 : g_V16) + gb16;
#pragma unroll
      for (int j = 0; j < 8; ++j) {
        const int row = r + 16 * j;
        cpasync16(sb + op * CS_OP + (uint32_t)(row * CS_LDH + cb * 8) * 2,
                  src + (size_t)row * HD + cb * 8);
      }
    }
    cp_commit();
    cp_wait<0>();
  }
  __syncthreads();

  {
    const int vec = tid >> 6, d = tid & 63;
    const __half* sK = (const __half*)(smem + vec * CS_OP);
    float z = 0.f;
#pragma unroll 4
    for (int t = 0; t < CH; ++t) z += __half2float(sK[t * CS_LDH + d]);
    const size_t zb = ((size_t)bh * NCH + c) * DHc;
    ((vec == 0) ? g_zcos : g_zsin)[zb + d] = z;
  }

  const int m0 = wid * 16;
  float accC[8][4], accS[8][4];
#pragma unroll
  for (int i = 0; i < 8; ++i)
#pragma unroll
    for (int j = 0; j < 4; ++j) {
      accC[i][j] = 0.f;
      accS[i][j] = 0.f;
    }

  const uint32_t bKc = sb, bKs = sb + CS_OP, bV = sb + 2 * CS_OP;
#pragma unroll 1
  for (int ks = 0; ks < 8; ++ks) {
    const int k0 = ks * 16;
    const uint32_t akk = (uint32_t)(k0 + (lane & 7) + ((lane >> 4) << 3));
    const uint32_t amm = (uint32_t)(m0 + (((lane >> 3) & 1) << 3));
    const uint32_t aoff = akk * (CS_LDH * 2) + amm * 2;
    uint32_t aC[4], aS[4];
    ldsm4t(aC, bKc + aoff);
    ldsm4t(aS, bKs + aoff);
    const uint32_t bkk = (uint32_t)(k0 + (lane & 7) + (((lane >> 3) & 1) << 3));
#pragma unroll
    for (int n4 = 0; n4 < 4; ++n4) {
      const uint32_t bnn = (uint32_t)(n4 * 16 + ((lane >> 4) << 3));
      uint32_t bb[4];
      ldsm4t(bb, bV + bkk * (CS_LDH * 2) + bnn * 2);
      mma_hf(accC[2 * n4], aC, &bb[0]);
      mma_hf(accC[2 * n4 + 1], aC, &bb[2]);
      mma_hf(accS[2 * n4], aS, &bb[0]);
      mma_hf(accS[2 * n4 + 1], aS, &bb[2]);
    }
  }

  const size_t sbse = ((size_t)bh * NCH + c) * (DHc * DHc);
  const int r = lane >> 2, c2 = (lane & 3) * 2;
#pragma unroll
  for (int nt = 0; nt < 8; ++nt) {
    const int col = nt * 8 + c2;
    *(float2*)&g_Scos[sbse + (size_t)(m0 + r) * 64 + col] =
        make_float2(accC[nt][0], accC[nt][1]);
    *(float2*)&g_Scos[sbse + (size_t)(m0 + r + 8) * 64 + col] =
        make_float2(accC[nt][2], accC[nt][3]);
    *(float2*)&g_Ssin[sbse + (size_t)(m0 + r) * 64 + col] =
        make_float2(accS[nt][0], accS[nt][1]);
    *(float2*)&g_Ssin[sbse + (size_t)(m0 + r + 8) * 64 + col] =
        make_float2(accS[nt][2], accS[nt][3]);
  }
}

// ============================================================================
// Pass B: exclusive prefix over chunks; emits fp16 prefix states.
// ============================================================================
__global__ __launch_bounds__(256) void chunk_scan2() {
  const int bh = blockIdx.y;
  const int e = blockIdx.x * 256 + threadIdx.x;
  {
    const size_t base = (size_t)bh * NCH * (DHc * DHc) + e;
    float ac = 0.f, as2 = 0.f;
#pragma unroll 1
    for (int c = 0; c < NCH; ++c) {
      const size_t idx = base + (size_t)c * (DHc * DHc);
      const float tc = g_Scos[idx], ts = g_Ssin[idx];
      g_Sc16[idx] = __float2half(ac);
      g_Ss16[idx] = __float2half(as2);
      ac += tc;
      as2 += ts;
    }
  }
  if (blockIdx.x == 0 && threadIdx.x < DHc) {
    const size_t zb = (size_t)bh * NCH * DHc + threadIdx.x;
    float ac = 0.f, as2 = 0.f;
#pragma unroll 1
    for (int c = 0; c < NCH; ++c) {
      const size_t idx = zb + (size_t)c * DHc;
      const float tc = g_zcos[idx], ts = g_zsin[idx];
      g_zcos[idx] = ac;
      g_zsin[idx] = as2;
      ac += tc;
      as2 += ts;
    }
  }
}

// ============================================================================
// Pass C (tensor cores, register-resident P): per-chunk output.
// ============================================================================
constexpr int AT_LDQ = 72;
constexpr int AT_LDB = 80;
constexpr int AOF_QP = 0;                           // 128*72*2 = 18432
constexpr int AOF_KP = 18432;
constexpr int AOF_B = 36864;                        // 256*80*2 = 40960
constexpr int AOF_TRC = 77824;                      // 128 f32
constexpr int AOF_TRS = 78336;
constexpr int AOF_ZC = 78848;                       // 64 f32
constexpr int AOF_ZS = 79104;
constexpr int AT_SMEM = 79360;

__global__ __launch_bounds__(256, 1) void attn_tc() {
  extern __shared__ __align__(16) char smem[];
  const uint32_t sb = smem_u32(smem);
  const int blk = blockIdx.x;
  const int c = blk & (NCH - 1);
  const int bh = blk >> 5;
  const int b = bh >> 4, h = bh & 15;
  const int tid = threadIdx.x, wid = tid >> 5, lane = tid & 31;

  float* strc = (float*)(smem + AOF_TRC);
  float* strs = (float*)(smem + AOF_TRS);
  float* szc = (float*)(smem + AOF_ZC);
  float* szs = (float*)(smem + AOF_ZS);

  const size_t gb16 = ((size_t)b * Tc + (size_t)c * CH) * HD + h * DHc;
  const size_t sbse = ((size_t)bh * NCH + c) * (DHc * DHc);
  const size_t zb = ((size_t)bh * NCH + c) * DHc;

  if (tid < CH) {
    float sn, cs;
    sincosf(ANGC * (float)(c * CH + tid), &sn, &cs);
    strc[tid] = cs;
    strs[tid] = sn;
  }
  if (tid < 64) szc[tid] = g_zcos[zb + tid];
  else if (tid < 128) szs[tid - 64] = g_zsin[zb + tid - 64];

  {
    const int r = tid >> 3, cb = tid & 7;
#pragma unroll
    for (int j = 0; j < 4; ++j) {
      const int row = r + 32 * j;
      cpasync16(sb + AOF_QP + (uint32_t)(row * AT_LDQ + cb * 8) * 2,
                g_Qp16 + gb16 + (size_t)row * HD + cb * 8);
      cpasync16(sb + AOF_KP + (uint32_t)(row * AT_LDQ + cb * 8) * 2,
                g_Kp16 + gb16 + (size_t)row * HD + cb * 8);
      cpasync16(sb + AOF_B + (uint32_t)(row * AT_LDB + cb * 8) * 2,
                g_V16 + gb16 + (size_t)row * HD + cb * 8);
    }
#pragma unroll
    for (int j = 0; j < 2; ++j) {
      const int row = r + 32 * j;
      cpasync16(sb + AOF_B + (uint32_t)((row + 128) * AT_LDB + cb * 8) * 2,
                g_Sc16 + sbse + (size_t)row * 64 + cb * 8);
      cpasync16(sb + AOF_B + (uint32_t)((row + 192) * AT_LDB + cb * 8) * 2,
                g_Ss16 + sbse + (size_t)row * 64 + cb * 8);
    }
    cp_commit();
    cp_wait<0>();
  }
  __syncthreads();

  // fill B cols 64..79 (col 64 = 1 / zc / zs, rest 0)
  {
    const int row = tid;
    float cv = (row < 128) ? 1.f
               : (row < 192) ? szc[row - 128] : szs[row - 192];
    __half hv[8] = {__float2half(cv), __half(0), __half(0), __half(0),
                    __half(0), __half(0), __half(0), __half(0)};
    *(uint4*)(smem + AOF_B + (uint32_t)(row * AT_LDB + 64) * 2) = *(uint4*)hv;
    uint4 z4 = make_uint4(0, 0, 0, 0);
    *(uint4*)(smem + AOF_B + (uint32_t)(row * AT_LDB + 72) * 2) = z4;
  }
  __syncthreads();

  const int m0 = wid * 16;
  const int r = lane >> 2, tg2 = (lane & 3) * 2;
  const int t0r = m0 + r, t1r = t0r + 8;
  const float ct0 = strc[t0r], st0 = strs[t0r];
  const float ct1 = strc[t1r], st1 = strs[t1r];

  // Qp A-fragments (k = 0..63)
  uint32_t qa[4][4];
#pragma unroll
  for (int ks = 0; ks < 4; ++ks) {
    const uint32_t row = (uint32_t)(m0 + (lane & 15));
    const uint32_t off = row * (AT_LDQ * 2) + ks * 32 + ((lane >> 4) << 4);
    ldsm4(qa[ks], sb + AOF_QP + off);
  }

  // ---- phase 1: P fragments, register-resident ----
  uint32_t pa[8][4];
#pragma unroll
  for (int nt2 = 0; nt2 < 8; ++nt2) {
    if (nt2 <= wid) {
      uint32_t bbf[4][4];
#pragma unroll
      for (int ks = 0; ks < 4; ++ks) {
        const uint32_t row =
            (uint32_t)(nt2 * 16 + (lane & 7) + ((lane >> 4) << 3));
        const uint32_t off =
            row * (AT_LDQ * 2) + ks * 32 + (((lane >> 3) & 1) << 4);
        ldsm4(bbf[ks], sb + AOF_KP + off);
      }
      float pacc[2][4] = {};
#pragma unroll
      for (int ks = 0; ks < 4; ++ks) {
        mma_hf(pacc[0], qa[ks], &bbf[ks][0]);
        mma_hf(pacc[1], qa[ks], &bbf[ks][2]);
      }
#pragma unroll
      for (int ntl = 0; ntl < 2; ++ntl) {
        const int s0 = nt2 * 16 + ntl * 8 + tg2;
        const float cs0 = strc[s0], ss0 = strs[s0];
        const float cs1 = strc[s0 + 1], ss1 = strs[s0 + 1];
        const float w00 = (s0 <= t0r) ? (ct0 * cs0 + st0 * ss0) : 0.f;
        const float w01 = (s0 + 1 <= t0r) ? (ct0 * cs1 + st0 * ss1) : 0.f;
        const float w10 = (s0 <= t1r) ? (ct1 * cs0 + st1 * ss0) : 0.f;
        const float w11 = (s0 + 1 <= t1r) ? (ct1 * cs1 + st1 * ss1) : 0.f;
        pa[nt2][ntl * 2] = pack_h2(w00 * pacc[ntl][0], w01 * pacc[ntl][1]);
        pa[nt2][ntl * 2 + 1] =
            pack_h2(w10 * pacc[ntl][2], w11 * pacc[ntl][3]);
      }
    }
  }

  // ---- phase 2: acc over [A | Qc | Qs] @ B ----
  float acc[9][4];
#pragma unroll
  for (int i = 0; i < 9; ++i)
#pragma unroll
    for (int j = 0; j < 4; ++j) acc[i][j] = 0.f;

  auto do_btile = [&](const uint32_t* afrag, uint32_t krow_base) {
    const uint32_t kr =
        krow_base + (uint32_t)((lane & 7) + (((lane >> 3) & 1) << 3));
    uint32_t bbf[5][4];
#pragma unroll
    for (int g = 0; g < 5; ++g) {
      const uint32_t nn = (uint32_t)(g * 16 + ((lane >> 4) << 3));
      ldsm4t(bbf[g], sb + AOF_B + (kr * AT_LDB + nn) * 2);
    }
#pragma unroll
    for (int nt = 0; nt < 9; ++nt)
      mma_hf(acc[nt], afrag, &bbf[nt >> 1][(nt & 1) * 2]);
  };

  // A part (causal: only k-tiles 0..wid are nonzero)
#pragma unroll
  for (int kt2 = 0; kt2 < 8; ++kt2)
    if (kt2 <= wid) do_btile(pa[kt2], (uint32_t)(kt2 * 16));

  // Qc part (B rows 128..191) and Qs part (192..255).
  // Row scaling: a0/a2 live on row r (ct0/st0), a1/a3 on row r+8 (ct1/st1).
  const uint32_t hc0 = pack_h2(ct0, ct0), hc1 = pack_h2(ct1, ct1);
  const uint32_t hs0 = pack_h2(st0, st0), hs1 = pack_h2(st1, st1);
#pragma unroll
  for (int kc = 0; kc < 4; ++kc) {
    uint32_t qcf[4] = {hmul2_u(qa[kc][0], hc0), hmul2_u(qa[kc][1], hc1),
                       hmul2_u(qa[kc][2], hc0), hmul2_u(qa[kc][3], hc1)};
    do_btile(qcf, (uint32_t)(128 + kc * 16));
  }
#pragma unroll
  for (int kc = 0; kc < 4; ++kc) {
    uint32_t qsf[4] = {hmul2_u(qa[kc][0], hs0), hmul2_u(qa[kc][1], hs1),
                       hmul2_u(qa[kc][2], hs0), hmul2_u(qa[kc][3], hs1)};
    do_btile(qsf, (uint32_t)(192 + kc * 16));
  }

  // ---- epilogue: den = col 64 ----
  const float den0r = __shfl_sync(0xffffffffu, acc[8][0], lane & ~3);
  const float den1r = __shfl_sync(0xffffffffu, acc[8][2], lane & ~3);
  const float inv0 = 1.f / fmaxf(den0r, 1e-6f);
  const float inv1 = 1.f / fmaxf(den1r, 1e-6f);
#pragma unroll
  for (int nt = 0; nt < 8; ++nt) {
    const int col = nt * 8 + tg2;
    *(__half2*)&g_a16[gb16 + (size_t)t0r * HD + col] =
        __floats2half2_rn(acc[nt][0] * inv0, acc[nt][1] * inv0);
    *(__half2*)&g_a16[gb16 + (size_t)t1r * HD + col] =
        __floats2half2_rn(acc[nt][2] * inv1, acc[nt][3] * inv1);
  }
}

}  // namespace cf

extern "C" void kernel_launch(void* const* d_in, const int* in_sizes, int n_in,
                              void* d_out, int out_size) {
  using namespace cf;
  const float* x = (const float*)d_in[0];
  const float* Wq = (const float*)d_in[1];
  const float* bq = (const float*)d_in[2];
  const float* Wk = (const float*)d_in[3];
  const float* bk = (const float*)d_in[4];
  const float* Wv = (const float*)d_in[5];
  const float* bv = (const float*)d_in[6];
  const float* Wo = (const float*)d_in[7];
  const float* bo = (const float*)d_in[8];
  float* out = (float*)d_out;

  cudaFuncSetAttribute(gemm_1p<1>, cudaFuncAttributeMaxDynamicSharedMemorySize,
                       GEMM_SMEM);
  cudaFuncSetAttribute(gemm_1p<0>, cudaFuncAttributeMaxDynamicSharedMemorySize,
                       GEMM_SMEM);
  cudaFuncSetAttribute(chunk_stats16,
                       cudaFuncAttributeMaxDynamicSharedMemorySize, CS_SMEM);
  cudaFuncSetAttribute(attn_tc, cudaFuncAttributeMaxDynamicSharedMemorySize,
                       AT_SMEM);

  // 1) conversions
  conv_x<<<Mrows * DM / 4 / 256, 256>>>(x);
  wcast<<<dim3(1024 * 1024 / 4 / 256, 4), 256>>>(Wq, Wk, Wv, Wo);

  // 2) fused QKV projection
  dim3 gq(HD / 128, Mrows / 128, 3);
  gemm_1p<1><<<gq, 256, GEMM_SMEM>>>(bq, bk, bv, nullptr);

  // 3) attention
  chunk_stats16<<<BHc * NCH, 128, CS_SMEM>>>();
  chunk_scan2<<<dim3(16, 32), 256>>>();
  attn_tc<<<BHc * NCH, 256, AT_SMEM>>>();

  // 4) output projection
  dim3 go(HD / 128, Mrows / 128);
  gemm_1p<0><<<go, 256, GEMM_SMEM>>>(bo, nullptr, nullptr, out);
}

// round 16
// speedup vs baseline: 7.2122x; 1.0127x over previous
#include <cuda_runtime.h>
#include <cuda_fp16.h>
#include <math.h>
#include <stdint.h>

// ============================================================================
// CosFormer attention (sm_103 base; legacy HMMA mma.sync).
//  All heavy math on tensor cores (fp16, fp32 accum):
//   - QKV + out-proj GEMMs: B in natural [K][N] layout (ldsm.trans), 2 CTA/SM.
//   - chunk_stats: S = K16^T V16.
//   - attn_tc: register-resident P = Qp Kp^T -> [A|Qc|Qs] @ [V;Sc;Ss|1;zc;zs],
//     den as 65th output column, causal k-tile skipping; 2 CTA/SM.
//  Round 16: merged conversion launch, attn_tc occupancy 2, scan regrid.
// ============================================================================

namespace cf {

constexpr int Bc = 2, Tc = 4096, Hc = 16, DHc = 64;
constexpr int DM = 1024, HD = 1024;
constexpr int Mrows = Bc * Tc;            // 8192
constexpr int CH = 128, NCH = Tc / CH;    // 128, 32
constexpr int BHc = Bc * Hc;              // 32
constexpr float ANGC = 3.14159265358979323846f / (2.0f * (float)Tc);

constexpr int KDIM = 1024;
constexpr int KT = 64;
constexpr int NKT = KDIM / KT;            // 16

// ---- fp32 scratch ----
__device__ __align__(16) float g_Scos[(size_t)BHc * NCH * DHc * DHc];
__device__ __align__(16) float g_Ssin[(size_t)BHc * NCH * DHc * DHc];
__device__ __align__(16) float g_zcos[(size_t)BHc * NCH * DHc];
__device__ __align__(16) float g_zsin[(size_t)BHc * NCH * DHc];

// ---- fp16 operands ----
__device__ __align__(16) __half g_x16[(size_t)Mrows * DM];
__device__ __align__(16) __half g_Wq16[(size_t)DM * HD];   // [K][N]
__device__ __align__(16) __half g_Wk16[(size_t)DM * HD];
__device__ __align__(16) __half g_Wv16[(size_t)DM * HD];
__device__ __align__(16) __half g_Wo16[(size_t)HD * DM];
__device__ __align__(16) __half g_a16[(size_t)Mrows * HD];
__device__ __align__(16) __half g_Qp16[(size_t)Mrows * HD];
__device__ __align__(16) __half g_Kp16[(size_t)Mrows * HD];
__device__ __align__(16) __half g_Kc16[(size_t)Mrows * HD];
__device__ __align__(16) __half g_Ks16[(size_t)Mrows * HD];
__device__ __align__(16) __half g_V16[(size_t)Mrows * HD];
__device__ __align__(16) __half g_Sc16[(size_t)BHc * NCH * DHc * DHc];
__device__ __align__(16) __half g_Ss16[(size_t)BHc * NCH * DHc * DHc];

// ============================================================================
// helpers
// ============================================================================
__device__ __forceinline__ uint32_t smem_u32(const void* p) {
  uint32_t a;
  asm("{ .reg .u64 t; cvta.to.shared.u64 t, %1; cvt.u32.u64 %0, t; }"
      : "=r"(a) : "l"(p));
  return a;
}
__device__ __forceinline__ void ldsm4(uint32_t* r, uint32_t addr) {
  asm volatile(
      "ldmatrix.sync.aligned.m8n8.x4.shared.b16 {%0,%1,%2,%3}, [%4];"
      : "=r"(r[0]), "=r"(r[1]), "=r"(r[2]), "=r"(r[3]) : "r"(addr));
}
__device__ __forceinline__ void ldsm4t(uint32_t* r, uint32_t addr) {
  asm volatile(
      "ldmatrix.sync.aligned.m8n8.x4.trans.shared.b16 {%0,%1,%2,%3}, [%4];"
      : "=r"(r[0]), "=r"(r[1]), "=r"(r[2]), "=r"(r[3]) : "r"(addr));
}
__device__ __forceinline__ void mma_hf(float* d, const uint32_t* a,
                                       const uint32_t* b) {
  asm volatile(
      "mma.sync.aligned.m16n8k16.row.col.f32.f16.f16.f32 "
      "{%0,%1,%2,%3}, {%4,%5,%6,%7}, {%8,%9}, {%0,%1,%2,%3};"
      : "+f"(d[0]), "+f"(d[1]), "+f"(d[2]), "+f"(d[3])
      : "r"(a[0]), "r"(a[1]), "r"(a[2]), "r"(a[3]), "r"(b[0]), "r"(b[1]));
}
__device__ __forceinline__ void cpasync16(uint32_t dst, const void* src) {
  asm volatile("cp.async.cg.shared.global [%0], [%1], 16;"
               ::"r"(dst), "l"(src) : "memory");
}
__device__ __forceinline__ void cp_commit() {
  asm volatile("cp.async.commit_group;" ::: "memory");
}
template <int N>
__device__ __forceinline__ void cp_wait() {
  asm volatile("cp.async.wait_group %0;" ::"n"(N) : "memory");
}
__device__ __forceinline__ uint32_t pack_h2(float lo, float hi) {
  __half2 h = __floats2half2_rn(lo, hi);
  return *(uint32_t*)&h;
}
__device__ __forceinline__ uint32_t hmul2_u(uint32_t a, uint32_t s) {
  __half2 r = __hmul2(*(const __half2*)&a, *(const __half2*)&s);
  return *(uint32_t*)&r;
}

// ============================================================================
// Conversions: one launch.  Blocks [0,8192): x.  Then 1024-block bands for
// Wq, Wk, Wv, Wo (each 1024x1024 fp32 -> fp16, coalesced cast).
// ============================================================================
constexpr int XBLK = Mrows * DM / 4 / 256;        // 8192
constexpr int WBLK = 1024 * 1024 / 4 / 256;       // 1024

__global__ __launch_bounds__(256) void conv_all(const float* __restrict__ x,
                                                const float* __restrict__ Wq,
                                                const float* __restrict__ Wk,
                                                const float* __restrict__ Wv,
                                                const float* __restrict__ Wo) {
  const int blk = blockIdx.x;
  const float* src;
  __half* dst;
  int i;
  if (blk < XBLK) {
    src = x;
    dst = g_x16;
    i = blk * 256 + threadIdx.x;
  } else {
    const int w = (blk - XBLK) / WBLK;
    const int bi = (blk - XBLK) - w * WBLK;
    src = (w == 0) ? Wq : (w == 1) ? Wk : (w == 2) ? Wv : Wo;
    dst = (w == 0) ? g_Wq16 : (w == 1) ? g_Wk16 : (w == 2) ? g_Wv16 : g_Wo16;
    i = bi * 256 + threadIdx.x;
  }
  float4 v = *(const float4*)(src + (size_t)i * 4);
  __half h[4] = {__float2half(v.x), __float2half(v.y), __float2half(v.z),
                 __float2half(v.w)};
  *(uint2*)(dst + (size_t)i * 4) = *(uint2*)h;
}

// ============================================================================
// Single-pass fp16 GEMM (round-13 proven). FUSED=1: QKV.  FUSED=0: out proj.
// ============================================================================
constexpr int A_PIECE = 128 * KT * 2;            // 16384
constexpr int B_LDH = 136;
constexpr int B_PIECE = KT * B_LDH * 2;          // 17408
constexpr int STAGE_G = A_PIECE + B_PIECE;       // 33792
constexpr int GEMM_SMEM = 2 * STAGE_G;           // 67584

template <int FUSED>
__global__ __launch_bounds__(256, 2) void gemm_1p(
    const float* __restrict__ bias_q, const float* __restrict__ bias_k,
    const float* __restrict__ bias_v, float* __restrict__ outO) {
  extern __shared__ __align__(16) char smem[];
  const uint32_t sb = smem_u32(smem);
  const int tid = threadIdx.x, wid = tid >> 5, lane = tid & 31;
  const int wm = wid >> 2, wn = wid & 3;
  const int bm = blockIdx.y, bn = blockIdx.x;
  const int w = FUSED ? (int)blockIdx.z : 3;

  const __half* A = FUSED ? g_x16 : g_a16;
  const __half* Bm = (w == 0) ? g_Wq16 : (w == 1) ? g_Wk16
                       : (w == 2) ? g_Wv16 : g_Wo16;
  const float* bias = FUSED
                          ? ((w == 0) ? bias_q : (w == 1) ? bias_k : bias_v)
                          : bias_q;

  const int p = tid >> 7, q = tid & 127;
  const __half* psrcA =
      A + (size_t)bm * 128 * KDIM + (size_t)(q >> 3) * KDIM + (q & 7) * 8;
  const uint32_t aoff0 = (uint32_t)((q >> 3) * 128 + (q & 7) * 16);
  const __half* psrcB = Bm + (size_t)(q >> 4) * 1024 + bn * 128 + (q & 15) * 8;
  const uint32_t boff0 = (uint32_t)((q >> 4) * B_LDH + (q & 15) * 8) * 2;

  auto issue = [&](int kt) {
    const int buf = kt & 1;
    if (p == 0) {
      const __half* g = psrcA + kt * KT;
      const uint32_t dstbase = sb + buf * STAGE_G;
#pragma unroll
      for (int j = 0; j < 8; ++j) {
        const uint32_t off = aoff0 + j * 2048;
        const uint32_t swz = off ^ ((off >> 3) & 0x70);
        cpasync16(dstbase + swz, g + (size_t)j * 16 * KDIM);
      }
    } else {
      const __half* g = psrcB + (size_t)kt * KT * 1024;
      const uint32_t dstbase = sb + buf * STAGE_G + A_PIECE;
#pragma unroll
      for (int j = 0; j < 8; ++j)
        cpasync16(dstbase + boff0 + (uint32_t)(j * 8 * B_LDH) * 2,
                  g + (size_t)j * 8 * 1024);
    }
    cp_commit();
  };

  float acc[4][4][4];
#pragma unroll
  for (int i = 0; i < 4; ++i)
#pragma unroll
    for (int j = 0; j < 4; ++j)
#pragma unroll
      for (int k = 0; k < 4; ++k) acc[i][j][k] = 0.f;

  issue(0);
#pragma unroll 1
  for (int kt = 0; kt < NKT; ++kt) {
    if (kt + 1 < NKT) {
      issue(kt + 1);
      cp_wait<1>();
    } else {
      cp_wait<0>();
    }
    __syncthreads();
    const uint32_t base = sb + (kt & 1) * STAGE_G;
#pragma unroll
    for (int ks = 0; ks < 4; ++ks) {
      const int k0 = ks * 16;
      uint32_t a[4][4], bb[2][4];
#pragma unroll
      for (int mt = 0; mt < 4; ++mt) {
        const uint32_t row = wm * 64 + mt * 16 + (lane & 15);
        const uint32_t off = row * 128 + k0 * 2 + ((lane >> 4) << 4);
        const uint32_t swz = off ^ ((off >> 3) & 0x70);
        ldsm4(a[mt], base + swz);
      }
      const uint32_t kr =
          (uint32_t)(k0 + (lane & 7) + (((lane >> 3) & 1) << 3));
#pragma unroll
      for (int nt2 = 0; nt2 < 2; ++nt2) {
        const uint32_t nn =
            (uint32_t)(wn * 32 + nt2 * 16 + ((lane >> 4) << 3));
        ldsm4t(bb[nt2], base + A_PIECE + (kr * B_LDH + nn) * 2);
      }
#pragma unroll
      for (int mt = 0; mt < 4; ++mt)
#pragma unroll
        for (int nt = 0; nt < 4; ++nt)
          mma_hf(acc[mt][nt], a[mt], &bb[nt >> 1][(nt & 1) * 2]);
    }
    __syncthreads();
  }

  const int g = lane >> 2, t2 = (lane & 3) * 2;
#pragma unroll
  for (int mt = 0; mt < 4; ++mt) {
    const int r0 = bm * 128 + wm * 64 + mt * 16 + g;
    const int r1 = r0 + 8;
    float sn0 = 0.f, cs0 = 0.f, sn1 = 0.f, cs1 = 0.f;
    if (FUSED && w == 1) {
      sincosf(ANGC * (float)(r0 & (Tc - 1)), &sn0, &cs0);
      sincosf(ANGC * (float)(r1 & (Tc - 1)), &sn1, &cs1);
    }
#pragma unroll
    for (int nt = 0; nt < 4; ++nt) {
      const int col = bn * 128 + wn * 32 + nt * 8 + t2;
      const float b0 = __ldg(&bias[col]), b1 = __ldg(&bias[col + 1]);
      const float v00 = acc[mt][nt][0] + b0, v01 = acc[mt][nt][1] + b1;
      const float v10 = acc[mt][nt][2] + b0, v11 = acc[mt][nt][3] + b1;
      if (!FUSED) {
        *(float2*)&outO[(size_t)r0 * DM + col] = make_float2(v00, v01);
        *(float2*)&outO[(size_t)r1 * DM + col] = make_float2(v10, v11);
      } else if (w == 2) {
        *(__half2*)&g_V16[(size_t)r0 * HD + col] = __floats2half2_rn(v00, v01);
        *(__half2*)&g_V16[(size_t)r1 * HD + col] = __floats2half2_rn(v10, v11);
      } else if (w == 0) {
        *(__half2*)&g_Qp16[(size_t)r0 * HD + col] =
            __floats2half2_rn(fmaxf(v00, 0.f), fmaxf(v01, 0.f));
        *(__half2*)&g_Qp16[(size_t)r1 * HD + col] =
            __floats2half2_rn(fmaxf(v10, 0.f), fmaxf(v11, 0.f));
      } else {
        const float a00 = fmaxf(v00, 0.f), a01 = fmaxf(v01, 0.f);
        const float a10 = fmaxf(v10, 0.f), a11 = fmaxf(v11, 0.f);
        *(__half2*)&g_Kp16[(size_t)r0 * HD + col] = __floats2half2_rn(a00, a01);
        *(__half2*)&g_Kp16[(size_t)r1 * HD + col] = __floats2half2_rn(a10, a11);
        *(__half2*)&g_Kc16[(size_t)r0 * HD + col] =
            __floats2half2_rn(a00 * cs0, a01 * cs0);
        *(__half2*)&g_Kc16[(size_t)r1 * HD + col] =
            __floats2half2_rn(a10 * cs1, a11 * cs1);
        *(__half2*)&g_Ks16[(size_t)r0 * HD + col] =
            __floats2half2_rn(a00 * sn0, a01 * sn0);
        *(__half2*)&g_Ks16[(size_t)r1 * HD + col] =
            __floats2half2_rn(a10 * sn1, a11 * sn1);
      }
    }
  }
}

// ============================================================================
// Pass A (tensor cores): per-chunk states
// ============================================================================
constexpr int CS_LDH = 72;
constexpr int CS_OP = 128 * CS_LDH * 2;
constexpr int CS_SMEM = 3 * CS_OP;

__global__ __launch_bounds__(128, 4) void chunk_stats16() {
  extern __shared__ __align__(16) char smem[];
  const uint32_t sb = smem_u32(smem);
  const int blk = blockIdx.x;
  const int c = blk & (NCH - 1);
  const int bh = blk >> 5;
  const int b = bh >> 4, h = bh & 15;
  const int tid = threadIdx.x, wid = tid >> 5, lane = tid & 31;

  const size_t gb16 = ((size_t)b * Tc + (size_t)c * CH) * HD + h * DHc;
  {
    const int r = tid >> 3, cb = tid & 7;
#pragma unroll
    for (int op = 0; op < 3; ++op) {
      const __half* src =
          ((op == 0) ? g_Kc16 : (op == 1) ? g_Ks16 : g_V16) + gb16;
#pragma unroll
      for (int j = 0; j < 8; ++j) {
        const int row = r + 16 * j;
        cpasync16(sb + op * CS_OP + (uint32_t)(row * CS_LDH + cb * 8) * 2,
                  src + (size_t)row * HD + cb * 8);
      }
    }
    cp_commit();
    cp_wait<0>();
  }
  __syncthreads();

  {
    const int vec = tid >> 6, d = tid & 63;
    const __half* sK = (const __half*)(smem + vec * CS_OP);
    float z = 0.f;
#pragma unroll 4
    for (int t = 0; t < CH; ++t) z += __half2float(sK[t * CS_LDH + d]);
    const size_t zb = ((size_t)bh * NCH + c) * DHc;
    ((vec == 0) ? g_zcos : g_zsin)[zb + d] = z;
  }

  const int m0 = wid * 16;
  float accC[8][4], accS[8][4];
#pragma unroll
  for (int i = 0; i < 8; ++i)
#pragma unroll
    for (int j = 0; j < 4; ++j) {
      accC[i][j] = 0.f;
      accS[i][j] = 0.f;
    }

  const uint32_t bKc = sb, bKs = sb + CS_OP, bV = sb + 2 * CS_OP;
#pragma unroll 1
  for (int ks = 0; ks < 8; ++ks) {
    const int k0 = ks * 16;
    const uint32_t akk = (uint32_t)(k0 + (lane & 7) + ((lane >> 4) << 3));
    const uint32_t amm = (uint32_t)(m0 + (((lane >> 3) & 1) << 3));
    const uint32_t aoff = akk * (CS_LDH * 2) + amm * 2;
    uint32_t aC[4], aS[4];
    ldsm4t(aC, bKc + aoff);
    ldsm4t(aS, bKs + aoff);
    const uint32_t bkk = (uint32_t)(k0 + (lane & 7) + (((lane >> 3) & 1) << 3));
#pragma unroll
    for (int n4 = 0; n4 < 4; ++n4) {
      const uint32_t bnn = (uint32_t)(n4 * 16 + ((lane >> 4) << 3));
      uint32_t bb[4];
      ldsm4t(bb, bV + bkk * (CS_LDH * 2) + bnn * 2);
      mma_hf(accC[2 * n4], aC, &bb[0]);
      mma_hf(accC[2 * n4 + 1], aC, &bb[2]);
      mma_hf(accS[2 * n4], aS, &bb[0]);
      mma_hf(accS[2 * n4 + 1], aS, &bb[2]);
    }
  }

  const size_t sbse = ((size_t)bh * NCH + c) * (DHc * DHc);
  const int r = lane >> 2, c2 = (lane & 3) * 2;
#pragma unroll
  for (int nt = 0; nt < 8; ++nt) {
    const int col = nt * 8 + c2;
    *(float2*)&g_Scos[sbse + (size_t)(m0 + r) * 64 + col] =
        make_float2(accC[nt][0], accC[nt][1]);
    *(float2*)&g_Scos[sbse + (size_t)(m0 + r + 8) * 64 + col] =
        make_float2(accC[nt][2], accC[nt][3]);
    *(float2*)&g_Ssin[sbse + (size_t)(m0 + r) * 64 + col] =
        make_float2(accS[nt][0], accS[nt][1]);
    *(float2*)&g_Ssin[sbse + (size_t)(m0 + r + 8) * 64 + col] =
        make_float2(accS[nt][2], accS[nt][3]);
  }
}

// ============================================================================
// Pass B: exclusive prefix over chunks; emits fp16 prefix states.
// ============================================================================
__global__ __launch_bounds__(128) void chunk_scan2() {
  const int bh = blockIdx.y;
  const int e = blockIdx.x * 128 + threadIdx.x;
  {
    const size_t base = (size_t)bh * NCH * (DHc * DHc) + e;
    float ac = 0.f, as2 = 0.f;
#pragma unroll 1
    for (int c = 0; c < NCH; ++c) {
      const size_t idx = base + (size_t)c * (DHc * DHc);
      const float tc = g_Scos[idx], ts = g_Ssin[idx];
      g_Sc16[idx] = __float2half(ac);
      g_Ss16[idx] = __float2half(as2);
      ac += tc;
      as2 += ts;
    }
  }
  if (blockIdx.x == 0 && threadIdx.x < DHc) {
    const size_t zb = (size_t)bh * NCH * DHc + threadIdx.x;
    float ac = 0.f, as2 = 0.f;
#pragma unroll 1
    for (int c = 0; c < NCH; ++c) {
      const size_t idx = zb + (size_t)c * DHc;
      const float tc = g_zcos[idx], ts = g_zsin[idx];
      g_zcos[idx] = ac;
      g_zsin[idx] = as2;
      ac += tc;
      as2 += ts;
    }
  }
}

// ============================================================================
// Pass C (tensor cores, register-resident P): per-chunk output; 2 CTA/SM.
// ============================================================================
constexpr int AT_LDQ = 72;
constexpr int AT_LDB = 80;
constexpr int AOF_QP = 0;                           // 128*72*2 = 18432
constexpr int AOF_KP = 18432;
constexpr int AOF_B = 36864;                        // 256*80*2 = 40960
constexpr int AOF_TRC = 77824;                      // 128 f32
constexpr int AOF_TRS = 78336;
constexpr int AOF_ZC = 78848;                       // 64 f32
constexpr int AOF_ZS = 79104;
constexpr int AT_SMEM = 79360;

__global__ __launch_bounds__(256, 2) void attn_tc() {
  extern __shared__ __align__(16) char smem[];
  const uint32_t sb = smem_u32(smem);
  const int blk = blockIdx.x;
  const int c = blk & (NCH - 1);
  const int bh = blk >> 5;
  const int b = bh >> 4, h = bh & 15;
  const int tid = threadIdx.x, wid = tid >> 5, lane = tid & 31;

  float* strc = (float*)(smem + AOF_TRC);
  float* strs = (float*)(smem + AOF_TRS);
  float* szc = (float*)(smem + AOF_ZC);
  float* szs = (float*)(smem + AOF_ZS);

  const size_t gb16 = ((size_t)b * Tc + (size_t)c * CH) * HD + h * DHc;
  const size_t sbse = ((size_t)bh * NCH + c) * (DHc * DHc);
  const size_t zb = ((size_t)bh * NCH + c) * DHc;

  if (tid < CH) {
    float sn, cs;
    sincosf(ANGC * (float)(c * CH + tid), &sn, &cs);
    strc[tid] = cs;
    strs[tid] = sn;
  }
  if (tid < 64) szc[tid] = g_zcos[zb + tid];
  else if (tid < 128) szs[tid - 64] = g_zsin[zb + tid - 64];

  {
    const int r = tid >> 3, cb = tid & 7;
#pragma unroll
    for (int j = 0; j < 4; ++j) {
      const int row = r + 32 * j;
      cpasync16(sb + AOF_QP + (uint32_t)(row * AT_LDQ + cb * 8) * 2,
                g_Qp16 + gb16 + (size_t)row * HD + cb * 8);
      cpasync16(sb + AOF_KP + (uint32_t)(row * AT_LDQ + cb * 8) * 2,
                g_Kp16 + gb16 + (size_t)row * HD + cb * 8);
      cpasync16(sb + AOF_B + (uint32_t)(row * AT_LDB + cb * 8) * 2,
                g_V16 + gb16 + (size_t)row * HD + cb * 8);
    }
#pragma unroll
    for (int j = 0; j < 2; ++j) {
      const int row = r + 32 * j;
      cpasync16(sb + AOF_B + (uint32_t)((row + 128) * AT_LDB + cb * 8) * 2,
                g_Sc16 + sbse + (size_t)row * 64 + cb * 8);
      cpasync16(sb + AOF_B + (uint32_t)((row + 192) * AT_LDB + cb * 8) * 2,
                g_Ss16 + sbse + (size_t)row * 64 + cb * 8);
    }
    cp_commit();
    cp_wait<0>();
  }
  __syncthreads();

  // fill B cols 64..79 (col 64 = 1 / zc / zs, rest 0)
  {
    const int row = tid;
    float cv = (row < 128) ? 1.f
               : (row < 192) ? szc[row - 128] : szs[row - 192];
    __half hv[8] = {__float2half(cv), __half(0), __half(0), __half(0),
                    __half(0), __half(0), __half(0), __half(0)};
    *(uint4*)(smem + AOF_B + (uint32_t)(row * AT_LDB + 64) * 2) = *(uint4*)hv;
    uint4 z4 = make_uint4(0, 0, 0, 0);
    *(uint4*)(smem + AOF_B + (uint32_t)(row * AT_LDB + 72) * 2) = z4;
  }
  __syncthreads();

  const int m0 = wid * 16;
  const int r = lane >> 2, tg2 = (lane & 3) * 2;
  const int t0r = m0 + r, t1r = t0r + 8;
  const float ct0 = strc[t0r], st0 = strs[t0r];
  const float ct1 = strc[t1r], st1 = strs[t1r];

  uint32_t qa[4][4];
#pragma unroll
  for (int ks = 0; ks < 4; ++ks) {
    const uint32_t row = (uint32_t)(m0 + (lane & 15));
    const uint32_t off = row * (AT_LDQ * 2) + ks * 32 + ((lane >> 4) << 4);
    ldsm4(qa[ks], sb + AOF_QP + off);
  }

  // ---- phase 1: P fragments, register-resident ----
  uint32_t pa[8][4];
#pragma unroll
  for (int nt2 = 0; nt2 < 8; ++nt2) {
    if (nt2 <= wid) {
      uint32_t bbf[4][4];
#pragma unroll
      for (int ks = 0; ks < 4; ++ks) {
        const uint32_t row =
            (uint32_t)(nt2 * 16 + (lane & 7) + ((lane >> 4) << 3));
        const uint32_t off =
            row * (AT_LDQ * 2) + ks * 32 + (((lane >> 3) & 1) << 4);
        ldsm4(bbf[ks], sb + AOF_KP + off);
      }
      float pacc[2][4] = {};
#pragma unroll
      for (int ks = 0; ks < 4; ++ks) {
        mma_hf(pacc[0], qa[ks], &bbf[ks][0]);
        mma_hf(pacc[1], qa[ks], &bbf[ks][2]);
      }
#pragma unroll
      for (int ntl = 0; ntl < 2; ++ntl) {
        const int s0 = nt2 * 16 + ntl * 8 + tg2;
        const float cs0 = strc[s0], ss0 = strs[s0];
        const float cs1 = strc[s0 + 1], ss1 = strs[s0 + 1];
        const float w00 = (s0 <= t0r) ? (ct0 * cs0 + st0 * ss0) : 0.f;
        const float w01 = (s0 + 1 <= t0r) ? (ct0 * cs1 + st0 * ss1) : 0.f;
        const float w10 = (s0 <= t1r) ? (ct1 * cs0 + st1 * ss0) : 0.f;
        const float w11 = (s0 + 1 <= t1r) ? (ct1 * cs1 + st1 * ss1) : 0.f;
        pa[nt2][ntl * 2] = pack_h2(w00 * pacc[ntl][0], w01 * pacc[ntl][1]);
        pa[nt2][ntl * 2 + 1] =
            pack_h2(w10 * pacc[ntl][2], w11 * pacc[ntl][3]);
      }
    }
  }

  // ---- phase 2: acc over [A | Qc | Qs] @ B ----
  float acc[9][4];
#pragma unroll
  for (int i = 0; i < 9; ++i)
#pragma unroll
    for (int j = 0; j < 4; ++j) acc[i][j] = 0.f;

  auto do_btile = [&](const uint32_t* afrag, uint32_t krow_base) {
    const uint32_t kr =
        krow_base + (uint32_t)((lane & 7) + (((lane >> 3) & 1) << 3));
    uint32_t bbf[5][4];
#pragma unroll
    for (int g = 0; g < 5; ++g) {
      const uint32_t nn = (uint32_t)(g * 16 + ((lane >> 4) << 3));
      ldsm4t(bbf[g], sb + AOF_B + (kr * AT_LDB + nn) * 2);
    }
#pragma unroll
    for (int nt = 0; nt < 9; ++nt)
      mma_hf(acc[nt], afrag, &bbf[nt >> 1][(nt & 1) * 2]);
  };

#pragma unroll
  for (int kt2 = 0; kt2 < 8; ++kt2)
    if (kt2 <= wid) do_btile(pa[kt2], (uint32_t)(kt2 * 16));

  const uint32_t hc0 = pack_h2(ct0, ct0), hc1 = pack_h2(ct1, ct1);
  const uint32_t hs0 = pack_h2(st0, st0), hs1 = pack_h2(st1, st1);
#pragma unroll
  for (int kc = 0; kc < 4; ++kc) {
    uint32_t qcf[4] = {hmul2_u(qa[kc][0], hc0), hmul2_u(qa[kc][1], hc1),
                       hmul2_u(qa[kc][2], hc0), hmul2_u(qa[kc][3], hc1)};
    do_btile(qcf, (uint32_t)(128 + kc * 16));
  }
#pragma unroll
  for (int kc = 0; kc < 4; ++kc) {
    uint32_t qsf[4] = {hmul2_u(qa[kc][0], hs0), hmul2_u(qa[kc][1], hs1),
                       hmul2_u(qa[kc][2], hs0), hmul2_u(qa[kc][3], hs1)};
    do_btile(qsf, (uint32_t)(192 + kc * 16));
  }

  // ---- epilogue: den = col 64 ----
  const float den0r = __shfl_sync(0xffffffffu, acc[8][0], lane & ~3);
  const float den1r = __shfl_sync(0xffffffffu, acc[8][2], lane & ~3);
  const float inv0 = 1.f / fmaxf(den0r, 1e-6f);
  const float inv1 = 1.f / fmaxf(den1r, 1e-6f);
#pragma unroll
  for (int nt = 0; nt < 8; ++nt) {
    const int col = nt * 8 + tg2;
    *(__half2*)&g_a16[gb16 + (size_t)t0r * HD + col] =
        __floats2half2_rn(acc[nt][0] * inv0, acc[nt][1] * inv0);
    *(__half2*)&g_a16[gb16 + (size_t)t1r * HD + col] =
        __floats2half2_rn(acc[nt][2] * inv1, acc[nt][3] * inv1);
  }
}

}  // namespace cf

extern "C" void kernel_launch(void* const* d_in, const int* in_sizes, int n_in,
                              void* d_out, int out_size) {
  using namespace cf;
  const float* x = (const float*)d_in[0];
  const float* Wq = (const float*)d_in[1];
  const float* bq = (const float*)d_in[2];
  const float* Wk = (const float*)d_in[3];
  const float* bk = (const float*)d_in[4];
  const float* Wv = (const float*)d_in[5];
  const float* bv = (const float*)d_in[6];
  const float* Wo = (const float*)d_in[7];
  const float* bo = (const float*)d_in[8];
  float* out = (float*)d_out;

  cudaFuncSetAttribute(gemm_1p<1>, cudaFuncAttributeMaxDynamicSharedMemorySize,
                       GEMM_SMEM);
  cudaFuncSetAttribute(gemm_1p<0>, cudaFuncAttributeMaxDynamicSharedMemorySize,
                       GEMM_SMEM);
  cudaFuncSetAttribute(chunk_stats16,
                       cudaFuncAttributeMaxDynamicSharedMemorySize, CS_SMEM);
  cudaFuncSetAttribute(attn_tc, cudaFuncAttributeMaxDynamicSharedMemorySize,
                       AT_SMEM);

  // 1) conversions (single launch)
  conv_all<<<XBLK + 4 * WBLK, 256>>>(x, Wq, Wk, Wv, Wo);

  // 2) fused QKV projection
  dim3 gq(HD / 128, Mrows / 128, 3);
  gemm_1p<1><<<gq, 256, GEMM_SMEM>>>(bq, bk, bv, nullptr);

  // 3) attention
  chunk_stats16<<<BHc * NCH, 128, CS_SMEM>>>();
  chunk_scan2<<<dim3(32, 32), 128>>>();
  attn_tc<<<BHc * NCH, 256, AT_SMEM>>>();

  // 4) output projection
  dim3 go(HD / 128, Mrows / 128);
  gemm_1p<0><<<go, 256, GEMM_SMEM>>>(bo, nullptr, nullptr, out);
}

// round 17
// speedup vs baseline: 7.5913x; 1.0526x over previous
#include <cuda_runtime.h>
#include <cuda_fp16.h>
#include <math.h>
#include <stdint.h>

// ============================================================================
// CosFormer attention (sm_103 base; legacy HMMA mma.sync).
//  All heavy math on tensor cores (fp16, fp32 accum).
//  Round 17: chunk_stats emits fp16 S directly (fp32 S arrays deleted);
//  chunk_scan preloads all 32 chunks into registers (MLP ~32).
// ============================================================================

namespace cf {

constexpr int Bc = 2, Tc = 4096, Hc = 16, DHc = 64;
constexpr int DM = 1024, HD = 1024;
constexpr int Mrows = Bc * Tc;            // 8192
constexpr int CH = 128, NCH = Tc / CH;    // 128, 32
constexpr int BHc = Bc * Hc;              // 32
constexpr float ANGC = 3.14159265358979323846f / (2.0f * (float)Tc);

constexpr int KDIM = 1024;
constexpr int KT = 64;
constexpr int NKT = KDIM / KT;            // 16

// ---- z scratch (fp32) ----
__device__ __align__(16) float g_zcos[(size_t)BHc * NCH * DHc];
__device__ __align__(16) float g_zsin[(size_t)BHc * NCH * DHc];

// ---- fp16 operands ----
__device__ __align__(16) __half g_x16[(size_t)Mrows * DM];
__device__ __align__(16) __half g_Wq16[(size_t)DM * HD];   // [K][N]
__device__ __align__(16) __half g_Wk16[(size_t)DM * HD];
__device__ __align__(16) __half g_Wv16[(size_t)DM * HD];
__device__ __align__(16) __half g_Wo16[(size_t)HD * DM];
__device__ __align__(16) __half g_a16[(size_t)Mrows * HD];
__device__ __align__(16) __half g_Qp16[(size_t)Mrows * HD];
__device__ __align__(16) __half g_Kp16[(size_t)Mrows * HD];
__device__ __align__(16) __half g_Kc16[(size_t)Mrows * HD];
__device__ __align__(16) __half g_Ks16[(size_t)Mrows * HD];
__device__ __align__(16) __half g_V16[(size_t)Mrows * HD];
__device__ __align__(16) __half g_Scr16[(size_t)BHc * NCH * DHc * DHc];
__device__ __align__(16) __half g_Ssr16[(size_t)BHc * NCH * DHc * DHc];
__device__ __align__(16) __half g_Sc16[(size_t)BHc * NCH * DHc * DHc];
__device__ __align__(16) __half g_Ss16[(size_t)BHc * NCH * DHc * DHc];

// ============================================================================
// helpers
// ============================================================================
__device__ __forceinline__ uint32_t smem_u32(const void* p) {
  uint32_t a;
  asm("{ .reg .u64 t; cvta.to.shared.u64 t, %1; cvt.u32.u64 %0, t; }"
      : "=r"(a) : "l"(p));
  return a;
}
__device__ __forceinline__ void ldsm4(uint32_t* r, uint32_t addr) {
  asm volatile(
      "ldmatrix.sync.aligned.m8n8.x4.shared.b16 {%0,%1,%2,%3}, [%4];"
      : "=r"(r[0]), "=r"(r[1]), "=r"(r[2]), "=r"(r[3]) : "r"(addr));
}
__device__ __forceinline__ void ldsm4t(uint32_t* r, uint32_t addr) {
  asm volatile(
      "ldmatrix.sync.aligned.m8n8.x4.trans.shared.b16 {%0,%1,%2,%3}, [%4];"
      : "=r"(r[0]), "=r"(r[1]), "=r"(r[2]), "=r"(r[3]) : "r"(addr));
}
__device__ __forceinline__ void mma_hf(float* d, const uint32_t* a,
                                       const uint32_t* b) {
  asm volatile(
      "mma.sync.aligned.m16n8k16.row.col.f32.f16.f16.f32 "
      "{%0,%1,%2,%3}, {%4,%5,%6,%7}, {%8,%9}, {%0,%1,%2,%3};"
      : "+f"(d[0]), "+f"(d[1]), "+f"(d[2]), "+f"(d[3])
      : "r"(a[0]), "r"(a[1]), "r"(a[2]), "r"(a[3]), "r"(b[0]), "r"(b[1]));
}
__device__ __forceinline__ void cpasync16(uint32_t dst, const void* src) {
  asm volatile("cp.async.cg.shared.global [%0], [%1], 16;"
               ::"r"(dst), "l"(src) : "memory");
}
__device__ __forceinline__ void cp_commit() {
  asm volatile("cp.async.commit_group;" ::: "memory");
}
template <int N>
__device__ __forceinline__ void cp_wait() {
  asm volatile("cp.async.wait_group %0;" ::"n"(N) : "memory");
}
__device__ __forceinline__ uint32_t pack_h2(float lo, float hi) {
  __half2 h = __floats2half2_rn(lo, hi);
  return *(uint32_t*)&h;
}
__device__ __forceinline__ uint32_t hmul2_u(uint32_t a, uint32_t s) {
  __half2 r = __hmul2(*(const __half2*)&a, *(const __half2*)&s);
  return *(uint32_t*)&r;
}

// ============================================================================
// Conversions: one launch (x + 4 weight casts)
// ============================================================================
constexpr int XBLK = Mrows * DM / 4 / 256;        // 8192
constexpr int WBLK = 1024 * 1024 / 4 / 256;       // 1024

__global__ __launch_bounds__(256) void conv_all(const float* __restrict__ x,
                                                const float* __restrict__ Wq,
                                                const float* __restrict__ Wk,
                                                const float* __restrict__ Wv,
                                                const float* __restrict__ Wo) {
  const int blk = blockIdx.x;
  const float* src;
  __half* dst;
  int i;
  if (blk < XBLK) {
    src = x;
    dst = g_x16;
    i = blk * 256 + threadIdx.x;
  } else {
    const int w = (blk - XBLK) / WBLK;
    const int bi = (blk - XBLK) - w * WBLK;
    src = (w == 0) ? Wq : (w == 1) ? Wk : (w == 2) ? Wv : Wo;
    dst = (w == 0) ? g_Wq16 : (w == 1) ? g_Wk16 : (w == 2) ? g_Wv16 : g_Wo16;
    i = bi * 256 + threadIdx.x;
  }
  float4 v = *(const float4*)(src + (size_t)i * 4);
  __half h[4] = {__float2half(v.x), __float2half(v.y), __float2half(v.z),
                 __float2half(v.w)};
  *(uint2*)(dst + (size_t)i * 4) = *(uint2*)h;
}

// ============================================================================
// Single-pass fp16 GEMM. FUSED=1: QKV.  FUSED=0: out proj.
// ============================================================================
constexpr int A_PIECE = 128 * KT * 2;            // 16384
constexpr int B_LDH = 136;
constexpr int B_PIECE = KT * B_LDH * 2;          // 17408
constexpr int STAGE_G = A_PIECE + B_PIECE;       // 33792
constexpr int GEMM_SMEM = 2 * STAGE_G;           // 67584

template <int FUSED>
__global__ __launch_bounds__(256, 2) void gemm_1p(
    const float* __restrict__ bias_q, const float* __restrict__ bias_k,
    const float* __restrict__ bias_v, float* __restrict__ outO) {
  extern __shared__ __align__(16) char smem[];
  const uint32_t sb = smem_u32(smem);
  const int tid = threadIdx.x, wid = tid >> 5, lane = tid & 31;
  const int wm = wid >> 2, wn = wid & 3;
  const int bm = blockIdx.y, bn = blockIdx.x;
  const int w = FUSED ? (int)blockIdx.z : 3;

  const __half* A = FUSED ? g_x16 : g_a16;
  const __half* Bm = (w == 0) ? g_Wq16 : (w == 1) ? g_Wk16
                       : (w == 2) ? g_Wv16 : g_Wo16;
  const float* bias = FUSED
                          ? ((w == 0) ? bias_q : (w == 1) ? bias_k : bias_v)
                          : bias_q;

  const int p = tid >> 7, q = tid & 127;
  const __half* psrcA =
      A + (size_t)bm * 128 * KDIM + (size_t)(q >> 3) * KDIM + (q & 7) * 8;
  const uint32_t aoff0 = (uint32_t)((q >> 3) * 128 + (q & 7) * 16);
  const __half* psrcB = Bm + (size_t)(q >> 4) * 1024 + bn * 128 + (q & 15) * 8;
  const uint32_t boff0 = (uint32_t)((q >> 4) * B_LDH + (q & 15) * 8) * 2;

  auto issue = [&](int kt) {
    const int buf = kt & 1;
    if (p == 0) {
      const __half* g = psrcA + kt * KT;
      const uint32_t dstbase = sb + buf * STAGE_G;
#pragma unroll
      for (int j = 0; j < 8; ++j) {
        const uint32_t off = aoff0 + j * 2048;
        const uint32_t swz = off ^ ((off >> 3) & 0x70);
        cpasync16(dstbase + swz, g + (size_t)j * 16 * KDIM);
      }
    } else {
      const __half* g = psrcB + (size_t)kt * KT * 1024;
      const uint32_t dstbase = sb + buf * STAGE_G + A_PIECE;
#pragma unroll
      for (int j = 0; j < 8; ++j)
        cpasync16(dstbase + boff0 + (uint32_t)(j * 8 * B_LDH) * 2,
                  g + (size_t)j * 8 * 1024);
    }
    cp_commit();
  };

  float acc[4][4][4];
#pragma unroll
  for (int i = 0; i < 4; ++i)
#pragma unroll
    for (int j = 0; j < 4; ++j)
#pragma unroll
      for (int k = 0; k < 4; ++k) acc[i][j][k] = 0.f;

  issue(0);
#pragma unroll 1
  for (int kt = 0; kt < NKT; ++kt) {
    if (kt + 1 < NKT) {
      issue(kt + 1);
      cp_wait<1>();
    } else {
      cp_wait<0>();
    }
    __syncthreads();
    const uint32_t base = sb + (kt & 1) * STAGE_G;
#pragma unroll
    for (int ks = 0; ks < 4; ++ks) {
      const int k0 = ks * 16;
      uint32_t a[4][4], bb[2][4];
#pragma unroll
      for (int mt = 0; mt < 4; ++mt) {
        const uint32_t row = wm * 64 + mt * 16 + (lane & 15);
        const uint32_t off = row * 128 + k0 * 2 + ((lane >> 4) << 4);
        const uint32_t swz = off ^ ((off >> 3) & 0x70);
        ldsm4(a[mt], base + swz);
      }
      const uint32_t kr =
          (uint32_t)(k0 + (lane & 7) + (((lane >> 3) & 1) << 3));
#pragma unroll
      for (int nt2 = 0; nt2 < 2; ++nt2) {
        const uint32_t nn =
            (uint32_t)(wn * 32 + nt2 * 16 + ((lane >> 4) << 3));
        ldsm4t(bb[nt2], base + A_PIECE + (kr * B_LDH + nn) * 2);
      }
#pragma unroll
      for (int mt = 0; mt < 4; ++mt)
#pragma unroll
        for (int nt = 0; nt < 4; ++nt)
          mma_hf(acc[mt][nt], a[mt], &bb[nt >> 1][(nt & 1) * 2]);
    }
    __syncthreads();
  }

  const int g = lane >> 2, t2 = (lane & 3) * 2;
#pragma unroll
  for (int mt = 0; mt < 4; ++mt) {
    const int r0 = bm * 128 + wm * 64 + mt * 16 + g;
    const int r1 = r0 + 8;
    float sn0 = 0.f, cs0 = 0.f, sn1 = 0.f, cs1 = 0.f;
    if (FUSED && w == 1) {
      sincosf(ANGC * (float)(r0 & (Tc - 1)), &sn0, &cs0);
      sincosf(ANGC * (float)(r1 & (Tc - 1)), &sn1, &cs1);
    }
#pragma unroll
    for (int nt = 0; nt < 4; ++nt) {
      const int col = bn * 128 + wn * 32 + nt * 8 + t2;
      const float b0 = __ldg(&bias[col]), b1 = __ldg(&bias[col + 1]);
      const float v00 = acc[mt][nt][0] + b0, v01 = acc[mt][nt][1] + b1;
      const float v10 = acc[mt][nt][2] + b0, v11 = acc[mt][nt][3] + b1;
      if (!FUSED) {
        *(float2*)&outO[(size_t)r0 * DM + col] = make_float2(v00, v01);
        *(float2*)&outO[(size_t)r1 * DM + col] = make_float2(v10, v11);
      } else if (w == 2) {
        *(__half2*)&g_V16[(size_t)r0 * HD + col] = __floats2half2_rn(v00, v01);
        *(__half2*)&g_V16[(size_t)r1 * HD + col] = __floats2half2_rn(v10, v11);
      } else if (w == 0) {
        *(__half2*)&g_Qp16[(size_t)r0 * HD + col] =
            __floats2half2_rn(fmaxf(v00, 0.f), fmaxf(v01, 0.f));
        *(__half2*)&g_Qp16[(size_t)r1 * HD + col] =
            __floats2half2_rn(fmaxf(v10, 0.f), fmaxf(v11, 0.f));
      } else {
        const float a00 = fmaxf(v00, 0.f), a01 = fmaxf(v01, 0.f);
        const float a10 = fmaxf(v10, 0.f), a11 = fmaxf(v11, 0.f);
        *(__half2*)&g_Kp16[(size_t)r0 * HD + col] = __floats2half2_rn(a00, a01);
        *(__half2*)&g_Kp16[(size_t)r1 * HD + col] = __floats2half2_rn(a10, a11);
        *(__half2*)&g_Kc16[(size_t)r0 * HD + col] =
            __floats2half2_rn(a00 * cs0, a01 * cs0);
        *(__half2*)&g_Kc16[(size_t)r1 * HD + col] =
            __floats2half2_rn(a10 * cs1, a11 * cs1);
        *(__half2*)&g_Ks16[(size_t)r0 * HD + col] =
            __floats2half2_rn(a00 * sn0, a01 * sn0);
        *(__half2*)&g_Ks16[(size_t)r1 * HD + col] =
            __floats2half2_rn(a10 * sn1, a11 * sn1);
      }
    }
  }
}

// ============================================================================
// Pass A (tensor cores): per-chunk states; emits fp16 S directly.
// ============================================================================
constexpr int CS_LDH = 72;
constexpr int CS_OP = 128 * CS_LDH * 2;
constexpr int CS_SMEM = 3 * CS_OP;

__global__ __launch_bounds__(128, 4) void chunk_stats16() {
  extern __shared__ __align__(16) char smem[];
  const uint32_t sb = smem_u32(smem);
  const int blk = blockIdx.x;
  const int c = blk & (NCH - 1);
  const int bh = blk >> 5;
  const int b = bh >> 4, h = bh & 15;
  const int tid = threadIdx.x, wid = tid >> 5, lane = tid & 31;

  const size_t gb16 = ((size_t)b * Tc + (size_t)c * CH) * HD + h * DHc;
  {
    const int r = tid >> 3, cb = tid & 7;
#pragma unroll
    for (int op = 0; op < 3; ++op) {
      const __half* src =
          ((op == 0) ? g_Kc16 : (op == 1) ? g_Ks16 : g_V16) + gb16;
#pragma unroll
      for (int j = 0; j < 8; ++j) {
        const int row = r + 16 * j;
        cpasync16(sb + op * CS_OP + (uint32_t)(row * CS_LDH + cb * 8) * 2,
                  src + (size_t)row * HD + cb * 8);
      }
    }
    cp_commit();
    cp_wait<0>();
  }
  __syncthreads();

  {
    const int vec = tid >> 6, d = tid & 63;
    const __half* sK = (const __half*)(smem + vec * CS_OP);
    float z = 0.f;
#pragma unroll 4
    for (int t = 0; t < CH; ++t) z += __half2float(sK[t * CS_LDH + d]);
    const size_t zb = ((size_t)bh * NCH + c) * DHc;
    ((vec == 0) ? g_zcos : g_zsin)[zb + d] = z;
  }

  const int m0 = wid * 16;
  float accC[8][4], accS[8][4];
#pragma unroll
  for (int i = 0; i < 8; ++i)
#pragma unroll
    for (int j = 0; j < 4; ++j) {
      accC[i][j] = 0.f;
      accS[i][j] = 0.f;
    }

  const uint32_t bKc = sb, bKs = sb + CS_OP, bV = sb + 2 * CS_OP;
#pragma unroll 1
  for (int ks = 0; ks < 8; ++ks) {
    const int k0 = ks * 16;
    const uint32_t akk = (uint32_t)(k0 + (lane & 7) + ((lane >> 4) << 3));
    const uint32_t amm = (uint32_t)(m0 + (((lane >> 3) & 1) << 3));
    const uint32_t aoff = akk * (CS_LDH * 2) + amm * 2;
    uint32_t aC[4], aS[4];
    ldsm4t(aC, bKc + aoff);
    ldsm4t(aS, bKs + aoff);
    const uint32_t bkk = (uint32_t)(k0 + (lane & 7) + (((lane >> 3) & 1) << 3));
#pragma unroll
    for (int n4 = 0; n4 < 4; ++n4) {
      const uint32_t bnn = (uint32_t)(n4 * 16 + ((lane >> 4) << 3));
      uint32_t bb[4];
      ldsm4t(bb, bV + bkk * (CS_LDH * 2) + bnn * 2);
      mma_hf(accC[2 * n4], aC, &bb[0]);
      mma_hf(accC[2 * n4 + 1], aC, &bb[2]);
      mma_hf(accS[2 * n4], aS, &bb[0]);
      mma_hf(accS[2 * n4 + 1], aS, &bb[2]);
    }
  }

  const size_t sbse = ((size_t)bh * NCH + c) * (DHc * DHc);
  const int r = lane >> 2, c2 = (lane & 3) * 2;
#pragma unroll
  for (int nt = 0; nt < 8; ++nt) {
    const int col = nt * 8 + c2;
    *(__half2*)&g_Scr16[sbse + (size_t)(m0 + r) * 64 + col] =
        __floats2half2_rn(accC[nt][0], accC[nt][1]);
    *(__half2*)&g_Scr16[sbse + (size_t)(m0 + r + 8) * 64 + col] =
        __floats2half2_rn(accC[nt][2], accC[nt][3]);
    *(__half2*)&g_Ssr16[sbse + (size_t)(m0 + r) * 64 + col] =
        __floats2half2_rn(accS[nt][0], accS[nt][1]);
    *(__half2*)&g_Ssr16[sbse + (size_t)(m0 + r + 8) * 64 + col] =
        __floats2half2_rn(accS[nt][2], accS[nt][3]);
  }
}

// ============================================================================
// Pass B: exclusive prefix over chunks with full register preload (MLP ~32).
// Each thread owns one (bh, element); grid (32, 32) x 128.
// ============================================================================
__global__ __launch_bounds__(128) void chunk_scan3() {
  const int bh = blockIdx.y;
  const int e = blockIdx.x * 128 + threadIdx.x;  // 0..4095
  const size_t base = (size_t)bh * NCH * (DHc * DHc) + e;

  // cos stream
  {
    float v[NCH];
#pragma unroll
    for (int c = 0; c < NCH; ++c)
      v[c] = __half2float(g_Scr16[base + (size_t)c * (DHc * DHc)]);
    float ac = 0.f;
#pragma unroll
    for (int c = 0; c < NCH; ++c) {
      g_Sc16[base + (size_t)c * (DHc * DHc)] = __float2half(ac);
      ac += v[c];
    }
  }
  // sin stream
  {
    float v[NCH];
#pragma unroll
    for (int c = 0; c < NCH; ++c)
      v[c] = __half2float(g_Ssr16[base + (size_t)c * (DHc * DHc)]);
    float ac = 0.f;
#pragma unroll
    for (int c = 0; c < NCH; ++c) {
      g_Ss16[base + (size_t)c * (DHc * DHc)] = __float2half(ac);
      ac += v[c];
    }
  }
  // z vectors (first 64 threads of block x==0)
  if (blockIdx.x == 0 && threadIdx.x < DHc) {
    const size_t zb = (size_t)bh * NCH * DHc + threadIdx.x;
    float vz[NCH], vz2[NCH];
#pragma unroll
    for (int c = 0; c < NCH; ++c) {
      vz[c] = g_zcos[zb + (size_t)c * DHc];
      vz2[c] = g_zsin[zb + (size_t)c * DHc];
    }
    float ac = 0.f, as2 = 0.f;
#pragma unroll
    for (int c = 0; c < NCH; ++c) {
      g_zcos[zb + (size_t)c * DHc] = ac;
      g_zsin[zb + (size_t)c * DHc] = as2;
      ac += vz[c];
      as2 += vz2[c];
    }
  }
}

// ============================================================================
// Pass C (tensor cores, register-resident P): per-chunk output; 2 CTA/SM.
// ============================================================================
constexpr int AT_LDQ = 72;
constexpr int AT_LDB = 80;
constexpr int AOF_QP = 0;                           // 128*72*2 = 18432
constexpr int AOF_KP = 18432;
constexpr int AOF_B = 36864;                        // 256*80*2 = 40960
constexpr int AOF_TRC = 77824;                      // 128 f32
constexpr int AOF_TRS = 78336;
constexpr int AOF_ZC = 78848;                       // 64 f32
constexpr int AOF_ZS = 79104;
constexpr int AT_SMEM = 79360;

__global__ __launch_bounds__(256, 2) void attn_tc() {
  extern __shared__ __align__(16) char smem[];
  const uint32_t sb = smem_u32(smem);
  const int blk = blockIdx.x;
  const int c = blk & (NCH - 1);
  const int bh = blk >> 5;
  const int b = bh >> 4, h = bh & 15;
  const int tid = threadIdx.x, wid = tid >> 5, lane = tid & 31;

  float* strc = (float*)(smem + AOF_TRC);
  float* strs = (float*)(smem + AOF_TRS);
  float* szc = (float*)(smem + AOF_ZC);
  float* szs = (float*)(smem + AOF_ZS);

  const size_t gb16 = ((size_t)b * Tc + (size_t)c * CH) * HD + h * DHc;
  const size_t sbse = ((size_t)bh * NCH + c) * (DHc * DHc);
  const size_t zb = ((size_t)bh * NCH + c) * DHc;

  if (tid < CH) {
    float sn, cs;
    sincosf(ANGC * (float)(c * CH + tid), &sn, &cs);
    strc[tid] = cs;
    strs[tid] = sn;
  }
  if (tid < 64) szc[tid] = g_zcos[zb + tid];
  else if (tid < 128) szs[tid - 64] = g_zsin[zb + tid - 64];

  {
    const int r = tid >> 3, cb = tid & 7;
#pragma unroll
    for (int j = 0; j < 4; ++j) {
      const int row = r + 32 * j;
      cpasync16(sb + AOF_QP + (uint32_t)(row * AT_LDQ + cb * 8) * 2,
                g_Qp16 + gb16 + (size_t)row * HD + cb * 8);
      cpasync16(sb + AOF_KP + (uint32_t)(row * AT_LDQ + cb * 8) * 2,
                g_Kp16 + gb16 + (size_t)row * HD + cb * 8);
      cpasync16(sb + AOF_B + (uint32_t)(row * AT_LDB + cb * 8) * 2,
                g_V16 + gb16 + (size_t)row * HD + cb * 8);
    }
#pragma unroll
    for (int j = 0; j < 2; ++j) {
      const int row = r + 32 * j;
      cpasync16(sb + AOF_B + (uint32_t)((row + 128) * AT_LDB + cb * 8) * 2,
                g_Sc16 + sbse + (size_t)row * 64 + cb * 8);
      cpasync16(sb + AOF_B + (uint32_t)((row + 192) * AT_LDB + cb * 8) * 2,
                g_Ss16 + sbse + (size_t)row * 64 + cb * 8);
    }
    cp_commit();
    cp_wait<0>();
  }
  __syncthreads();

  {
    const int row = tid;
    float cv = (row < 128) ? 1.f
               : (row < 192) ? szc[row - 128] : szs[row - 192];
    __half hv[8] = {__float2half(cv), __half(0), __half(0), __half(0),
                    __half(0), __half(0), __half(0), __half(0)};
    *(uint4*)(smem + AOF_B + (uint32_t)(row * AT_LDB + 64) * 2) = *(uint4*)hv;
    uint4 z4 = make_uint4(0, 0, 0, 0);
    *(uint4*)(smem + AOF_B + (uint32_t)(row * AT_LDB + 72) * 2) = z4;
  }
  __syncthreads();

  const int m0 = wid * 16;
  const int r = lane >> 2, tg2 = (lane & 3) * 2;
  const int t0r = m0 + r, t1r = t0r + 8;
  const float ct0 = strc[t0r], st0 = strs[t0r];
  const float ct1 = strc[t1r], st1 = strs[t1r];

  uint32_t qa[4][4];
#pragma unroll
  for (int ks = 0; ks < 4; ++ks) {
    const uint32_t row = (uint32_t)(m0 + (lane & 15));
    const uint32_t off = row * (AT_LDQ * 2) + ks * 32 + ((lane >> 4) << 4);
    ldsm4(qa[ks], sb + AOF_QP + off);
  }

  uint32_t pa[8][4];
#pragma unroll
  for (int nt2 = 0; nt2 < 8; ++nt2) {
    if (nt2 <= wid) {
      uint32_t bbf[4][4];
#pragma unroll
      for (int ks = 0; ks < 4; ++ks) {
        const uint32_t row =
            (uint32_t)(nt2 * 16 + (lane & 7) + ((lane >> 4) << 3));
        const uint32_t off =
            row * (AT_LDQ * 2) + ks * 32 + (((lane >> 3) & 1) << 4);
        ldsm4(bbf[ks], sb + AOF_KP + off);
      }
      float pacc[2][4] = {};
#pragma unroll
      for (int ks = 0; ks < 4; ++ks) {
        mma_hf(pacc[0], qa[ks], &bbf[ks][0]);
        mma_hf(pacc[1], qa[ks], &bbf[ks][2]);
      }
#pragma unroll
      for (int ntl = 0; ntl < 2; ++ntl) {
        const int s0 = nt2 * 16 + ntl * 8 + tg2;
        const float cs0 = strc[s0], ss0 = strs[s0];
        const float cs1 = strc[s0 + 1], ss1 = strs[s0 + 1];
        const float w00 = (s0 <= t0r) ? (ct0 * cs0 + st0 * ss0) : 0.f;
        const float w01 = (s0 + 1 <= t0r) ? (ct0 * cs1 + st0 * ss1) : 0.f;
        const float w10 = (s0 <= t1r) ? (ct1 * cs0 + st1 * ss0) : 0.f;
        const float w11 = (s0 + 1 <= t1r) ? (ct1 * cs1 + st1 * ss1) : 0.f;
        pa[nt2][ntl * 2] = pack_h2(w00 * pacc[ntl][0], w01 * pacc[ntl][1]);
        pa[nt2][ntl * 2 + 1] =
            pack_h2(w10 * pacc[ntl][2], w11 * pacc[ntl][3]);
      }
    }
  }

  float acc[9][4];
#pragma unroll
  for (int i = 0; i < 9; ++i)
#pragma unroll
    for (int j = 0; j < 4; ++j) acc[i][j] = 0.f;

  auto do_btile = [&](const uint32_t* afrag, uint32_t krow_base) {
    const uint32_t kr =
        krow_base + (uint32_t)((lane & 7) + (((lane >> 3) & 1) << 3));
    uint32_t bbf[5][4];
#pragma unroll
    for (int g = 0; g < 5; ++g) {
      const uint32_t nn = (uint32_t)(g * 16 + ((lane >> 4) << 3));
      ldsm4t(bbf[g], sb + AOF_B + (kr * AT_LDB + nn) * 2);
    }
#pragma unroll
    for (int nt = 0; nt < 9; ++nt)
      mma_hf(acc[nt], afrag, &bbf[nt >> 1][(nt & 1) * 2]);
  };

#pragma unroll
  for (int kt2 = 0; kt2 < 8; ++kt2)
    if (kt2 <= wid) do_btile(pa[kt2], (uint32_t)(kt2 * 16));

  const uint32_t hc0 = pack_h2(ct0, ct0), hc1 = pack_h2(ct1, ct1);
  const uint32_t hs0 = pack_h2(st0, st0), hs1 = pack_h2(st1, st1);
#pragma unroll
  for (int kc = 0; kc < 4; ++kc) {
    uint32_t qcf[4] = {hmul2_u(qa[kc][0], hc0), hmul2_u(qa[kc][1], hc1),
                       hmul2_u(qa[kc][2], hc0), hmul2_u(qa[kc][3], hc1)};
    do_btile(qcf, (uint32_t)(128 + kc * 16));
  }
#pragma unroll
  for (int kc = 0; kc < 4; ++kc) {
    uint32_t qsf[4] = {hmul2_u(qa[kc][0], hs0), hmul2_u(qa[kc][1], hs1),
                       hmul2_u(qa[kc][2], hs0), hmul2_u(qa[kc][3], hs1)};
    do_btile(qsf, (uint32_t)(192 + kc * 16));
  }

  const float den0r = __shfl_sync(0xffffffffu, acc[8][0], lane & ~3);
  const float den1r = __shfl_sync(0xffffffffu, acc[8][2], lane & ~3);
  const float inv0 = 1.f / fmaxf(den0r, 1e-6f);
  const float inv1 = 1.f / fmaxf(den1r, 1e-6f);
#pragma unroll
  for (int nt = 0; nt < 8; ++nt) {
    const int col = nt * 8 + tg2;
    *(__half2*)&g_a16[gb16 + (size_t)t0r * HD + col] =
        __floats2half2_rn(acc[nt][0] * inv0, acc[nt][1] * inv0);
    *(__half2*)&g_a16[gb16 + (size_t)t1r * HD + col] =
        __floats2half2_rn(acc[nt][2] * inv1, acc[nt][3] * inv1);
  }
}

}  // namespace cf

extern "C" void kernel_launch(void* const* d_in, const int* in_sizes, int n_in,
                              void* d_out, int out_size) {
  using namespace cf;
  const float* x = (const float*)d_in[0];
  const float* Wq = (const float*)d_in[1];
  const float* bq = (const float*)d_in[2];
  const float* Wk = (const float*)d_in[3];
  const float* bk = (const float*)d_in[4];
  const float* Wv = (const float*)d_in[5];
  const float* bv = (const float*)d_in[6];
  const float* Wo = (const float*)d_in[7];
  const float* bo = (const float*)d_in[8];
  float* out = (float*)d_out;

  cudaFuncSetAttribute(gemm_1p<1>, cudaFuncAttributeMaxDynamicSharedMemorySize,
                       GEMM_SMEM);
  cudaFuncSetAttribute(gemm_1p<0>, cudaFuncAttributeMaxDynamicSharedMemorySize,
                       GEMM_SMEM);
  cudaFuncSetAttribute(chunk_stats16,
                       cudaFuncAttributeMaxDynamicSharedMemorySize, CS_SMEM);
  cudaFuncSetAttribute(attn_tc, cudaFuncAttributeMaxDynamicSharedMemorySize,
                       AT_SMEM);

  // 1) conversions
  conv_all<<<XBLK + 4 * WBLK, 256>>>(x, Wq, Wk, Wv, Wo);

  // 2) fused QKV projection
  dim3 gq(HD / 128, Mrows / 128, 3);
  gemm_1p<1><<<gq, 256, GEMM_SMEM>>>(bq, bk, bv, nullptr);

  // 3) attention
  chunk_stats16<<<BHc * NCH, 128, CS_SMEM>>>();
  chunk_scan3<<<dim3(32, 32), 128>>>();
  attn_tc<<<BHc * NCH, 256, AT_SMEM>>>();

  // 4) output projection
  dim3 go(HD / 128, Mrows / 128);
  gemm_1p<0><<<go, 256, GEMM_SMEM>>>(bo, nullptr, nullptr, out);
}